// round 5
// baseline (speedup 1.0000x reference)
#include <cuda_runtime.h>
#include <cuda_bf16.h>
#include <cstdint>

typedef unsigned long long u64;

// Problem constants
#define BB 32
#define TT 512
#define II 512
#define HH 512
#define G4H 2048
#define EE 4
#define OUTD 512
#define NPAIR 64     // B * TOPK
#define NCHAIN 128   // NPAIR * 2 directions
#define LSTM_BLOCKS 128   // 4 experts x 32 col-tiles, 1 block/SM

#define WS_STRIDE 258     // u64 stride per gate-row (256 kpairs + pad)
#define WS_ROWS   64
#define HS_STRIDE 258
#define HS_ROWS   32
#define SMEM_BYTES ((WS_ROWS * WS_STRIDE + HS_ROWS * HS_STRIDE) * 8)

// ---------------- device scratch (static; no allocations allowed) -------------
__device__ __align__(16) float g_xp[(size_t)NCHAIN * TT * G4H];       // 512 MB
__device__ __align__(16) float g_hout[(size_t)NPAIR * TT * 2 * HH];   // 128 MB
__device__ __align__(16) float g_hbuf[2][NCHAIN * HH];
__device__ __align__(16) float g_router_in[BB * II];
__device__ __align__(16) float g_router_h[BB * II];
__device__ int   g_pair_b[NPAIR];
__device__ int   g_pair_e[NPAIR];
__device__ int   g_off[EE];
__device__ int   g_cnt[EE];
__device__ int   g_bpair[BB * 2];
__device__ float g_bw[BB * 2];
__device__ float g_lb;
__device__ int   g_gbar[8];       // per (expert, dir) barrier counters

// ---------------- packed f32x2 helpers ----------------------------------------
__device__ __forceinline__ u64 ffma2(u64 a, u64 b, u64 c) {
    u64 d;
    asm("fma.rn.f32x2 %0, %1, %2, %3;" : "=l"(d) : "l"(a), "l"(b), "l"(c));
    return d;
}
__device__ __forceinline__ float f2sum(u64 v) {
    float lo, hi;
    asm("mov.b64 {%0,%1}, %2;" : "=f"(lo), "=f"(hi) : "l"(v));
    return lo + hi;
}
__device__ __forceinline__ float sigmoid_fast(float x) {
    return 0.5f * __tanhf(0.5f * x) + 0.5f;
}
__device__ __forceinline__ int ld_acq(const int* p) {
    int v;
    asm volatile("ld.acquire.gpu.b32 %0, [%1];" : "=r"(v) : "l"(p));
    return v;
}

// ---------------- router ------------------------------------------------------
__global__ void mean_kernel(const float* __restrict__ x) {
    int b = blockIdx.x;
    int i = threadIdx.x;            // 512 threads
    const float* xb = x + (size_t)b * TT * II + i;
    float s = 0.f;
    for (int t = 0; t < TT; t++) s += xb[(size_t)t * II];
    g_router_in[b * II + i] = s * (1.0f / (float)TT);
}

__global__ void router1_kernel(const float* __restrict__ rW1, const float* __restrict__ rb1) {
    int b = blockIdx.x;
    __shared__ float rin[II];
    for (int i = threadIdx.x; i < II; i += blockDim.x) rin[i] = g_router_in[b * II + i];
    __syncthreads();
    for (int n = threadIdx.x; n < II; n += blockDim.x) {
        float s = rb1[n];
        const float* w = rW1 + (size_t)n * II;
        for (int k = 0; k < II; k += 4) {
            float4 wv = *(const float4*)(w + k);
            s += rin[k] * wv.x + rin[k + 1] * wv.y + rin[k + 2] * wv.z + rin[k + 3] * wv.w;
        }
        float sg = 1.f / (1.f + expf(-s));
        g_router_h[b * II + n] = s * sg;
    }
}

__global__ void router2_kernel(const float* __restrict__ rW2, const float* __restrict__ rb2) {
    __shared__ float logits[BB][EE];
    __shared__ float probs[BB][EE];
    __shared__ float gate[BB][EE];
    int tid = threadIdx.x;          // 128 threads
    {
        int b = tid >> 2, e = tid & 3;
        float s = rb2[e];
        const float* w = rW2 + (size_t)e * II;
        const float* h = g_router_h + (size_t)b * II;
        for (int k = 0; k < II; k++) s += h[k] * w[k];
        logits[b][e] = s;
    }
    __syncthreads();
    if (tid < BB) {
        int b = tid;
        float m = logits[b][0];
        for (int e = 1; e < EE; e++) m = fmaxf(m, logits[b][e]);
        float pr[EE], sum = 0.f;
        for (int e = 0; e < EE; e++) { pr[e] = expf(logits[b][e] - m); sum += pr[e]; }
        for (int e = 0; e < EE; e++) { pr[e] /= sum; probs[b][e] = pr[e]; gate[b][e] = 0.f; }
        int i1 = 0;
        for (int e = 1; e < EE; e++) if (pr[e] > pr[i1]) i1 = e;
        int i2 = -1;
        for (int e = 0; e < EE; e++) {
            if (e == i1) continue;
            if (i2 < 0 || pr[e] > pr[i2]) i2 = e;
        }
        float ws = pr[i1] + pr[i2];
        gate[b][i1] = pr[i1] / ws;
        gate[b][i2] = pr[i2] / ws;
    }
    __syncthreads();
    if (tid == 0) {
        float lb = 0.f;
        for (int e = 0; e < EE; e++) {
            float u = 0.f;
            for (int b = 0; b < BB; b++) u += probs[b][e];
            u *= (1.f / (float)BB);
            float d = u - 1.0f / (float)EE;
            lb += d * d;
        }
        g_lb = 0.01f * (lb / (float)EE);
        int P = 0;
        int slotc[BB];
        for (int b = 0; b < BB; b++) slotc[b] = 0;
        for (int e = 0; e < EE; e++) {
            g_off[e] = P;
            for (int b = 0; b < BB; b++) {
                if (gate[b][e] > 0.f) {
                    g_pair_b[P] = b;
                    g_pair_e[P] = e;
                    g_bpair[b * 2 + slotc[b]] = P;
                    g_bw[b * 2 + slotc[b]] = gate[b][e];
                    slotc[b]++;
                    P++;
                }
            }
            g_cnt[e] = P - g_off[e];
        }
    }
}

__global__ void init_state_kernel() {
    int idx = blockIdx.x * blockDim.x + threadIdx.x;
    if (idx < 8) g_gbar[idx] = 0;
    if (idx < NCHAIN * HH) {
        g_hbuf[0][idx] = 0.f;
        g_hbuf[1][idx] = 0.f;
    }
}

// ---------- 128x128 reg-blocked SGEMM, k-packed f32x2 (C = A @ B^T + bias) -----
#define TMm 128
#define TNn 128
#define TKk 32

__device__ __forceinline__ void sgemm_block(
    const float* __restrict__ A, const float* __restrict__ Bw,
    float* __restrict__ C, int ldc, int K, int m0, int n0,
    const float* __restrict__ bias1, const float* __restrict__ bias2)
{
    __shared__ float2 As2[TKk / 2][TMm + 1];
    __shared__ float2 Bs2[TKk / 2][TNn + 1];
    int tid = threadIdx.x;       // 256
    int tx = tid & 15;
    int ty = tid >> 4;
    u64 acc2[8][8];
#pragma unroll
    for (int i = 0; i < 8; i++)
#pragma unroll
        for (int j = 0; j < 8; j++) acc2[i][j] = 0ull;

    for (int k0 = 0; k0 < K; k0 += TKk) {
#pragma unroll
        for (int it = 0; it < 4; it++) {
            int idx = tid + it * 256;
            int row = idx >> 3;
            int kv  = (idx & 7) * 4;
            float4 v = *(const float4*)(A + (size_t)(m0 + row) * K + k0 + kv);
            int kv2 = kv >> 1;
            As2[kv2][row]     = make_float2(v.x, v.y);
            As2[kv2 + 1][row] = make_float2(v.z, v.w);
        }
#pragma unroll
        for (int it = 0; it < 4; it++) {
            int idx = tid + it * 256;
            int row = idx >> 3;
            int kv  = (idx & 7) * 4;
            float4 v = *(const float4*)(Bw + (size_t)(n0 + row) * K + k0 + kv);
            int kv2 = kv >> 1;
            Bs2[kv2][row]     = make_float2(v.x, v.y);
            Bs2[kv2 + 1][row] = make_float2(v.z, v.w);
        }
        __syncthreads();
#pragma unroll
        for (int kk2 = 0; kk2 < TKk / 2; kk2++) {
            u64 a2[8], b2[8];
#pragma unroll
            for (int i = 0; i < 8; i++) a2[i] = *(const u64*)&As2[kk2][ty + 16 * i];
#pragma unroll
            for (int j = 0; j < 8; j++) b2[j] = *(const u64*)&Bs2[kk2][tx + 16 * j];
#pragma unroll
            for (int i = 0; i < 8; i++)
#pragma unroll
                for (int j = 0; j < 8; j++) acc2[i][j] = ffma2(a2[i], b2[j], acc2[i][j]);
        }
        __syncthreads();
    }
#pragma unroll
    for (int j = 0; j < 8; j++) {
        int n = n0 + tx + 16 * j;
        float bv = 0.f;
        if (bias1) bv += bias1[n];
        if (bias2) bv += bias2[n];
#pragma unroll
        for (int i = 0; i < 8; i++) {
            int m = m0 + ty + 16 * i;
            C[(size_t)m * ldc + n] = f2sum(acc2[i][j]) + bv;
        }
    }
}

__global__ __launch_bounds__(256, 1) void xp_gemm_kernel(
    const float* __restrict__ x, const float* __restrict__ Wih,
    const float* __restrict__ bih, const float* __restrict__ bhh)
{
    int z = blockIdx.z;
    int p = z >> 1, d = z & 1;
    int b = g_pair_b[p];
    int e = g_pair_e[p];
    int ed = e * 2 + d;
    const float* A  = x + (size_t)b * TT * II;
    const float* Bw = Wih + (size_t)ed * G4H * II;
    const float* b1 = bih + (size_t)ed * G4H;
    const float* b2 = bhh + (size_t)ed * G4H;
    float* C = g_xp + (size_t)z * TT * G4H;
    sgemm_block(A, Bw, C, G4H, II, blockIdx.y * TMm, blockIdx.x * TNn, b1, b2);
}

// ---- output projection fused with gate-combine -------------------------------
__global__ __launch_bounds__(256, 1) void out_gemm_fused_kernel(
    const float* __restrict__ Wout, const float* __restrict__ bout, float* __restrict__ out)
{
    const int K = 2 * HH;
    int m0 = blockIdx.y * TMm, n0 = blockIdx.x * TNn;
    __shared__ float2 As2[TKk / 2][TMm + 1];
    __shared__ float2 Bs2[TKk / 2][TNn + 1];
    int tid = threadIdx.x;
    int tx = tid & 15;
    int ty = tid >> 4;
    u64 acc2[8][8];
#pragma unroll
    for (int i = 0; i < 8; i++)
#pragma unroll
        for (int j = 0; j < 8; j++) acc2[i][j] = 0ull;

    for (int k0 = 0; k0 < K; k0 += TKk) {
#pragma unroll
        for (int it = 0; it < 4; it++) {
            int idx = tid + it * 256;
            int row = idx >> 3;
            int kv  = (idx & 7) * 4;
            int m = m0 + row;
            int b = m >> 9, t = m & (TT - 1);
            int p0 = g_bpair[b * 2 + 0], p1 = g_bpair[b * 2 + 1];
            float w0 = g_bw[b * 2 + 0],  w1 = g_bw[b * 2 + 1];
            const float* h0 = g_hout + ((size_t)p0 * TT + t) * (2 * HH) + k0 + kv;
            const float* h1 = g_hout + ((size_t)p1 * TT + t) * (2 * HH) + k0 + kv;
            float4 v0 = __ldg((const float4*)h0);
            float4 v1 = __ldg((const float4*)h1);
            float4 v = make_float4(w0 * v0.x + w1 * v1.x, w0 * v0.y + w1 * v1.y,
                                   w0 * v0.z + w1 * v1.z, w0 * v0.w + w1 * v1.w);
            int kv2 = kv >> 1;
            As2[kv2][row]     = make_float2(v.x, v.y);
            As2[kv2 + 1][row] = make_float2(v.z, v.w);
        }
#pragma unroll
        for (int it = 0; it < 4; it++) {
            int idx = tid + it * 256;
            int row = idx >> 3;
            int kv  = (idx & 7) * 4;
            float4 v = *(const float4*)(Wout + (size_t)(n0 + row) * K + k0 + kv);
            int kv2 = kv >> 1;
            Bs2[kv2][row]     = make_float2(v.x, v.y);
            Bs2[kv2 + 1][row] = make_float2(v.z, v.w);
        }
        __syncthreads();
#pragma unroll
        for (int kk2 = 0; kk2 < TKk / 2; kk2++) {
            u64 a2[8], b2[8];
#pragma unroll
            for (int i = 0; i < 8; i++) a2[i] = *(const u64*)&As2[kk2][ty + 16 * i];
#pragma unroll
            for (int j = 0; j < 8; j++) b2[j] = *(const u64*)&Bs2[kk2][tx + 16 * j];
#pragma unroll
            for (int i = 0; i < 8; i++)
#pragma unroll
                for (int j = 0; j < 8; j++) acc2[i][j] = ffma2(a2[i], b2[j], acc2[i][j]);
        }
        __syncthreads();
    }
#pragma unroll
    for (int j = 0; j < 8; j++) {
        int n = n0 + tx + 16 * j;
        float bv = bout[n];
#pragma unroll
        for (int i = 0; i < 8; i++) {
            int m = m0 + ty + 16 * i;
            out[(size_t)m * OUTD + n] = f2sum(acc2[i][j]) + bv;
        }
    }
}

// ---------------- persistent LSTM recurrence, W resident in SMEM --------------
// 128 blocks = 4 experts x 32 col-tiles (16 cols). Two sequential direction
// phases per block; W tile (64 gate-rows x 512) loaded to smem once per phase.
// Lane map: r0 = lane&3 (row slot), gl = lane>>2 = gate + 4*colhalf.
// Warp w covers cols j0 + w*2 + {0,1}. Gates recombined via shfl_xor at tail.

template<int RPL>
__device__ void lstm_phase(int e, int d, int j0, int off, int cnt,
                           const float* __restrict__ Whh,
                           u64* __restrict__ wsu, u64* __restrict__ hs)
{
    const int g = e * 2 + d;
    int tid = threadIdx.x;

    // ---- W preload: 64 rows x 512 floats = 8192 float4 over 256 threads ----
    {
        const float* W = Whh + (size_t)g * G4H * HH;
#pragma unroll
        for (int it = 0; it < 32; it++) {
            int idx = tid + it * 256;       // 0..8191
            int r = idx >> 7;               // gate-row 0..63
            int f = idx & 127;              // float4 index
            int lc = r >> 2, gate = r & 3;
            int grow = gate * HH + j0 + lc;
            float4 v = __ldg((const float4*)(W + (size_t)grow * HH + f * 4));
            union { float4 f4; u64 u2[2]; } cv; cv.f4 = v;
            wsu[r * WS_STRIDE + f * 2]     = cv.u2[0];
            wsu[r * WS_STRIDE + f * 2 + 1] = cv.u2[1];
        }
    }
    __syncthreads();

    int lane = tid & 31, w = tid >> 5;
    int r0 = lane & 3;
    int gl = lane >> 2;                 // 0..7 = gate + 4*colhalf
    int gate = gl & 3;
    int lc = w * 2 + (gl >> 2);
    int j = j0 + lc;
    const u64* wrow = wsu + (size_t)(w * 8 + gl) * WS_STRIDE;

    int rows[RPL], chains[RPL];
#pragma unroll
    for (int ri = 0; ri < RPL; ri++) {
        rows[ri] = r0 + ri * 4;
        chains[ri] = (off + rows[ri]) * 2 + d;
    }
    float c_reg[RPL];
#pragma unroll
    for (int ri = 0; ri < RPL; ri++) c_reg[ri] = 0.f;

    int* bar = &g_gbar[g];
    const int RR = RPL * 4;             // rows covered

    for (int s = 0; s < TT; s++) {
        int rb = s & 1;
        int t = d ? (TT - 1 - s) : s;
        const float* hread = g_hbuf[rb];
        float* hwrite = g_hbuf[rb ^ 1];

        // xp prefetch (own gate only)
        float xpv[RPL];
#pragma unroll
        for (int ri = 0; ri < RPL; ri++) {
            xpv[ri] = 0.f;
            if (rows[ri] < cnt)
                xpv[ri] = __ldg(g_xp + ((size_t)chains[ri] * TT + t) * G4H + gate * HH + j);
        }

        // h fill: RR rows x 128 float4
#pragma unroll
        for (int it = 0; it < RR / 2; it++) {
            int idx = tid + it * 256;
            int row = idx >> 7;
            int f = idx & 127;
            float4 v = make_float4(0.f, 0.f, 0.f, 0.f);
            if (row < cnt)
                v = __ldcg((const float4*)(hread + (size_t)((off + row) * 2 + d) * HH + f * 4));
            union { float4 f4; u64 u2[2]; } cv; cv.f4 = v;
            hs[row * HS_STRIDE + f * 2]     = cv.u2[0];
            hs[row * HS_STRIDE + f * 2 + 1] = cv.u2[1];
        }
        __syncthreads();

        u64 acc[RPL];
#pragma unroll
        for (int ri = 0; ri < RPL; ri++) acc[ri] = 0ull;

#pragma unroll 8
        for (int kq = 0; kq < 128; kq++) {
            ulonglong2 wv = *(const ulonglong2*)&wrow[kq * 2];
#pragma unroll
            for (int ri = 0; ri < RPL; ri++) {
                ulonglong2 h2 = *(const ulonglong2*)&hs[rows[ri] * HS_STRIDE + kq * 2];
                acc[ri] = ffma2(h2.x, wv.x, acc[ri]);
                acc[ri] = ffma2(h2.y, wv.y, acc[ri]);
            }
        }

        // tail: recombine gates via shfl, update cell, store h
#pragma unroll
        for (int ri = 0; ri < RPL; ri++) {
            float v = xpv[ri] + f2sum(acc[ri]);
            float vx = __shfl_xor_sync(0xffffffffu, v, 4);
            float lo = (gate & 1) ? vx : v;
            float hi = (gate & 1) ? v : vx;
            float lo2 = __shfl_xor_sync(0xffffffffu, lo, 8);
            float hi2 = __shfl_xor_sync(0xffffffffu, hi, 8);
            float gi = (gate & 2) ? lo2 : lo;
            float gf = (gate & 2) ? hi2 : hi;
            float gg = (gate & 2) ? lo : lo2;
            float go = (gate & 2) ? hi : hi2;
            float iv = sigmoid_fast(gi);
            float fv = sigmoid_fast(gf);
            float gv = __tanhf(gg);
            float ov = sigmoid_fast(go);
            float cvv = fv * c_reg[ri] + iv * gv;
            c_reg[ri] = cvv;
            float hvv = ov * __tanhf(cvv);
            if (gate == 0 && rows[ri] < cnt) {
                __stcg(hwrite + (size_t)chains[ri] * HH + j, hvv);
                __stcg(g_hout + ((size_t)(off + rows[ri]) * TT + t) * (2 * HH) + d * HH + j, hvv);
            }
        }

        // per-group barrier (32 blocks)
        __threadfence();
        __syncthreads();
        if (tid == 0) {
            atomicAdd(bar, 1);
            while (ld_acq(bar) < (s + 1) * 32) __nanosleep(64);
        }
        __syncthreads();
    }
}

template<int RPL>
__device__ void lstm_both_dirs(int e, int j0, int off, int cnt,
                               const float* __restrict__ Whh,
                               u64* wsu, u64* hs)
{
    lstm_phase<RPL>(e, 0, j0, off, cnt, Whh, wsu, hs);
    lstm_phase<RPL>(e, 1, j0, off, cnt, Whh, wsu, hs);
}

__global__ __launch_bounds__(256, 1) void lstm_persist_kernel(const float* __restrict__ Whh) {
    extern __shared__ __align__(16) u64 smem_dyn[];
    u64* wsu = smem_dyn;
    u64* hs  = smem_dyn + WS_ROWS * WS_STRIDE;

    int bid = blockIdx.x;
    int e = bid >> 5;
    int ct = bid & 31;
    int j0 = ct * 16;
    int cnt = g_cnt[e];
    int off = g_off[e];
    if (cnt == 0) return;
    if (cnt <= 4)       lstm_both_dirs<1>(e, j0, off, cnt, Whh, wsu, hs);
    else if (cnt <= 8)  lstm_both_dirs<2>(e, j0, off, cnt, Whh, wsu, hs);
    else if (cnt <= 16) lstm_both_dirs<4>(e, j0, off, cnt, Whh, wsu, hs);
    else                lstm_both_dirs<8>(e, j0, off, cnt, Whh, wsu, hs);
}

__global__ void write_lb_kernel(float* out, int out_size) {
    out[out_size - 1] = g_lb;
}

// ---------------- host entry --------------------------------------------------
extern "C" void kernel_launch(void* const* d_in, const int* in_sizes, int n_in,
                              void* d_out, int out_size) {
    const float* x    = (const float*)d_in[0];
    const float* rW1  = (const float*)d_in[1];
    const float* rb1  = (const float*)d_in[2];
    const float* rW2  = (const float*)d_in[3];
    const float* rb2  = (const float*)d_in[4];
    const float* Wih  = (const float*)d_in[5];
    const float* Whh  = (const float*)d_in[6];
    const float* bih  = (const float*)d_in[7];
    const float* bhh  = (const float*)d_in[8];
    const float* Wout = (const float*)d_in[9];
    const float* bout = (const float*)d_in[10];
    float* out = (float*)d_out;
    (void)in_sizes; (void)n_in;

    cudaFuncSetAttribute(lstm_persist_kernel,
                         cudaFuncAttributeMaxDynamicSharedMemorySize, SMEM_BYTES);

    mean_kernel<<<BB, II>>>(x);
    router1_kernel<<<BB, 256>>>(rW1, rb1);
    router2_kernel<<<1, 128>>>(rW2, rb2);
    init_state_kernel<<<(NCHAIN * HH + 255) / 256, 256>>>();

    dim3 gxp(G4H / TNn, TT / TMm, NCHAIN);      // (16, 4, 128)
    xp_gemm_kernel<<<gxp, 256>>>(x, Wih, bih, bhh);

    lstm_persist_kernel<<<LSTM_BLOCKS, 256, SMEM_BYTES>>>(Whh);

    dim3 gout(OUTD / TNn, (BB * TT) / TMm);     // (4, 128)
    out_gemm_fused_kernel<<<gout, 256>>>(Wout, bout, out);

    write_lb_kernel<<<1, 1>>>(out, out_size);
}

// round 7
// speedup vs baseline: 1.6250x; 1.6250x over previous
#include <cuda_runtime.h>
#include <cuda_bf16.h>
#include <cstdint>

typedef unsigned long long u64;

// Problem constants
#define BB 32
#define TT 512
#define II 512
#define HH 512
#define G4H 2048
#define EE 4
#define OUTD 512
#define NPAIR 64
#define NCHAIN 128
#define LSTM_BLOCKS 128   // 8 (e,d) groups x 16 col-tiles (32 cols each)

// smem layouts (u64 units)
#define WS_KSTRIDE 130    // [kq_local][out0..127] + pad
#define WS_TILE    (32 * WS_KSTRIDE)          // one 64-k tile
#define HS_KSTRIDE 34     // [kq_global][row0..31] + pad
#define HS_SIZE    (256 * HS_KSTRIDE)
#define SMEM_U64   (2 * WS_TILE + HS_SIZE)
#define SMEM_BYTES (SMEM_U64 * 8)             // 136,192 B

// ---------------- device scratch ----------------------------------------------
__device__ __align__(16) float g_xp[(size_t)NCHAIN * TT * G4H];       // 512 MB
__device__ __align__(16) float g_hout[(size_t)NPAIR * TT * 2 * HH];   // 128 MB
__device__ __align__(16) float g_hbuf[2][NCHAIN * HH];
__device__ __align__(16) float g_router_in[BB * II];
__device__ __align__(16) float g_router_h[BB * II];
__device__ int   g_pair_b[NPAIR];
__device__ int   g_pair_e[NPAIR];
__device__ int   g_off[EE];
__device__ int   g_cnt[EE];
__device__ int   g_bpair[BB * 2];
__device__ float g_bw[BB * 2];
__device__ float g_lb;
__device__ int   g_gbar[8];

// ---------------- helpers ------------------------------------------------------
__device__ __forceinline__ u64 ffma2(u64 a, u64 b, u64 c) {
    u64 d;
    asm("fma.rn.f32x2 %0, %1, %2, %3;" : "=l"(d) : "l"(a), "l"(b), "l"(c));
    return d;
}
__device__ __forceinline__ float f2sum(u64 v) {
    float lo, hi;
    asm("mov.b64 {%0,%1}, %2;" : "=f"(lo), "=f"(hi) : "l"(v));
    return lo + hi;
}
__device__ __forceinline__ float sigmoid_fast(float x) {
    return 0.5f * __tanhf(0.5f * x) + 0.5f;
}
__device__ __forceinline__ int ld_acq(const int* p) {
    int v;
    asm volatile("ld.acquire.gpu.b32 %0, [%1];" : "=r"(v) : "l"(p));
    return v;
}

// ---------------- router -------------------------------------------------------
__global__ void mean_kernel(const float* __restrict__ x) {
    int b = blockIdx.x;
    int i = threadIdx.x;
    const float* xb = x + (size_t)b * TT * II + i;
    float s = 0.f;
    for (int t = 0; t < TT; t++) s += xb[(size_t)t * II];
    g_router_in[b * II + i] = s * (1.0f / (float)TT);
}

__global__ void router1_kernel(const float* __restrict__ rW1, const float* __restrict__ rb1) {
    int b = blockIdx.x;
    __shared__ float rin[II];
    for (int i = threadIdx.x; i < II; i += blockDim.x) rin[i] = g_router_in[b * II + i];
    __syncthreads();
    for (int n = threadIdx.x; n < II; n += blockDim.x) {
        float s = rb1[n];
        const float* w = rW1 + (size_t)n * II;
        for (int k = 0; k < II; k += 4) {
            float4 wv = *(const float4*)(w + k);
            s += rin[k] * wv.x + rin[k + 1] * wv.y + rin[k + 2] * wv.z + rin[k + 3] * wv.w;
        }
        float sg = 1.f / (1.f + expf(-s));
        g_router_h[b * II + n] = s * sg;
    }
}

__global__ void router2_kernel(const float* __restrict__ rW2, const float* __restrict__ rb2) {
    __shared__ float logits[BB][EE];
    __shared__ float probs[BB][EE];
    __shared__ float gate[BB][EE];
    int tid = threadIdx.x;
    {
        int b = tid >> 2, e = tid & 3;
        float s = rb2[e];
        const float* w = rW2 + (size_t)e * II;
        const float* h = g_router_h + (size_t)b * II;
        for (int k = 0; k < II; k++) s += h[k] * w[k];
        logits[b][e] = s;
    }
    __syncthreads();
    if (tid < BB) {
        int b = tid;
        float m = logits[b][0];
        for (int e = 1; e < EE; e++) m = fmaxf(m, logits[b][e]);
        float pr[EE], sum = 0.f;
        for (int e = 0; e < EE; e++) { pr[e] = expf(logits[b][e] - m); sum += pr[e]; }
        for (int e = 0; e < EE; e++) { pr[e] /= sum; probs[b][e] = pr[e]; gate[b][e] = 0.f; }
        int i1 = 0;
        for (int e = 1; e < EE; e++) if (pr[e] > pr[i1]) i1 = e;
        int i2 = -1;
        for (int e = 0; e < EE; e++) {
            if (e == i1) continue;
            if (i2 < 0 || pr[e] > pr[i2]) i2 = e;
        }
        float ws = pr[i1] + pr[i2];
        gate[b][i1] = pr[i1] / ws;
        gate[b][i2] = pr[i2] / ws;
    }
    __syncthreads();
    if (tid == 0) {
        float lb = 0.f;
        for (int e = 0; e < EE; e++) {
            float u = 0.f;
            for (int b = 0; b < BB; b++) u += probs[b][e];
            u *= (1.f / (float)BB);
            float d = u - 1.0f / (float)EE;
            lb += d * d;
        }
        g_lb = 0.01f * (lb / (float)EE);
        int P = 0;
        int slotc[BB];
        for (int b = 0; b < BB; b++) slotc[b] = 0;
        for (int e = 0; e < EE; e++) {
            g_off[e] = P;
            for (int b = 0; b < BB; b++) {
                if (gate[b][e] > 0.f) {
                    g_pair_b[P] = b;
                    g_pair_e[P] = e;
                    g_bpair[b * 2 + slotc[b]] = P;
                    g_bw[b * 2 + slotc[b]] = gate[b][e];
                    slotc[b]++;
                    P++;
                }
            }
            g_cnt[e] = P - g_off[e];
        }
    }
}

__global__ void init_state_kernel() {
    int idx = blockIdx.x * blockDim.x + threadIdx.x;
    if (idx < 8) g_gbar[idx] = 0;
    if (idx < NCHAIN * HH) {
        g_hbuf[0][idx] = 0.f;
        g_hbuf[1][idx] = 0.f;
    }
}

// ---------- 128x128 reg-blocked SGEMM, k-packed f32x2 --------------------------
#define TMm 128
#define TNn 128
#define TKk 32

__device__ __forceinline__ void sgemm_block(
    const float* __restrict__ A, const float* __restrict__ Bw,
    float* __restrict__ C, int ldc, int K, int m0, int n0,
    const float* __restrict__ bias1, const float* __restrict__ bias2)
{
    __shared__ float2 As2[TKk / 2][TMm + 1];
    __shared__ float2 Bs2[TKk / 2][TNn + 1];
    int tid = threadIdx.x;
    int tx = tid & 15;
    int ty = tid >> 4;
    u64 acc2[8][8];
#pragma unroll
    for (int i = 0; i < 8; i++)
#pragma unroll
        for (int j = 0; j < 8; j++) acc2[i][j] = 0ull;

    for (int k0 = 0; k0 < K; k0 += TKk) {
#pragma unroll
        for (int it = 0; it < 4; it++) {
            int idx = tid + it * 256;
            int row = idx >> 3;
            int kv  = (idx & 7) * 4;
            float4 v = *(const float4*)(A + (size_t)(m0 + row) * K + k0 + kv);
            int kv2 = kv >> 1;
            As2[kv2][row]     = make_float2(v.x, v.y);
            As2[kv2 + 1][row] = make_float2(v.z, v.w);
        }
#pragma unroll
        for (int it = 0; it < 4; it++) {
            int idx = tid + it * 256;
            int row = idx >> 3;
            int kv  = (idx & 7) * 4;
            float4 v = *(const float4*)(Bw + (size_t)(n0 + row) * K + k0 + kv);
            int kv2 = kv >> 1;
            Bs2[kv2][row]     = make_float2(v.x, v.y);
            Bs2[kv2 + 1][row] = make_float2(v.z, v.w);
        }
        __syncthreads();
#pragma unroll
        for (int kk2 = 0; kk2 < TKk / 2; kk2++) {
            u64 a2[8], b2[8];
#pragma unroll
            for (int i = 0; i < 8; i++) a2[i] = *(const u64*)&As2[kk2][ty + 16 * i];
#pragma unroll
            for (int j = 0; j < 8; j++) b2[j] = *(const u64*)&Bs2[kk2][tx + 16 * j];
#pragma unroll
            for (int i = 0; i < 8; i++)
#pragma unroll
                for (int j = 0; j < 8; j++) acc2[i][j] = ffma2(a2[i], b2[j], acc2[i][j]);
        }
        __syncthreads();
    }
#pragma unroll
    for (int j = 0; j < 8; j++) {
        int n = n0 + tx + 16 * j;
        float bv = 0.f;
        if (bias1) bv += bias1[n];
        if (bias2) bv += bias2[n];
#pragma unroll
        for (int i = 0; i < 8; i++) {
            int m = m0 + ty + 16 * i;
            C[(size_t)m * ldc + n] = f2sum(acc2[i][j]) + bv;
        }
    }
}

__global__ __launch_bounds__(256, 1) void xp_gemm_kernel(
    const float* __restrict__ x, const float* __restrict__ Wih,
    const float* __restrict__ bih, const float* __restrict__ bhh)
{
    int z = blockIdx.z;
    int p = z >> 1, d = z & 1;
    int b = g_pair_b[p];
    int e = g_pair_e[p];
    int ed = e * 2 + d;
    const float* A  = x + (size_t)b * TT * II;
    const float* Bw = Wih + (size_t)ed * G4H * II;
    const float* b1 = bih + (size_t)ed * G4H;
    const float* b2 = bhh + (size_t)ed * G4H;
    float* C = g_xp + (size_t)z * TT * G4H;
    sgemm_block(A, Bw, C, G4H, II, blockIdx.y * TMm, blockIdx.x * TNn, b1, b2);
}

__global__ __launch_bounds__(256, 1) void out_gemm_fused_kernel(
    const float* __restrict__ Wout, const float* __restrict__ bout, float* __restrict__ out)
{
    const int K = 2 * HH;
    int m0 = blockIdx.y * TMm, n0 = blockIdx.x * TNn;
    __shared__ float2 As2[TKk / 2][TMm + 1];
    __shared__ float2 Bs2[TKk / 2][TNn + 1];
    int tid = threadIdx.x;
    int tx = tid & 15;
    int ty = tid >> 4;
    u64 acc2[8][8];
#pragma unroll
    for (int i = 0; i < 8; i++)
#pragma unroll
        for (int j = 0; j < 8; j++) acc2[i][j] = 0ull;

    for (int k0 = 0; k0 < K; k0 += TKk) {
#pragma unroll
        for (int it = 0; it < 4; it++) {
            int idx = tid + it * 256;
            int row = idx >> 3;
            int kv  = (idx & 7) * 4;
            int m = m0 + row;
            int b = m >> 9, t = m & (TT - 1);
            int p0 = g_bpair[b * 2 + 0], p1 = g_bpair[b * 2 + 1];
            float w0 = g_bw[b * 2 + 0],  w1 = g_bw[b * 2 + 1];
            const float* h0 = g_hout + ((size_t)p0 * TT + t) * (2 * HH) + k0 + kv;
            const float* h1 = g_hout + ((size_t)p1 * TT + t) * (2 * HH) + k0 + kv;
            float4 v0 = __ldg((const float4*)h0);
            float4 v1 = __ldg((const float4*)h1);
            float4 v = make_float4(w0 * v0.x + w1 * v1.x, w0 * v0.y + w1 * v1.y,
                                   w0 * v0.z + w1 * v1.z, w0 * v0.w + w1 * v1.w);
            int kv2 = kv >> 1;
            As2[kv2][row]     = make_float2(v.x, v.y);
            As2[kv2 + 1][row] = make_float2(v.z, v.w);
        }
#pragma unroll
        for (int it = 0; it < 4; it++) {
            int idx = tid + it * 256;
            int row = idx >> 3;
            int kv  = (idx & 7) * 4;
            float4 v = *(const float4*)(Wout + (size_t)(n0 + row) * K + k0 + kv);
            int kv2 = kv >> 1;
            Bs2[kv2][row]     = make_float2(v.x, v.y);
            Bs2[kv2 + 1][row] = make_float2(v.z, v.w);
        }
        __syncthreads();
#pragma unroll
        for (int kk2 = 0; kk2 < TKk / 2; kk2++) {
            u64 a2[8], b2[8];
#pragma unroll
            for (int i = 0; i < 8; i++) a2[i] = *(const u64*)&As2[kk2][ty + 16 * i];
#pragma unroll
            for (int j = 0; j < 8; j++) b2[j] = *(const u64*)&Bs2[kk2][tx + 16 * j];
#pragma unroll
            for (int i = 0; i < 8; i++)
#pragma unroll
                for (int j = 0; j < 8; j++) acc2[i][j] = ffma2(a2[i], b2[j], acc2[i][j]);
        }
        __syncthreads();
    }
#pragma unroll
    for (int j = 0; j < 8; j++) {
        int n = n0 + tx + 16 * j;
        float bv = bout[n];
#pragma unroll
        for (int i = 0; i < 8; i++) {
            int m = m0 + ty + 16 * i;
            out[(size_t)m * OUTD + n] = f2sum(acc2[i][j]) + bv;
        }
    }
}

// ---------------- persistent LSTM recurrence -----------------------------------
// 128 blocks = 8 (e,d) groups x 16 col-tiles (32 cols). 256 threads.
// Warp w: cols j0 + w*4 .. +3 (x 4 gates = 16 outputs). Lane: r0=lane&3 (row
// slot), hv=lane>>2 (8 groups of 2 outputs: col=w*4+(hv>>1), gates 2*(hv&1)+{0,1}).
// RPL = ceil(cnt/4) rows per lane. W streamed per 64-k tile, double-buffered.
// h full-k resident in smem, filled once per step. Gate recombine: shfl_xor(4).

template<int RPL>
__device__ void run_lstm(int g, int d, int j0, int off, int cnt,
                         const float* __restrict__ Whh, u64* __restrict__ smem)
{
    u64* wsA = smem;                       // 2 tile buffers
    u64* hs  = smem + 2 * WS_TILE;         // [kq_global][row]

    int tid = threadIdx.x;
    int lane = tid & 31, w = tid >> 5;
    int r0 = lane & 3, hv = lane >> 2;
    int col = w * 4 + (hv >> 1);
    int gbase = (hv & 1) * 2;              // my gates: gbase, gbase+1
    int j = j0 + col;

    // W fill mapping: 8 float4 per thread per tile
    const float* wsrc[8];
    int wdst_out[8], wdst_kq[8];
#pragma unroll
    for (int it = 0; it < 8; it++) {
        int idx = tid + it * 256;          // 0..2047
        int out = idx >> 4;                // 0..127
        int fq  = idx & 15;                // float4 within 64 k
        int ww = out >> 4, rem = out & 15;
        int c = ww * 4 + (rem >> 2);
        int gate = ((rem >> 1) & 1) * 2 + (rem & 1);
        int grow = gate * HH + j0 + c;
        wsrc[it] = Whh + (size_t)grow * HH + fq * 4;
        wdst_out[it] = out;
        wdst_kq[it]  = fq * 2;             // local kpair base
    }

    // compute-lane rows
    int rows[RPL], chains[RPL];
#pragma unroll
    for (int ri = 0; ri < RPL; ri++) {
        rows[ri] = r0 + ri * 4;
        chains[ri] = (off + rows[ri]) * 2 + d;
    }
    float c_reg[RPL];
#pragma unroll
    for (int ri = 0; ri < RPL; ri++) c_reg[ri] = 0.f;

    int* bar = &g_gbar[g];

    // prologue: prefetch W tile 0
    float4 wreg[8];
#pragma unroll
    for (int it = 0; it < 8; it++) wreg[it] = __ldg((const float4*)wsrc[it]);

    for (int s = 0; s < TT; s++) {
        int rb = s & 1;
        int t = d ? (TT - 1 - s) : s;
        const float* hread = g_hbuf[rb];
        float* hwrite = g_hbuf[rb ^ 1];

        // xp prefetch (my 2 gates x RPL rows)
        float xpv[RPL][2];
#pragma unroll
        for (int ri = 0; ri < RPL; ri++) {
            xpv[ri][0] = xpv[ri][1] = 0.f;
            if (rows[ri] < cnt) {
                const float* xpt = g_xp + ((size_t)chains[ri] * TT + t) * G4H;
                xpv[ri][0] = __ldg(xpt + (gbase + 0) * HH + j);
                xpv[ri][1] = __ldg(xpt + (gbase + 1) * HH + j);
            }
        }

        // h fill: RR rows x 128 float4 = RPL*512 float4 over 256 threads
        //  => exactly 2*RPL iterations  (R6 bug: was ceil(RPL/2))
#pragma unroll
        for (int it = 0; it < 2 * RPL; it++) {
            int idx = tid + it * 256;
            int row = idx >> 7;
            int f = idx & 127;
            float4 v = make_float4(0.f, 0.f, 0.f, 0.f);
            if (row < cnt)
                v = __ldcg((const float4*)(hread + (size_t)((off + row) * 2 + d) * HH + f * 4));
            union { float4 f4; u64 u2[2]; } cv; cv.f4 = v;
            hs[(f * 2 + 0) * HS_KSTRIDE + row] = cv.u2[0];
            hs[(f * 2 + 1) * HS_KSTRIDE + row] = cv.u2[1];
        }

        u64 acc[RPL][2];
#pragma unroll
        for (int ri = 0; ri < RPL; ri++) { acc[ri][0] = 0ull; acc[ri][1] = 0ull; }

        for (int kt = 0; kt < 8; kt++) {
            u64* wbuf = wsA + (kt & 1) * WS_TILE;
            // store prefetched tile kt
#pragma unroll
            for (int it = 0; it < 8; it++) {
                union { float4 f4; u64 u2[2]; } cv; cv.f4 = wreg[it];
                wbuf[(wdst_kq[it] + 0) * WS_KSTRIDE + wdst_out[it]] = cv.u2[0];
                wbuf[(wdst_kq[it] + 1) * WS_KSTRIDE + wdst_out[it]] = cv.u2[1];
            }
            __syncthreads();   // covers h-fill (kt==0) + this tile's STS
            // prefetch tile kt+1 (wraps to next step's tile 0)
            {
                int nk = ((kt + 1) & 7) * 64;
#pragma unroll
                for (int it = 0; it < 8; it++)
                    wreg[it] = __ldg((const float4*)(wsrc[it] + nk));
            }
            // compute tile kt
            const u64* wp = wbuf + w * 16 + hv * 2;
            const u64* hp = hs + (kt * 32) * HS_KSTRIDE;
#pragma unroll 8
            for (int kql = 0; kql < 32; kql++) {
                ulonglong2 wv = *(const ulonglong2*)(wp + kql * WS_KSTRIDE);
#pragma unroll
                for (int ri = 0; ri < RPL; ri++) {
                    u64 h2 = hp[kql * HS_KSTRIDE + rows[ri]];
                    acc[ri][0] = ffma2(h2, wv.x, acc[ri][0]);
                    acc[ri][1] = ffma2(h2, wv.y, acc[ri][1]);
                }
            }
            __syncthreads();
        }

        // tail: recombine gates, cell update, store h
#pragma unroll
        for (int ri = 0; ri < RPL; ri++) {
            float v0 = xpv[ri][0] + f2sum(acc[ri][0]);
            float v1 = xpv[ri][1] + f2sum(acc[ri][1]);
            float p0 = __shfl_xor_sync(0xffffffffu, v0, 4);
            float p1 = __shfl_xor_sync(0xffffffffu, v1, 4);
            float gi = (hv & 1) ? p0 : v0;
            float gf = (hv & 1) ? p1 : v1;
            float gg = (hv & 1) ? v0 : p0;
            float go = (hv & 1) ? v1 : p1;
            float iv = sigmoid_fast(gi);
            float fv = sigmoid_fast(gf);
            float gv = __tanhf(gg);
            float ov = sigmoid_fast(go);
            float cvv = fv * c_reg[ri] + iv * gv;
            c_reg[ri] = cvv;
            float hvv = ov * __tanhf(cvv);
            if (!(hv & 1) && rows[ri] < cnt) {
                __stcg(hwrite + (size_t)chains[ri] * HH + j, hvv);
                __stcg(g_hout + ((size_t)(off + rows[ri]) * TT + t) * (2 * HH) + d * HH + j, hvv);
            }
        }

        // group-local barrier (16 blocks)
        __threadfence();
        __syncthreads();
        if (tid == 0) {
            atomicAdd(bar, 1);
            int target = (s + 1) * 16;
            while (ld_acq(bar) < target) { }
        }
        __syncthreads();
    }
}

__global__ __launch_bounds__(256, 1) void lstm_persist_kernel(const float* __restrict__ Whh) {
    extern __shared__ __align__(16) u64 smem_dyn[];
    int bid = blockIdx.x;
    int g = bid >> 4;                 // (e,d) group
    int ct = bid & 15;
    int e = g >> 1, d = g & 1;
    int cnt = g_cnt[e];
    int off = g_off[e];
    int j0 = ct * 32;
    if (cnt == 0) return;
    const float* W = Whh + (size_t)g * G4H * HH;
    int rpl = (cnt + 3) >> 2;
    switch (rpl) {
        case 1: run_lstm<1>(g, d, j0, off, cnt, W, smem_dyn); break;
        case 2: run_lstm<2>(g, d, j0, off, cnt, W, smem_dyn); break;
        case 3: run_lstm<3>(g, d, j0, off, cnt, W, smem_dyn); break;
        case 4: run_lstm<4>(g, d, j0, off, cnt, W, smem_dyn); break;
        case 5: run_lstm<5>(g, d, j0, off, cnt, W, smem_dyn); break;
        case 6: run_lstm<6>(g, d, j0, off, cnt, W, smem_dyn); break;
        case 7: run_lstm<7>(g, d, j0, off, cnt, W, smem_dyn); break;
        default: run_lstm<8>(g, d, j0, off, cnt, W, smem_dyn); break;
    }
}

__global__ void write_lb_kernel(float* out, int out_size) {
    out[out_size - 1] = g_lb;
}

// ---------------- host entry ---------------------------------------------------
extern "C" void kernel_launch(void* const* d_in, const int* in_sizes, int n_in,
                              void* d_out, int out_size) {
    const float* x    = (const float*)d_in[0];
    const float* rW1  = (const float*)d_in[1];
    const float* rb1  = (const float*)d_in[2];
    const float* rW2  = (const float*)d_in[3];
    const float* rb2  = (const float*)d_in[4];
    const float* Wih  = (const float*)d_in[5];
    const float* Whh  = (const float*)d_in[6];
    const float* bih  = (const float*)d_in[7];
    const float* bhh  = (const float*)d_in[8];
    const float* Wout = (const float*)d_in[9];
    const float* bout = (const float*)d_in[10];
    float* out = (float*)d_out;
    (void)in_sizes; (void)n_in;

    cudaFuncSetAttribute(lstm_persist_kernel,
                         cudaFuncAttributeMaxDynamicSharedMemorySize, SMEM_BYTES);

    mean_kernel<<<BB, II>>>(x);
    router1_kernel<<<BB, 256>>>(rW1, rb1);
    router2_kernel<<<1, 128>>>(rW2, rb2);

    dim3 gxp(G4H / TNn, TT / TMm, NCHAIN);      // (16, 4, 128)
    xp_gemm_kernel<<<gxp, 256>>>(x, Wih, bih, bhh);   // 4th launch -> profiled slot

    init_state_kernel<<<(NCHAIN * HH + 255) / 256, 256>>>();

    lstm_persist_kernel<<<LSTM_BLOCKS, 256, SMEM_BYTES>>>(Whh);

    dim3 gout(OUTD / TNn, (BB * TT) / TMm);     // (4, 128)
    out_gemm_fused_kernel<<<gout, 256>>>(Wout, bout, out);

    write_lb_kernel<<<1, 1>>>(out, out_size);
}

// round 8
// speedup vs baseline: 1.6445x; 1.0120x over previous
#include <cuda_runtime.h>
#include <cuda_bf16.h>
#include <cstdint>

typedef unsigned long long u64;

// Problem constants
#define BB 32
#define TT 512
#define II 512
#define HH 512
#define G4H 2048
#define EE 4
#define OUTD 512
#define NPAIR 64
#define NCHAIN 128
#define LSTM_BLOCKS 128   // 8 (e,d) groups x 16 col-tiles (32 cols each)

// smem layouts (u64 units)
#define WS_KSTRIDE 130    // [kq_local 0..31][out 0..127] + pad
#define WS_TILE    (32 * WS_KSTRIDE)          // one 64-k tile buffer (33,280 B)
#define HS_KSTRIDE 34     // [kq_global][row 0..31] + pad
#define HS_SIZE    (256 * HS_KSTRIDE)
#define SMEM_U64   (4 * WS_TILE + HS_SIZE)    // 4 W bufs (2 per k-half) + h
#define SMEM_BYTES (SMEM_U64 * 8)             // 202,752 B

// ---------------- device scratch ----------------------------------------------
__device__ __align__(16) float g_xp[(size_t)NCHAIN * TT * G4H];       // 512 MB
__device__ __align__(16) float g_hout[(size_t)NPAIR * TT * 2 * HH];   // 128 MB
__device__ __align__(16) float g_hbuf[2][NCHAIN * HH];
__device__ __align__(16) float g_router_in[BB * II];
__device__ __align__(16) float g_router_h[BB * II];
__device__ int   g_pair_b[NPAIR];
__device__ int   g_pair_e[NPAIR];
__device__ int   g_off[EE];
__device__ int   g_cnt[EE];
__device__ int   g_bpair[BB * 2];
__device__ float g_bw[BB * 2];
__device__ float g_lb;
__device__ int   g_gbar[8];

// ---------------- helpers ------------------------------------------------------
__device__ __forceinline__ u64 ffma2(u64 a, u64 b, u64 c) {
    u64 d;
    asm("fma.rn.f32x2 %0, %1, %2, %3;" : "=l"(d) : "l"(a), "l"(b), "l"(c));
    return d;
}
__device__ __forceinline__ float f2sum(u64 v) {
    float lo, hi;
    asm("mov.b64 {%0,%1}, %2;" : "=f"(lo), "=f"(hi) : "l"(v));
    return lo + hi;
}
__device__ __forceinline__ float sigmoid_fast(float x) {
    return 0.5f * __tanhf(0.5f * x) + 0.5f;
}
__device__ __forceinline__ int ld_acq(const int* p) {
    int v;
    asm volatile("ld.acquire.gpu.b32 %0, [%1];" : "=r"(v) : "l"(p));
    return v;
}

// ---------------- router -------------------------------------------------------
__global__ void mean_kernel(const float* __restrict__ x) {
    int b = blockIdx.x;
    int i = threadIdx.x;
    const float* xb = x + (size_t)b * TT * II + i;
    float s = 0.f;
    for (int t = 0; t < TT; t++) s += xb[(size_t)t * II];
    g_router_in[b * II + i] = s * (1.0f / (float)TT);
}

__global__ void router1_kernel(const float* __restrict__ rW1, const float* __restrict__ rb1) {
    int b = blockIdx.x;
    __shared__ float rin[II];
    for (int i = threadIdx.x; i < II; i += blockDim.x) rin[i] = g_router_in[b * II + i];
    __syncthreads();
    for (int n = threadIdx.x; n < II; n += blockDim.x) {
        float s = rb1[n];
        const float* w = rW1 + (size_t)n * II;
        for (int k = 0; k < II; k += 4) {
            float4 wv = *(const float4*)(w + k);
            s += rin[k] * wv.x + rin[k + 1] * wv.y + rin[k + 2] * wv.z + rin[k + 3] * wv.w;
        }
        float sg = 1.f / (1.f + expf(-s));
        g_router_h[b * II + n] = s * sg;
    }
}

__global__ void router2_kernel(const float* __restrict__ rW2, const float* __restrict__ rb2) {
    __shared__ float logits[BB][EE];
    __shared__ float probs[BB][EE];
    __shared__ float gate[BB][EE];
    int tid = threadIdx.x;
    {
        int b = tid >> 2, e = tid & 3;
        float s = rb2[e];
        const float* w = rW2 + (size_t)e * II;
        const float* h = g_router_h + (size_t)b * II;
        for (int k = 0; k < II; k++) s += h[k] * w[k];
        logits[b][e] = s;
    }
    __syncthreads();
    if (tid < BB) {
        int b = tid;
        float m = logits[b][0];
        for (int e = 1; e < EE; e++) m = fmaxf(m, logits[b][e]);
        float pr[EE], sum = 0.f;
        for (int e = 0; e < EE; e++) { pr[e] = expf(logits[b][e] - m); sum += pr[e]; }
        for (int e = 0; e < EE; e++) { pr[e] /= sum; probs[b][e] = pr[e]; gate[b][e] = 0.f; }
        int i1 = 0;
        for (int e = 1; e < EE; e++) if (pr[e] > pr[i1]) i1 = e;
        int i2 = -1;
        for (int e = 0; e < EE; e++) {
            if (e == i1) continue;
            if (i2 < 0 || pr[e] > pr[i2]) i2 = e;
        }
        float ws = pr[i1] + pr[i2];
        gate[b][i1] = pr[i1] / ws;
        gate[b][i2] = pr[i2] / ws;
    }
    __syncthreads();
    if (tid == 0) {
        float lb = 0.f;
        for (int e = 0; e < EE; e++) {
            float u = 0.f;
            for (int b = 0; b < BB; b++) u += probs[b][e];
            u *= (1.f / (float)BB);
            float d = u - 1.0f / (float)EE;
            lb += d * d;
        }
        g_lb = 0.01f * (lb / (float)EE);
        int P = 0;
        int slotc[BB];
        for (int b = 0; b < BB; b++) slotc[b] = 0;
        for (int e = 0; e < EE; e++) {
            g_off[e] = P;
            for (int b = 0; b < BB; b++) {
                if (gate[b][e] > 0.f) {
                    g_pair_b[P] = b;
                    g_pair_e[P] = e;
                    g_bpair[b * 2 + slotc[b]] = P;
                    g_bw[b * 2 + slotc[b]] = gate[b][e];
                    slotc[b]++;
                    P++;
                }
            }
            g_cnt[e] = P - g_off[e];
        }
    }
}

__global__ void init_state_kernel() {
    int idx = blockIdx.x * blockDim.x + threadIdx.x;
    if (idx < 8) g_gbar[idx] = 0;
    if (idx < NCHAIN * HH) {
        g_hbuf[0][idx] = 0.f;
        g_hbuf[1][idx] = 0.f;
    }
}

// ---------- 128x128 reg-blocked SGEMM, k-packed f32x2 --------------------------
#define TMm 128
#define TNn 128
#define TKk 32

__device__ __forceinline__ void sgemm_block(
    const float* __restrict__ A, const float* __restrict__ Bw,
    float* __restrict__ C, int ldc, int K, int m0, int n0,
    const float* __restrict__ bias1, const float* __restrict__ bias2)
{
    __shared__ float2 As2[TKk / 2][TMm + 1];
    __shared__ float2 Bs2[TKk / 2][TNn + 1];
    int tid = threadIdx.x;
    int tx = tid & 15;
    int ty = tid >> 4;
    u64 acc2[8][8];
#pragma unroll
    for (int i = 0; i < 8; i++)
#pragma unroll
        for (int j = 0; j < 8; j++) acc2[i][j] = 0ull;

    for (int k0 = 0; k0 < K; k0 += TKk) {
#pragma unroll
        for (int it = 0; it < 4; it++) {
            int idx = tid + it * 256;
            int row = idx >> 3;
            int kv  = (idx & 7) * 4;
            float4 v = *(const float4*)(A + (size_t)(m0 + row) * K + k0 + kv);
            int kv2 = kv >> 1;
            As2[kv2][row]     = make_float2(v.x, v.y);
            As2[kv2 + 1][row] = make_float2(v.z, v.w);
        }
#pragma unroll
        for (int it = 0; it < 4; it++) {
            int idx = tid + it * 256;
            int row = idx >> 3;
            int kv  = (idx & 7) * 4;
            float4 v = *(const float4*)(Bw + (size_t)(n0 + row) * K + k0 + kv);
            int kv2 = kv >> 1;
            Bs2[kv2][row]     = make_float2(v.x, v.y);
            Bs2[kv2 + 1][row] = make_float2(v.z, v.w);
        }
        __syncthreads();
#pragma unroll
        for (int kk2 = 0; kk2 < TKk / 2; kk2++) {
            u64 a2[8], b2[8];
#pragma unroll
            for (int i = 0; i < 8; i++) a2[i] = *(const u64*)&As2[kk2][ty + 16 * i];
#pragma unroll
            for (int j = 0; j < 8; j++) b2[j] = *(const u64*)&Bs2[kk2][tx + 16 * j];
#pragma unroll
            for (int i = 0; i < 8; i++)
#pragma unroll
                for (int j = 0; j < 8; j++) acc2[i][j] = ffma2(a2[i], b2[j], acc2[i][j]);
        }
        __syncthreads();
    }
#pragma unroll
    for (int j = 0; j < 8; j++) {
        int n = n0 + tx + 16 * j;
        float bv = 0.f;
        if (bias1) bv += bias1[n];
        if (bias2) bv += bias2[n];
#pragma unroll
        for (int i = 0; i < 8; i++) {
            int m = m0 + ty + 16 * i;
            C[(size_t)m * ldc + n] = f2sum(acc2[i][j]) + bv;
        }
    }
}

__global__ __launch_bounds__(256, 1) void xp_gemm_kernel(
    const float* __restrict__ x, const float* __restrict__ Wih,
    const float* __restrict__ bih, const float* __restrict__ bhh)
{
    int z = blockIdx.z;
    int p = z >> 1, d = z & 1;
    int b = g_pair_b[p];
    int e = g_pair_e[p];
    int ed = e * 2 + d;
    const float* A  = x + (size_t)b * TT * II;
    const float* Bw = Wih + (size_t)ed * G4H * II;
    const float* b1 = bih + (size_t)ed * G4H;
    const float* b2 = bhh + (size_t)ed * G4H;
    float* C = g_xp + (size_t)z * TT * G4H;
    sgemm_block(A, Bw, C, G4H, II, blockIdx.y * TMm, blockIdx.x * TNn, b1, b2);
}

__global__ __launch_bounds__(256, 1) void out_gemm_fused_kernel(
    const float* __restrict__ Wout, const float* __restrict__ bout, float* __restrict__ out)
{
    const int K = 2 * HH;
    int m0 = blockIdx.y * TMm, n0 = blockIdx.x * TNn;
    __shared__ float2 As2[TKk / 2][TMm + 1];
    __shared__ float2 Bs2[TKk / 2][TNn + 1];
    int tid = threadIdx.x;
    int tx = tid & 15;
    int ty = tid >> 4;
    u64 acc2[8][8];
#pragma unroll
    for (int i = 0; i < 8; i++)
#pragma unroll
        for (int j = 0; j < 8; j++) acc2[i][j] = 0ull;

    for (int k0 = 0; k0 < K; k0 += TKk) {
#pragma unroll
        for (int it = 0; it < 4; it++) {
            int idx = tid + it * 256;
            int row = idx >> 3;
            int kv  = (idx & 7) * 4;
            int m = m0 + row;
            int b = m >> 9, t = m & (TT - 1);
            int p0 = g_bpair[b * 2 + 0], p1 = g_bpair[b * 2 + 1];
            float w0 = g_bw[b * 2 + 0],  w1 = g_bw[b * 2 + 1];
            const float* h0 = g_hout + ((size_t)p0 * TT + t) * (2 * HH) + k0 + kv;
            const float* h1 = g_hout + ((size_t)p1 * TT + t) * (2 * HH) + k0 + kv;
            float4 v0 = __ldg((const float4*)h0);
            float4 v1 = __ldg((const float4*)h1);
            float4 v = make_float4(w0 * v0.x + w1 * v1.x, w0 * v0.y + w1 * v1.y,
                                   w0 * v0.z + w1 * v1.z, w0 * v0.w + w1 * v1.w);
            int kv2 = kv >> 1;
            As2[kv2][row]     = make_float2(v.x, v.y);
            As2[kv2 + 1][row] = make_float2(v.z, v.w);
        }
#pragma unroll
        for (int it = 0; it < 4; it++) {
            int idx = tid + it * 256;
            int row = idx >> 3;
            int kv  = (idx & 7) * 4;
            float4 v = *(const float4*)(Wout + (size_t)(n0 + row) * K + k0 + kv);
            int kv2 = kv >> 1;
            Bs2[kv2][row]     = make_float2(v.x, v.y);
            Bs2[kv2 + 1][row] = make_float2(v.z, v.w);
        }
        __syncthreads();
#pragma unroll
        for (int kk2 = 0; kk2 < TKk / 2; kk2++) {
            u64 a2[8], b2[8];
#pragma unroll
            for (int i = 0; i < 8; i++) a2[i] = *(const u64*)&As2[kk2][ty + 16 * i];
#pragma unroll
            for (int j = 0; j < 8; j++) b2[j] = *(const u64*)&Bs2[kk2][tx + 16 * j];
#pragma unroll
            for (int i = 0; i < 8; i++)
#pragma unroll
                for (int j = 0; j < 8; j++) acc2[i][j] = ffma2(a2[i], b2[j], acc2[i][j]);
        }
        __syncthreads();
    }
#pragma unroll
    for (int j = 0; j < 8; j++) {
        int n = n0 + tx + 16 * j;
        float bv = bout[n];
#pragma unroll
        for (int i = 0; i < 8; i++) {
            int m = m0 + ty + 16 * i;
            out[(size_t)m * OUTD + n] = f2sum(acc2[i][j]) + bv;
        }
    }
}

// ---------------- persistent LSTM recurrence -----------------------------------
// 128 blocks = 8 (e,d) groups x 16 col-tiles (32 cols). 512 threads:
// k-split — half 0 (warps 0-7) k in [0,256), half 1 (warps 8-15) k in [256,512).
// Within a half: warp w': cols j0 + w'*4..+3 x 4 gates. Lane: r0=lane&3,
// hv=lane>>2 (col=w'*4+(hv>>1), gates (hv&1)*2+{0,1}). RPL=ceil(cnt/4).
// Per half: 4 double-buffered 64-k W tiles, ONE sync per tile. Partial accs
// combined via smem (half1 -> half0), tail on half 0 only.

template<int RPL>
__device__ void run_lstm(int g, int d, int j0, int off, int cnt,
                         const float* __restrict__ Whh, u64* __restrict__ smem)
{
    u64* wsA = smem;                       // 4 tile buffers (2 per half)
    u64* hs  = smem + 4 * WS_TILE;         // [kq_global][row]
    u64* redbuf = wsA;                     // aliases buf0 (safe: see ordering)

    int tid = threadIdx.x;
    int half = tid >> 8;                   // 0 or 1
    int htid = tid & 255;
    int lane = tid & 31;
    int w8 = htid >> 5;                    // warp within half: 0..7
    int r0 = lane & 3, hv = lane >> 2;
    int col = w8 * 4 + (hv >> 1);
    int gbase = (hv & 1) * 2;
    int j = j0 + col;
    int kbase = half * 256;                // float offset of my k-half

    // W fill mapping: 8 float4 per thread per 64-k tile (per half: 256 threads)
    const float* wsrc[8];
    int wdst_out[8];
    int fq = htid & 15;                    // float4 index within tile
#pragma unroll
    for (int it = 0; it < 8; it++) {
        int idx = htid + it * 256;         // 0..2047
        int out = idx >> 4;                // 0..127
        int ww = out >> 4, rem = out & 15;
        int c = ww * 4 + (rem >> 2);
        int gate = ((rem >> 1) & 1) * 2 + (rem & 1);
        int grow = gate * HH + j0 + c;
        wsrc[it] = Whh + (size_t)grow * HH + kbase + fq * 4;
        wdst_out[it] = out;
    }

    // compute-lane rows
    int rows[RPL], chains[RPL];
#pragma unroll
    for (int ri = 0; ri < RPL; ri++) {
        rows[ri] = r0 + ri * 4;
        chains[ri] = (off + rows[ri]) * 2 + d;
    }
    float c_reg[RPL];
#pragma unroll
    for (int ri = 0; ri < RPL; ri++) c_reg[ri] = 0.f;

    int* bar = &g_gbar[g];

    // prologue: prefetch W tile 0 of my half
    float4 wreg[8];
#pragma unroll
    for (int it = 0; it < 8; it++) wreg[it] = __ldg((const float4*)wsrc[it]);

    for (int s = 0; s < TT; s++) {
        int rb = s & 1;
        int t = d ? (TT - 1 - s) : s;
        const float* hread = g_hbuf[rb];
        float* hwrite = g_hbuf[rb ^ 1];

        // xp prefetch (half 0 only; tail lives there)
        float xpv[RPL][2];
        if (half == 0) {
#pragma unroll
            for (int ri = 0; ri < RPL; ri++) {
                xpv[ri][0] = xpv[ri][1] = 0.f;
                if (rows[ri] < cnt) {
                    const float* xpt = g_xp + ((size_t)chains[ri] * TT + t) * G4H;
                    xpv[ri][0] = __ldg(xpt + (gbase + 0) * HH + j);
                    xpv[ri][1] = __ldg(xpt + (gbase + 1) * HH + j);
                }
            }
        }

        // h fill: each half fills its k-half: RR rows x 64 float4 over 256 thr
#pragma unroll
        for (int it = 0; it < RPL; it++) {
            int idx = htid + it * 256;
            int row = idx >> 6;            // 0..4*RPL-1
            int fl = idx & 63;
            int f4g = half * 64 + fl;
            float4 v = make_float4(0.f, 0.f, 0.f, 0.f);
            if (row < cnt)
                v = __ldcg((const float4*)(hread + (size_t)((off + row) * 2 + d) * HH + f4g * 4));
            union { float4 f4; u64 u2[2]; } cv; cv.f4 = v;
            hs[(f4g * 2 + 0) * HS_KSTRIDE + row] = cv.u2[0];
            hs[(f4g * 2 + 1) * HS_KSTRIDE + row] = cv.u2[1];
        }

        // store prefetched tile 0 into buf[half*2 + 0]
        {
            u64* wbuf = wsA + (half * 2 + 0) * WS_TILE;
#pragma unroll
            for (int it = 0; it < 8; it++) {
                union { float4 f4; u64 u2[2]; } cv; cv.f4 = wreg[it];
                wbuf[(fq * 2 + 0) * WS_KSTRIDE + wdst_out[it]] = cv.u2[0];
                wbuf[(fq * 2 + 1) * WS_KSTRIDE + wdst_out[it]] = cv.u2[1];
            }
        }
        __syncthreads();

        u64 acc[RPL][2];
#pragma unroll
        for (int ri = 0; ri < RPL; ri++) { acc[ri][0] = 0ull; acc[ri][1] = 0ull; }

#pragma unroll
        for (int kt = 0; kt < 4; kt++) {
            int nkt = (kt + 1) & 3;
            // prefetch next tile (kt==3 wraps to next step's tile 0)
#pragma unroll
            for (int it = 0; it < 8; it++)
                wreg[it] = __ldg((const float4*)(wsrc[it] + nkt * 64));
            // compute tile kt from buf[half*2 + (kt&1)]
            {
                const u64* wbuf = wsA + (half * 2 + (kt & 1)) * WS_TILE;
                const u64* wp = wbuf + w8 * 16 + hv * 2;
                const u64* hp = hs + (half * 128 + kt * 32) * HS_KSTRIDE;
#pragma unroll 8
                for (int kql = 0; kql < 32; kql++) {
                    ulonglong2 wv = *(const ulonglong2*)(wp + kql * WS_KSTRIDE);
#pragma unroll
                    for (int ri = 0; ri < RPL; ri++) {
                        u64 h2 = hp[kql * HS_KSTRIDE + rows[ri]];
                        acc[ri][0] = ffma2(h2, wv.x, acc[ri][0]);
                        acc[ri][1] = ffma2(h2, wv.y, acc[ri][1]);
                    }
                }
            }
            // store next tile into the other buffer (not read this phase)
            if (kt < 3) {
                u64* wbuf = wsA + (half * 2 + (nkt & 1)) * WS_TILE;
#pragma unroll
                for (int it = 0; it < 8; it++) {
                    union { float4 f4; u64 u2[2]; } cv; cv.f4 = wreg[it];
                    wbuf[(fq * 2 + 0) * WS_KSTRIDE + wdst_out[it]] = cv.u2[0];
                    wbuf[(fq * 2 + 1) * WS_KSTRIDE + wdst_out[it]] = cv.u2[1];
                }
            }
            __syncthreads();
        }

        // k-split reduction: half 1 exports partial accs (into buf0 region,
        // whose last reader was kt2 — done by kt2's sync)
        if (half == 1) {
#pragma unroll
            for (int ri = 0; ri < RPL; ri++) {
                redbuf[((w8 * 32 + lane) * RPL + ri) * 2 + 0] = acc[ri][0];
                redbuf[((w8 * 32 + lane) * RPL + ri) * 2 + 1] = acc[ri][1];
            }
        }
        __syncthreads();

        // tail on half 0
        if (half == 0) {
#pragma unroll
            for (int ri = 0; ri < RPL; ri++) {
                u64 b0 = redbuf[((w8 * 32 + lane) * RPL + ri) * 2 + 0];
                u64 b1 = redbuf[((w8 * 32 + lane) * RPL + ri) * 2 + 1];
                float v0 = xpv[ri][0] + f2sum(acc[ri][0]) + f2sum(b0);
                float v1 = xpv[ri][1] + f2sum(acc[ri][1]) + f2sum(b1);
                float p0 = __shfl_xor_sync(0xffffffffu, v0, 4);
                float p1 = __shfl_xor_sync(0xffffffffu, v1, 4);
                float gi = (hv & 1) ? p0 : v0;
                float gf = (hv & 1) ? p1 : v1;
                float gg = (hv & 1) ? v0 : p0;
                float go = (hv & 1) ? v1 : p1;
                float iv = sigmoid_fast(gi);
                float fv = sigmoid_fast(gf);
                float gv = __tanhf(gg);
                float ov = sigmoid_fast(go);
                float cvv = fv * c_reg[ri] + iv * gv;
                c_reg[ri] = cvv;
                float hvv = ov * __tanhf(cvv);
                if (!(hv & 1) && rows[ri] < cnt) {
                    __stcg(hwrite + (size_t)chains[ri] * HH + j, hvv);
                    __stcg(g_hout + ((size_t)(off + rows[ri]) * TT + t) * (2 * HH) + d * HH + j, hvv);
                }
            }
        }

        // group-local barrier (16 blocks)
        __threadfence();
        __syncthreads();
        if (tid == 0) {
            atomicAdd(bar, 1);
            int target = (s + 1) * 16;
            while (ld_acq(bar) < target) __nanosleep(20);
        }
        __syncthreads();
    }
}

__global__ __launch_bounds__(512, 1) void lstm_persist_kernel(const float* __restrict__ Whh) {
    extern __shared__ __align__(16) u64 smem_dyn[];
    int bid = blockIdx.x;
    int g = bid >> 4;
    int ct = bid & 15;
    int e = g >> 1, d = g & 1;
    int cnt = g_cnt[e];
    int off = g_off[e];
    int j0 = ct * 32;
    if (cnt == 0) return;
    const float* W = Whh + (size_t)g * G4H * HH;
    int rpl = (cnt + 3) >> 2;
    switch (rpl) {
        case 1: run_lstm<1>(g, d, j0, off, cnt, W, smem_dyn); break;
        case 2: run_lstm<2>(g, d, j0, off, cnt, W, smem_dyn); break;
        case 3: run_lstm<3>(g, d, j0, off, cnt, W, smem_dyn); break;
        case 4: run_lstm<4>(g, d, j0, off, cnt, W, smem_dyn); break;
        case 5: run_lstm<5>(g, d, j0, off, cnt, W, smem_dyn); break;
        case 6: run_lstm<6>(g, d, j0, off, cnt, W, smem_dyn); break;
        case 7: run_lstm<7>(g, d, j0, off, cnt, W, smem_dyn); break;
        default: run_lstm<8>(g, d, j0, off, cnt, W, smem_dyn); break;
    }
}

__global__ void write_lb_kernel(float* out, int out_size) {
    out[out_size - 1] = g_lb;
}

// ---------------- host entry ---------------------------------------------------
extern "C" void kernel_launch(void* const* d_in, const int* in_sizes, int n_in,
                              void* d_out, int out_size) {
    const float* x    = (const float*)d_in[0];
    const float* rW1  = (const float*)d_in[1];
    const float* rb1  = (const float*)d_in[2];
    const float* rW2  = (const float*)d_in[3];
    const float* rb2  = (const float*)d_in[4];
    const float* Wih  = (const float*)d_in[5];
    const float* Whh  = (const float*)d_in[6];
    const float* bih  = (const float*)d_in[7];
    const float* bhh  = (const float*)d_in[8];
    const float* Wout = (const float*)d_in[9];
    const float* bout = (const float*)d_in[10];
    float* out = (float*)d_out;
    (void)in_sizes; (void)n_in;

    cudaFuncSetAttribute(lstm_persist_kernel,
                         cudaFuncAttributeMaxDynamicSharedMemorySize, SMEM_BYTES);

    mean_kernel<<<BB, II>>>(x);
    router1_kernel<<<BB, 256>>>(rW1, rb1);
    router2_kernel<<<1, 128>>>(rW2, rb2);

    dim3 gxp(G4H / TNn, TT / TMm, NCHAIN);      // (16, 4, 128)
    xp_gemm_kernel<<<gxp, 256>>>(x, Wih, bih, bhh);

    init_state_kernel<<<(NCHAIN * HH + 255) / 256, 256>>>();

    lstm_persist_kernel<<<LSTM_BLOCKS, 512, SMEM_BYTES>>>(Whh);

    dim3 gout(OUTD / TNn, (BB * TT) / TMm);     // (4, 128)
    out_gemm_fused_kernel<<<gout, 256>>>(Wout, bout, out);

    write_lb_kernel<<<1, 1>>>(out, out_size);
}

// round 9
// speedup vs baseline: 1.6449x; 1.0003x over previous
#include <cuda_runtime.h>
#include <cuda_bf16.h>
#include <cstdint>

typedef unsigned long long u64;

// Problem constants
#define BB 32
#define TT 512
#define II 512
#define HH 512
#define G4H 2048
#define EE 4
#define OUTD 512
#define NPAIR 64
#define NCHAIN 128
#define LSTM_BLOCKS 128   // 8 (e,d) groups x 16 col-tiles (32 cols each)

// smem layouts (u64 units) for recurrence
#define WS_KSTRIDE 130
#define WS_TILE    (32 * WS_KSTRIDE)
#define HS_KSTRIDE 34
#define HS_SIZE    (256 * HS_KSTRIDE)
#define SMEM_U64   (4 * WS_TILE + HS_SIZE)
#define SMEM_BYTES (SMEM_U64 * 8)             // 202,752 B

// ---------------- device scratch ----------------------------------------------
__device__ __align__(16) float g_xp[(size_t)NCHAIN * TT * G4H];       // 512 MB
__device__ __align__(16) float g_hout[(size_t)NPAIR * TT * 2 * HH];   // 128 MB
__device__ __align__(16) float g_hbuf[2][NCHAIN * HH];
__device__ __align__(16) float g_router_in[BB * II];
__device__ __align__(16) float g_router_h[BB * II];
__device__ int   g_pair_b[NPAIR];
__device__ int   g_pair_e[NPAIR];
__device__ int   g_off[EE];
__device__ int   g_cnt[EE];
__device__ int   g_bpair[BB * 2];
__device__ float g_bw[BB * 2];
__device__ float g_lb;
__device__ int   g_gbar[8];

// ---------------- helpers ------------------------------------------------------
__device__ __forceinline__ u64 ffma2(u64 a, u64 b, u64 c) {
    u64 d;
    asm("fma.rn.f32x2 %0, %1, %2, %3;" : "=l"(d) : "l"(a), "l"(b), "l"(c));
    return d;
}
__device__ __forceinline__ float f2sum(u64 v) {
    float lo, hi;
    asm("mov.b64 {%0,%1}, %2;" : "=f"(lo), "=f"(hi) : "l"(v));
    return lo + hi;
}
__device__ __forceinline__ float sigmoid_fast(float x) {
    return 0.5f * __tanhf(0.5f * x) + 0.5f;
}
__device__ __forceinline__ int ld_acq(const int* p) {
    int v;
    asm volatile("ld.acquire.gpu.b32 %0, [%1];" : "=r"(v) : "l"(p));
    return v;
}
__device__ __forceinline__ void red_release_add(int* p, int v) {
    asm volatile("red.release.gpu.global.add.s32 [%0], %1;" :: "l"(p), "r"(v) : "memory");
}

// ---------------- router -------------------------------------------------------
__global__ void mean_kernel(const float* __restrict__ x) {
    int b = blockIdx.x;
    int i = threadIdx.x;
    const float* xb = x + (size_t)b * TT * II + i;
    float s = 0.f;
    for (int t = 0; t < TT; t++) s += xb[(size_t)t * II];
    g_router_in[b * II + i] = s * (1.0f / (float)TT);
}

__global__ void router1_kernel(const float* __restrict__ rW1, const float* __restrict__ rb1) {
    int b = blockIdx.x;
    __shared__ float rin[II];
    for (int i = threadIdx.x; i < II; i += blockDim.x) rin[i] = g_router_in[b * II + i];
    __syncthreads();
    for (int n = threadIdx.x; n < II; n += blockDim.x) {
        float s = rb1[n];
        const float* w = rW1 + (size_t)n * II;
        for (int k = 0; k < II; k += 4) {
            float4 wv = *(const float4*)(w + k);
            s += rin[k] * wv.x + rin[k + 1] * wv.y + rin[k + 2] * wv.z + rin[k + 3] * wv.w;
        }
        float sg = 1.f / (1.f + expf(-s));
        g_router_h[b * II + n] = s * sg;
    }
}

__global__ void router2_kernel(const float* __restrict__ rW2, const float* __restrict__ rb2) {
    __shared__ float logits[BB][EE];
    __shared__ float probs[BB][EE];
    __shared__ float gate[BB][EE];
    int tid = threadIdx.x;
    {
        int b = tid >> 2, e = tid & 3;
        float s = rb2[e];
        const float* w = rW2 + (size_t)e * II;
        const float* h = g_router_h + (size_t)b * II;
        for (int k = 0; k < II; k++) s += h[k] * w[k];
        logits[b][e] = s;
    }
    __syncthreads();
    if (tid < BB) {
        int b = tid;
        float m = logits[b][0];
        for (int e = 1; e < EE; e++) m = fmaxf(m, logits[b][e]);
        float pr[EE], sum = 0.f;
        for (int e = 0; e < EE; e++) { pr[e] = expf(logits[b][e] - m); sum += pr[e]; }
        for (int e = 0; e < EE; e++) { pr[e] /= sum; probs[b][e] = pr[e]; gate[b][e] = 0.f; }
        int i1 = 0;
        for (int e = 1; e < EE; e++) if (pr[e] > pr[i1]) i1 = e;
        int i2 = -1;
        for (int e = 0; e < EE; e++) {
            if (e == i1) continue;
            if (i2 < 0 || pr[e] > pr[i2]) i2 = e;
        }
        float ws = pr[i1] + pr[i2];
        gate[b][i1] = pr[i1] / ws;
        gate[b][i2] = pr[i2] / ws;
    }
    __syncthreads();
    if (tid == 0) {
        float lb = 0.f;
        for (int e = 0; e < EE; e++) {
            float u = 0.f;
            for (int b = 0; b < BB; b++) u += probs[b][e];
            u *= (1.f / (float)BB);
            float d = u - 1.0f / (float)EE;
            lb += d * d;
        }
        g_lb = 0.01f * (lb / (float)EE);
        int P = 0;
        int slotc[BB];
        for (int b = 0; b < BB; b++) slotc[b] = 0;
        for (int e = 0; e < EE; e++) {
            g_off[e] = P;
            for (int b = 0; b < BB; b++) {
                if (gate[b][e] > 0.f) {
                    g_pair_b[P] = b;
                    g_pair_e[P] = e;
                    g_bpair[b * 2 + slotc[b]] = P;
                    g_bw[b * 2 + slotc[b]] = gate[b][e];
                    slotc[b]++;
                    P++;
                }
            }
            g_cnt[e] = P - g_off[e];
        }
    }
}

__global__ void init_state_kernel() {
    int idx = blockIdx.x * blockDim.x + threadIdx.x;
    if (idx < 8) g_gbar[idx] = 0;
    if (idx < NCHAIN * HH) {
        g_hbuf[0][idx] = 0.f;
        g_hbuf[1][idx] = 0.f;
    }
}

// ---------- 128x128 SGEMM, f32x2, double-buffered software pipeline ------------
#define TMm 128
#define TNn 128
#define TKk 16

// C = A @ B^T + bias. ONE __syncthreads per 16-k tile; LDG of tile t+1 issued
// before compute of tile t. Buffer reuse is 2 syncs after last read -> safe.
__device__ __forceinline__ void sgemm_block(
    const float* __restrict__ A, const float* __restrict__ Bw,
    float* __restrict__ C, int ldc, int K, int m0, int n0,
    const float* __restrict__ bias1, const float* __restrict__ bias2)
{
    __shared__ float2 As2[2][TKk / 2][TMm + 1];
    __shared__ float2 Bs2[2][TKk / 2][TNn + 1];
    int tid = threadIdx.x;       // 256
    int tx = tid & 15;
    int ty = tid >> 4;
    u64 acc2[8][8];
#pragma unroll
    for (int i = 0; i < 8; i++)
#pragma unroll
        for (int j = 0; j < 8; j++) acc2[i][j] = 0ull;

    // per tile: 512 float4 per matrix over 256 threads (2 each)
    float4 pa[2], pb[2];
#pragma unroll
    for (int it = 0; it < 2; it++) {
        int idx = tid + it * 256;
        int row = idx >> 2;
        int kv  = (idx & 3) * 4;
        pa[it] = *(const float4*)(A  + (size_t)(m0 + row) * K + kv);
        pb[it] = *(const float4*)(Bw + (size_t)(n0 + row) * K + kv);
    }
    int nk = K / TKk;
    for (int kt = 0; kt < nk; kt++) {
        int bsel = kt & 1;
#pragma unroll
        for (int it = 0; it < 2; it++) {
            int idx = tid + it * 256;
            int row = idx >> 2;
            int kv2 = (idx & 3) * 2;
            As2[bsel][kv2][row]     = make_float2(pa[it].x, pa[it].y);
            As2[bsel][kv2 + 1][row] = make_float2(pa[it].z, pa[it].w);
            Bs2[bsel][kv2][row]     = make_float2(pb[it].x, pb[it].y);
            Bs2[bsel][kv2 + 1][row] = make_float2(pb[it].z, pb[it].w);
        }
        __syncthreads();
        if (kt + 1 < nk) {
            int k0n = (kt + 1) * TKk;
#pragma unroll
            for (int it = 0; it < 2; it++) {
                int idx = tid + it * 256;
                int row = idx >> 2;
                int kv  = (idx & 3) * 4;
                pa[it] = *(const float4*)(A  + (size_t)(m0 + row) * K + k0n + kv);
                pb[it] = *(const float4*)(Bw + (size_t)(n0 + row) * K + k0n + kv);
            }
        }
#pragma unroll
        for (int kk2 = 0; kk2 < TKk / 2; kk2++) {
            u64 a2[8], b2[8];
#pragma unroll
            for (int i = 0; i < 8; i++) a2[i] = *(const u64*)&As2[bsel][kk2][ty + 16 * i];
#pragma unroll
            for (int j = 0; j < 8; j++) b2[j] = *(const u64*)&Bs2[bsel][kk2][tx + 16 * j];
#pragma unroll
            for (int i = 0; i < 8; i++)
#pragma unroll
                for (int j = 0; j < 8; j++) acc2[i][j] = ffma2(a2[i], b2[j], acc2[i][j]);
        }
    }
#pragma unroll
    for (int j = 0; j < 8; j++) {
        int n = n0 + tx + 16 * j;
        float bv = 0.f;
        if (bias1) bv += bias1[n];
        if (bias2) bv += bias2[n];
#pragma unroll
        for (int i = 0; i < 8; i++) {
            int m = m0 + ty + 16 * i;
            C[(size_t)m * ldc + n] = f2sum(acc2[i][j]) + bv;
        }
    }
}

__global__ __launch_bounds__(256, 1) void xp_gemm_kernel(
    const float* __restrict__ x, const float* __restrict__ Wih,
    const float* __restrict__ bih, const float* __restrict__ bhh)
{
    int z = blockIdx.z;
    int p = z >> 1, d = z & 1;
    int b = g_pair_b[p];
    int e = g_pair_e[p];
    int ed = e * 2 + d;
    const float* A  = x + (size_t)b * TT * II;
    const float* Bw = Wih + (size_t)ed * G4H * II;
    const float* b1 = bih + (size_t)ed * G4H;
    const float* b2 = bhh + (size_t)ed * G4H;
    float* C = g_xp + (size_t)z * TT * G4H;
    sgemm_block(A, Bw, C, G4H, II, blockIdx.y * TMm, blockIdx.x * TNn, b1, b2);
}

// out-proj with fused gate-combine A; same pipelined structure
__global__ __launch_bounds__(256, 1) void out_gemm_fused_kernel(
    const float* __restrict__ Wout, const float* __restrict__ bout, float* __restrict__ out)
{
    const int K = 2 * HH;
    int m0 = blockIdx.y * TMm, n0 = blockIdx.x * TNn;
    __shared__ float2 As2[2][TKk / 2][TMm + 1];
    __shared__ float2 Bs2[2][TKk / 2][TNn + 1];
    int tid = threadIdx.x;
    int tx = tid & 15;
    int ty = tid >> 4;
    u64 acc2[8][8];
#pragma unroll
    for (int i = 0; i < 8; i++)
#pragma unroll
        for (int j = 0; j < 8; j++) acc2[i][j] = 0ull;

    // A-load helper state
    int arow[2], akv[2];
    int ap0[2], ap1[2];
    float aw0[2], aw1[2];
#pragma unroll
    for (int it = 0; it < 2; it++) {
        int idx = tid + it * 256;
        arow[it] = idx >> 2;
        akv[it]  = (idx & 3) * 4;
        int m = m0 + arow[it];
        int b = m >> 9, t = m & (TT - 1);
        ap0[it] = g_bpair[b * 2 + 0]; ap1[it] = g_bpair[b * 2 + 1];
        aw0[it] = g_bw[b * 2 + 0];    aw1[it] = g_bw[b * 2 + 1];
    }

    float4 pa[2], pb[2];
#pragma unroll
    for (int it = 0; it < 2; it++) {
        int m = m0 + arow[it];
        int t = m & (TT - 1);
        const float* h0 = g_hout + ((size_t)ap0[it] * TT + t) * (2 * HH) + akv[it];
        const float* h1 = g_hout + ((size_t)ap1[it] * TT + t) * (2 * HH) + akv[it];
        float4 v0 = __ldg((const float4*)h0);
        float4 v1 = __ldg((const float4*)h1);
        pa[it] = make_float4(aw0[it] * v0.x + aw1[it] * v1.x, aw0[it] * v0.y + aw1[it] * v1.y,
                             aw0[it] * v0.z + aw1[it] * v1.z, aw0[it] * v0.w + aw1[it] * v1.w);
        pb[it] = *(const float4*)(Wout + (size_t)(n0 + arow[it]) * K + akv[it]);
    }
    int nk = K / TKk;
    for (int kt = 0; kt < nk; kt++) {
        int bsel = kt & 1;
#pragma unroll
        for (int it = 0; it < 2; it++) {
            int row = arow[it];
            int kv2 = (akv[it] >> 1);
            As2[bsel][kv2][row]     = make_float2(pa[it].x, pa[it].y);
            As2[bsel][kv2 + 1][row] = make_float2(pa[it].z, pa[it].w);
            Bs2[bsel][kv2][row]     = make_float2(pb[it].x, pb[it].y);
            Bs2[bsel][kv2 + 1][row] = make_float2(pb[it].z, pb[it].w);
        }
        __syncthreads();
        if (kt + 1 < nk) {
            int k0n = (kt + 1) * TKk;
#pragma unroll
            for (int it = 0; it < 2; it++) {
                int m = m0 + arow[it];
                int t = m & (TT - 1);
                const float* h0 = g_hout + ((size_t)ap0[it] * TT + t) * (2 * HH) + k0n + akv[it];
                const float* h1 = g_hout + ((size_t)ap1[it] * TT + t) * (2 * HH) + k0n + akv[it];
                float4 v0 = __ldg((const float4*)h0);
                float4 v1 = __ldg((const float4*)h1);
                pa[it] = make_float4(aw0[it] * v0.x + aw1[it] * v1.x, aw0[it] * v0.y + aw1[it] * v1.y,
                                     aw0[it] * v0.z + aw1[it] * v1.z, aw0[it] * v0.w + aw1[it] * v1.w);
                pb[it] = *(const float4*)(Wout + (size_t)(n0 + arow[it]) * K + k0n + akv[it]);
            }
        }
#pragma unroll
        for (int kk2 = 0; kk2 < TKk / 2; kk2++) {
            u64 a2[8], b2[8];
#pragma unroll
            for (int i = 0; i < 8; i++) a2[i] = *(const u64*)&As2[bsel][kk2][ty + 16 * i];
#pragma unroll
            for (int j = 0; j < 8; j++) b2[j] = *(const u64*)&Bs2[bsel][kk2][tx + 16 * j];
#pragma unroll
            for (int i = 0; i < 8; i++)
#pragma unroll
                for (int j = 0; j < 8; j++) acc2[i][j] = ffma2(a2[i], b2[j], acc2[i][j]);
        }
    }
#pragma unroll
    for (int j = 0; j < 8; j++) {
        int n = n0 + tx + 16 * j;
        float bv = bout[n];
#pragma unroll
        for (int i = 0; i < 8; i++) {
            int m = m0 + ty + 16 * i;
            out[(size_t)m * OUTD + n] = f2sum(acc2[i][j]) + bv;
        }
    }
}

// ---------------- persistent LSTM recurrence (math identical to R8) ------------
template<int RPL>
__device__ void run_lstm(int g, int d, int j0, int off, int cnt,
                         const float* __restrict__ Whh, u64* __restrict__ smem)
{
    u64* wsA = smem;
    u64* hs  = smem + 4 * WS_TILE;
    u64* redbuf = wsA;

    int tid = threadIdx.x;
    int half = tid >> 8;
    int htid = tid & 255;
    int lane = tid & 31;
    int w8 = htid >> 5;
    int r0 = lane & 3, hv = lane >> 2;
    int col = w8 * 4 + (hv >> 1);
    int gbase = (hv & 1) * 2;
    int j = j0 + col;
    int kbase = half * 256;

    const float* wsrc[8];
    int wdst_out[8];
    int fq = htid & 15;
#pragma unroll
    for (int it = 0; it < 8; it++) {
        int idx = htid + it * 256;
        int out = idx >> 4;
        int ww = out >> 4, rem = out & 15;
        int c = ww * 4 + (rem >> 2);
        int gate = ((rem >> 1) & 1) * 2 + (rem & 1);
        int grow = gate * HH + j0 + c;
        wsrc[it] = Whh + (size_t)grow * HH + kbase + fq * 4;
        wdst_out[it] = out;
    }

    int rows[RPL], chains[RPL];
#pragma unroll
    for (int ri = 0; ri < RPL; ri++) {
        rows[ri] = r0 + ri * 4;
        chains[ri] = (off + rows[ri]) * 2 + d;
    }
    float c_reg[RPL];
#pragma unroll
    for (int ri = 0; ri < RPL; ri++) c_reg[ri] = 0.f;

    int* bar = &g_gbar[g];

    float4 wreg[8];
#pragma unroll
    for (int it = 0; it < 8; it++) wreg[it] = __ldg((const float4*)wsrc[it]);

    for (int s = 0; s < TT; s++) {
        int rb = s & 1;
        int t = d ? (TT - 1 - s) : s;
        const float* hread = g_hbuf[rb];
        float* hwrite = g_hbuf[rb ^ 1];

        float xpv[RPL][2];
        if (half == 0) {
#pragma unroll
            for (int ri = 0; ri < RPL; ri++) {
                xpv[ri][0] = xpv[ri][1] = 0.f;
                if (rows[ri] < cnt) {
                    const float* xpt = g_xp + ((size_t)chains[ri] * TT + t) * G4H;
                    xpv[ri][0] = __ldg(xpt + (gbase + 0) * HH + j);
                    xpv[ri][1] = __ldg(xpt + (gbase + 1) * HH + j);
                }
            }
        }

#pragma unroll
        for (int it = 0; it < RPL; it++) {
            int idx = htid + it * 256;
            int row = idx >> 6;
            int fl = idx & 63;
            int f4g = half * 64 + fl;
            float4 v = make_float4(0.f, 0.f, 0.f, 0.f);
            if (row < cnt)
                v = __ldcg((const float4*)(hread + (size_t)((off + row) * 2 + d) * HH + f4g * 4));
            union { float4 f4; u64 u2[2]; } cv; cv.f4 = v;
            hs[(f4g * 2 + 0) * HS_KSTRIDE + row] = cv.u2[0];
            hs[(f4g * 2 + 1) * HS_KSTRIDE + row] = cv.u2[1];
        }

        {
            u64* wbuf = wsA + (half * 2 + 0) * WS_TILE;
#pragma unroll
            for (int it = 0; it < 8; it++) {
                union { float4 f4; u64 u2[2]; } cv; cv.f4 = wreg[it];
                wbuf[(fq * 2 + 0) * WS_KSTRIDE + wdst_out[it]] = cv.u2[0];
                wbuf[(fq * 2 + 1) * WS_KSTRIDE + wdst_out[it]] = cv.u2[1];
            }
        }
        __syncthreads();

        u64 acc[RPL][2];
#pragma unroll
        for (int ri = 0; ri < RPL; ri++) { acc[ri][0] = 0ull; acc[ri][1] = 0ull; }

#pragma unroll
        for (int kt = 0; kt < 4; kt++) {
            int nkt = (kt + 1) & 3;
#pragma unroll
            for (int it = 0; it < 8; it++)
                wreg[it] = __ldg((const float4*)(wsrc[it] + nkt * 64));
            {
                const u64* wbuf = wsA + (half * 2 + (kt & 1)) * WS_TILE;
                const u64* wp = wbuf + w8 * 16 + hv * 2;
                const u64* hp = hs + (half * 128 + kt * 32) * HS_KSTRIDE;
#pragma unroll 8
                for (int kql = 0; kql < 32; kql++) {
                    ulonglong2 wv = *(const ulonglong2*)(wp + kql * WS_KSTRIDE);
#pragma unroll
                    for (int ri = 0; ri < RPL; ri++) {
                        u64 h2 = hp[kql * HS_KSTRIDE + rows[ri]];
                        acc[ri][0] = ffma2(h2, wv.x, acc[ri][0]);
                        acc[ri][1] = ffma2(h2, wv.y, acc[ri][1]);
                    }
                }
            }
            if (kt < 3) {
                u64* wbuf = wsA + (half * 2 + (nkt & 1)) * WS_TILE;
#pragma unroll
                for (int it = 0; it < 8; it++) {
                    union { float4 f4; u64 u2[2]; } cv; cv.f4 = wreg[it];
                    wbuf[(fq * 2 + 0) * WS_KSTRIDE + wdst_out[it]] = cv.u2[0];
                    wbuf[(fq * 2 + 1) * WS_KSTRIDE + wdst_out[it]] = cv.u2[1];
                }
            }
            __syncthreads();
        }

        if (half == 1) {
#pragma unroll
            for (int ri = 0; ri < RPL; ri++) {
                redbuf[((w8 * 32 + lane) * RPL + ri) * 2 + 0] = acc[ri][0];
                redbuf[((w8 * 32 + lane) * RPL + ri) * 2 + 1] = acc[ri][1];
            }
        }
        __syncthreads();

        if (half == 0) {
#pragma unroll
            for (int ri = 0; ri < RPL; ri++) {
                u64 b0 = redbuf[((w8 * 32 + lane) * RPL + ri) * 2 + 0];
                u64 b1 = redbuf[((w8 * 32 + lane) * RPL + ri) * 2 + 1];
                float v0 = xpv[ri][0] + f2sum(acc[ri][0]) + f2sum(b0);
                float v1 = xpv[ri][1] + f2sum(acc[ri][1]) + f2sum(b1);
                float p0 = __shfl_xor_sync(0xffffffffu, v0, 4);
                float p1 = __shfl_xor_sync(0xffffffffu, v1, 4);
                float gi = (hv & 1) ? p0 : v0;
                float gf = (hv & 1) ? p1 : v1;
                float gg = (hv & 1) ? v0 : p0;
                float go = (hv & 1) ? v1 : p1;
                float iv = sigmoid_fast(gi);
                float fv = sigmoid_fast(gf);
                float gv = __tanhf(gg);
                float ov = sigmoid_fast(go);
                float cvv = fv * c_reg[ri] + iv * gv;
                c_reg[ri] = cvv;
                float hvv = ov * __tanhf(cvv);
                if (!(hv & 1) && rows[ri] < cnt) {
                    __stcg(hwrite + (size_t)chains[ri] * HH + j, hvv);
                    __stcg(g_hout + ((size_t)(off + rows[ri]) * TT + t) * (2 * HH) + d * HH + j, hvv);
                }
            }
        }

        // group-local barrier (16 blocks), release on counter (no per-thread membar)
        __syncthreads();
        if (tid == 0) {
            red_release_add(bar, 1);
            int target = (s + 1) * 16;
            while (ld_acq(bar) < target) __nanosleep(20);
        }
        __syncthreads();
    }
}

__global__ __launch_bounds__(512, 1) void lstm_persist_kernel(const float* __restrict__ Whh) {
    extern __shared__ __align__(16) u64 smem_dyn[];
    int bid = blockIdx.x;
    int g = bid >> 4;
    int ct = bid & 15;
    int e = g >> 1, d = g & 1;
    int cnt = g_cnt[e];
    int off = g_off[e];
    int j0 = ct * 32;
    if (cnt == 0) return;
    const float* W = Whh + (size_t)g * G4H * HH;
    int rpl = (cnt + 3) >> 2;
    switch (rpl) {
        case 1: run_lstm<1>(g, d, j0, off, cnt, W, smem_dyn); break;
        case 2: run_lstm<2>(g, d, j0, off, cnt, W, smem_dyn); break;
        case 3: run_lstm<3>(g, d, j0, off, cnt, W, smem_dyn); break;
        case 4: run_lstm<4>(g, d, j0, off, cnt, W, smem_dyn); break;
        case 5: run_lstm<5>(g, d, j0, off, cnt, W, smem_dyn); break;
        case 6: run_lstm<6>(g, d, j0, off, cnt, W, smem_dyn); break;
        case 7: run_lstm<7>(g, d, j0, off, cnt, W, smem_dyn); break;
        default: run_lstm<8>(g, d, j0, off, cnt, W, smem_dyn); break;
    }
}

__global__ void write_lb_kernel(float* out, int out_size) {
    out[out_size - 1] = g_lb;
}

// ---------------- host entry ---------------------------------------------------
extern "C" void kernel_launch(void* const* d_in, const int* in_sizes, int n_in,
                              void* d_out, int out_size) {
    const float* x    = (const float*)d_in[0];
    const float* rW1  = (const float*)d_in[1];
    const float* rb1  = (const float*)d_in[2];
    const float* rW2  = (const float*)d_in[3];
    const float* rb2  = (const float*)d_in[4];
    const float* Wih  = (const float*)d_in[5];
    const float* Whh  = (const float*)d_in[6];
    const float* bih  = (const float*)d_in[7];
    const float* bhh  = (const float*)d_in[8];
    const float* Wout = (const float*)d_in[9];
    const float* bout = (const float*)d_in[10];
    float* out = (float*)d_out;
    (void)in_sizes; (void)n_in;

    cudaFuncSetAttribute(lstm_persist_kernel,
                         cudaFuncAttributeMaxDynamicSharedMemorySize, SMEM_BYTES);

    mean_kernel<<<BB, II>>>(x);
    router1_kernel<<<BB, 256>>>(rW1, rb1);
    router2_kernel<<<1, 128>>>(rW2, rb2);

    dim3 gxp(G4H / TNn, TT / TMm, NCHAIN);      // (16, 4, 128)
    xp_gemm_kernel<<<gxp, 256>>>(x, Wih, bih, bhh);

    init_state_kernel<<<(NCHAIN * HH + 255) / 256, 256>>>();

    lstm_persist_kernel<<<LSTM_BLOCKS, 512, SMEM_BYTES>>>(Whh);

    dim3 gout(OUTD / TNn, (BB * TT) / TMm);     // (4, 128)
    out_gemm_fused_kernel<<<gout, 256>>>(Wout, bout, out);

    write_lb_kernel<<<1, 1>>>(out, out_size);
}

// round 10
// speedup vs baseline: 1.7129x; 1.0413x over previous
#include <cuda_runtime.h>
#include <cuda_bf16.h>
#include <cstdint>

typedef unsigned long long u64;

// Problem constants
#define BB 32
#define TT 512
#define II 512
#define HH 512
#define G4H 2048
#define EE 4
#define OUTD 512
#define NPAIR 64
#define NCHAIN 128
#define LSTM_BLOCKS 128   // 8 (e,d) groups x 16 col-tiles (32 cols each)

// smem layouts (u64 units) for recurrence
#define WS_KSTRIDE 130                         // [kq_local 0..31][out 0..127] + pad
#define WS_TILE    (32 * WS_KSTRIDE)
#define HS_RSTRIDE 258                         // [row 0..31][kq 0..255] + pad (16B-aligned rows)
#define HS_SIZE    (32 * HS_RSTRIDE)
#define SMEM_U64   (4 * WS_TILE + HS_SIZE)
#define SMEM_BYTES (SMEM_U64 * 8)              // 199,168 B

// ---------------- device scratch ----------------------------------------------
__device__ __align__(16) float g_xp[(size_t)NCHAIN * TT * G4H];       // 512 MB
__device__ __align__(16) float g_hout[(size_t)NPAIR * TT * 2 * HH];   // 128 MB
__device__ __align__(16) float g_hbuf[2][NCHAIN * HH];
__device__ __align__(16) float g_router_in[BB * II];
__device__ int   g_pair_b[NPAIR];
__device__ int   g_pair_e[NPAIR];
__device__ int   g_off[EE];
__device__ int   g_cnt[EE];
__device__ int   g_bpair[BB * 2];
__device__ float g_bw[BB * 2];
__device__ float g_lb;
__device__ int   g_gbar[8];

// ---------------- helpers ------------------------------------------------------
__device__ __forceinline__ u64 ffma2(u64 a, u64 b, u64 c) {
    u64 d;
    asm("fma.rn.f32x2 %0, %1, %2, %3;" : "=l"(d) : "l"(a), "l"(b), "l"(c));
    return d;
}
__device__ __forceinline__ float f2sum(u64 v) {
    float lo, hi;
    asm("mov.b64 {%0,%1}, %2;" : "=f"(lo), "=f"(hi) : "l"(v));
    return lo + hi;
}
__device__ __forceinline__ u64 pack2(float lo, float hi) {
    u64 v;
    asm("mov.b64 %0, {%1,%2};" : "=l"(v) : "f"(lo), "f"(hi));
    return v;
}
__device__ __forceinline__ float sigmoid_fast(float x) {
    return 0.5f * __tanhf(0.5f * x) + 0.5f;
}
__device__ __forceinline__ int ld_acq(const int* p) {
    int v;
    asm volatile("ld.acquire.gpu.b32 %0, [%1];" : "=r"(v) : "l"(p));
    return v;
}
__device__ __forceinline__ void red_release_add(int* p, int v) {
    asm volatile("red.release.gpu.global.add.s32 [%0], %1;" :: "l"(p), "r"(v) : "memory");
}

// ---------------- launch 1: fused init + mean ----------------------------------
// blocks 0..31: per-sequence mean; blocks 32..95: zero h buffers + barrier ctrs.
__global__ __launch_bounds__(512) void init_mean_kernel(const float* __restrict__ x) {
    int bid = blockIdx.x;
    int tid = threadIdx.x;
    if (bid < BB) {
        const float* xb = x + (size_t)bid * TT * II + tid;
        float s = 0.f;
        for (int t = 0; t < TT; t++) s += xb[(size_t)t * II];
        g_router_in[bid * II + tid] = s * (1.0f / (float)TT);
    } else {
        int idx = (bid - BB) * 512 + tid;          // 0..32767
        g_hbuf[0][idx] = 0.f;
        g_hbuf[0][idx + 32768] = 0.f;
        g_hbuf[1][idx] = 0.f;
        g_hbuf[1][idx + 32768] = 0.f;
        if (bid == BB && tid < 8) g_gbar[tid] = 0;
    }
}

// ---------------- launch 2: fused router (single block, 512 threads) -----------
__global__ __launch_bounds__(512, 1) void router12_kernel(
    const float* __restrict__ rW1, const float* __restrict__ rb1,
    const float* __restrict__ rW2, const float* __restrict__ rb2)
{
    extern __shared__ float rsm[];
    float* rin = rsm;                 // [BB*II] = 64 KB
    float* r1h = rsm + BB * II;      // [BB*II] = 64 KB
    __shared__ float logits[BB][EE];
    __shared__ float probs[BB][EE];
    __shared__ float gate[BB][EE];
    int tid = threadIdx.x;

    for (int i = tid; i < BB * II; i += 512) rin[i] = g_router_in[i];
    __syncthreads();

    // layer 1: thread tid owns output column n = tid for all 32 sequences
    {
        int n = tid;
        u64 acc2[BB];
#pragma unroll
        for (int b = 0; b < BB; b++) acc2[b] = 0ull;
        const float* w = rW1 + (size_t)n * II;
        for (int k = 0; k < II; k += 4) {
            float4 wv = *(const float4*)(w + k);
            u64 w01 = pack2(wv.x, wv.y);
            u64 w23 = pack2(wv.z, wv.w);
#pragma unroll
            for (int b = 0; b < BB; b++) {
                float4 rv = *(const float4*)&rin[b * II + k];
                acc2[b] = ffma2(pack2(rv.x, rv.y), w01, acc2[b]);
                acc2[b] = ffma2(pack2(rv.z, rv.w), w23, acc2[b]);
            }
        }
        float bv = rb1[n];
#pragma unroll
        for (int b = 0; b < BB; b++) {
            float s = f2sum(acc2[b]) + bv;
            float sg = 1.f / (1.f + expf(-s));
            r1h[b * II + n] = s * sg;
        }
    }
    __syncthreads();

    // layer 2: logits
    if (tid < BB * EE) {
        int b = tid >> 2, e = tid & 3;
        float s = rb2[e];
        const float* w = rW2 + (size_t)e * II;
        const float* h = r1h + (size_t)b * II;
        for (int k = 0; k < II; k++) s += h[k] * w[k];
        logits[b][e] = s;
    }
    __syncthreads();

    if (tid < BB) {
        int b = tid;
        float m = logits[b][0];
        for (int e = 1; e < EE; e++) m = fmaxf(m, logits[b][e]);
        float pr[EE], sum = 0.f;
        for (int e = 0; e < EE; e++) { pr[e] = expf(logits[b][e] - m); sum += pr[e]; }
        for (int e = 0; e < EE; e++) { pr[e] /= sum; probs[b][e] = pr[e]; gate[b][e] = 0.f; }
        int i1 = 0;
        for (int e = 1; e < EE; e++) if (pr[e] > pr[i1]) i1 = e;
        int i2 = -1;
        for (int e = 0; e < EE; e++) {
            if (e == i1) continue;
            if (i2 < 0 || pr[e] > pr[i2]) i2 = e;
        }
        float ws = pr[i1] + pr[i2];
        gate[b][i1] = pr[i1] / ws;
        gate[b][i2] = pr[i2] / ws;
    }
    __syncthreads();
    if (tid == 0) {
        float lb = 0.f;
        for (int e = 0; e < EE; e++) {
            float u = 0.f;
            for (int b = 0; b < BB; b++) u += probs[b][e];
            u *= (1.f / (float)BB);
            float d = u - 1.0f / (float)EE;
            lb += d * d;
        }
        g_lb = 0.01f * (lb / (float)EE);
        int P = 0;
        int slotc[BB];
        for (int b = 0; b < BB; b++) slotc[b] = 0;
        for (int e = 0; e < EE; e++) {
            g_off[e] = P;
            for (int b = 0; b < BB; b++) {
                if (gate[b][e] > 0.f) {
                    g_pair_b[P] = b;
                    g_pair_e[P] = e;
                    g_bpair[b * 2 + slotc[b]] = P;
                    g_bw[b * 2 + slotc[b]] = gate[b][e];
                    slotc[b]++;
                    P++;
                }
            }
            g_cnt[e] = P - g_off[e];
        }
    }
}

// ---------- 128x128 SGEMM, f32x2, double-buffered software pipeline ------------
#define TMm 128
#define TNn 128
#define TKk 16

__device__ __forceinline__ void sgemm_block(
    const float* __restrict__ A, const float* __restrict__ Bw,
    float* __restrict__ C, int ldc, int K, int m0, int n0,
    const float* __restrict__ bias1, const float* __restrict__ bias2)
{
    __shared__ float2 As2[2][TKk / 2][TMm + 1];
    __shared__ float2 Bs2[2][TKk / 2][TNn + 1];
    int tid = threadIdx.x;       // 256
    int tx = tid & 15;
    int ty = tid >> 4;
    u64 acc2[8][8];
#pragma unroll
    for (int i = 0; i < 8; i++)
#pragma unroll
        for (int j = 0; j < 8; j++) acc2[i][j] = 0ull;

    float4 pa[2], pb[2];
#pragma unroll
    for (int it = 0; it < 2; it++) {
        int idx = tid + it * 256;
        int row = idx >> 2;
        int kv  = (idx & 3) * 4;
        pa[it] = *(const float4*)(A  + (size_t)(m0 + row) * K + kv);
        pb[it] = *(const float4*)(Bw + (size_t)(n0 + row) * K + kv);
    }
    int nk = K / TKk;
    for (int kt = 0; kt < nk; kt++) {
        int bsel = kt & 1;
#pragma unroll
        for (int it = 0; it < 2; it++) {
            int idx = tid + it * 256;
            int row = idx >> 2;
            int kv2 = (idx & 3) * 2;
            As2[bsel][kv2][row]     = make_float2(pa[it].x, pa[it].y);
            As2[bsel][kv2 + 1][row] = make_float2(pa[it].z, pa[it].w);
            Bs2[bsel][kv2][row]     = make_float2(pb[it].x, pb[it].y);
            Bs2[bsel][kv2 + 1][row] = make_float2(pb[it].z, pb[it].w);
        }
        __syncthreads();
        if (kt + 1 < nk) {
            int k0n = (kt + 1) * TKk;
#pragma unroll
            for (int it = 0; it < 2; it++) {
                int idx = tid + it * 256;
                int row = idx >> 2;
                int kv  = (idx & 3) * 4;
                pa[it] = *(const float4*)(A  + (size_t)(m0 + row) * K + k0n + kv);
                pb[it] = *(const float4*)(Bw + (size_t)(n0 + row) * K + k0n + kv);
            }
        }
#pragma unroll
        for (int kk2 = 0; kk2 < TKk / 2; kk2++) {
            u64 a2[8], b2[8];
#pragma unroll
            for (int i = 0; i < 8; i++) a2[i] = *(const u64*)&As2[bsel][kk2][ty + 16 * i];
#pragma unroll
            for (int j = 0; j < 8; j++) b2[j] = *(const u64*)&Bs2[bsel][kk2][tx + 16 * j];
#pragma unroll
            for (int i = 0; i < 8; i++)
#pragma unroll
                for (int j = 0; j < 8; j++) acc2[i][j] = ffma2(a2[i], b2[j], acc2[i][j]);
        }
    }
#pragma unroll
    for (int j = 0; j < 8; j++) {
        int n = n0 + tx + 16 * j;
        float bv = 0.f;
        if (bias1) bv += bias1[n];
        if (bias2) bv += bias2[n];
#pragma unroll
        for (int i = 0; i < 8; i++) {
            int m = m0 + ty + 16 * i;
            C[(size_t)m * ldc + n] = f2sum(acc2[i][j]) + bv;
        }
    }
}

__global__ __launch_bounds__(256, 1) void xp_gemm_kernel(
    const float* __restrict__ x, const float* __restrict__ Wih,
    const float* __restrict__ bih, const float* __restrict__ bhh)
{
    int z = blockIdx.z;
    int p = z >> 1, d = z & 1;
    int b = g_pair_b[p];
    int e = g_pair_e[p];
    int ed = e * 2 + d;
    const float* A  = x + (size_t)b * TT * II;
    const float* Bw = Wih + (size_t)ed * G4H * II;
    const float* b1 = bih + (size_t)ed * G4H;
    const float* b2 = bhh + (size_t)ed * G4H;
    float* C = g_xp + (size_t)z * TT * G4H;
    sgemm_block(A, Bw, C, G4H, II, blockIdx.y * TMm, blockIdx.x * TNn, b1, b2);
}

__global__ __launch_bounds__(256, 1) void out_gemm_fused_kernel(
    const float* __restrict__ Wout, const float* __restrict__ bout, float* __restrict__ out)
{
    const int K = 2 * HH;
    int m0 = blockIdx.y * TMm, n0 = blockIdx.x * TNn;
    __shared__ float2 As2[2][TKk / 2][TMm + 1];
    __shared__ float2 Bs2[2][TKk / 2][TNn + 1];
    int tid = threadIdx.x;
    int tx = tid & 15;
    int ty = tid >> 4;
    u64 acc2[8][8];
#pragma unroll
    for (int i = 0; i < 8; i++)
#pragma unroll
        for (int j = 0; j < 8; j++) acc2[i][j] = 0ull;

    int arow[2], akv[2];
    int ap0[2], ap1[2];
    float aw0[2], aw1[2];
#pragma unroll
    for (int it = 0; it < 2; it++) {
        int idx = tid + it * 256;
        arow[it] = idx >> 2;
        akv[it]  = (idx & 3) * 4;
        int m = m0 + arow[it];
        int b = m >> 9;
        ap0[it] = g_bpair[b * 2 + 0]; ap1[it] = g_bpair[b * 2 + 1];
        aw0[it] = g_bw[b * 2 + 0];    aw1[it] = g_bw[b * 2 + 1];
    }

    float4 pa[2], pb[2];
#pragma unroll
    for (int it = 0; it < 2; it++) {
        int m = m0 + arow[it];
        int t = m & (TT - 1);
        const float* h0 = g_hout + ((size_t)ap0[it] * TT + t) * (2 * HH) + akv[it];
        const float* h1 = g_hout + ((size_t)ap1[it] * TT + t) * (2 * HH) + akv[it];
        float4 v0 = __ldg((const float4*)h0);
        float4 v1 = __ldg((const float4*)h1);
        pa[it] = make_float4(aw0[it] * v0.x + aw1[it] * v1.x, aw0[it] * v0.y + aw1[it] * v1.y,
                             aw0[it] * v0.z + aw1[it] * v1.z, aw0[it] * v0.w + aw1[it] * v1.w);
        pb[it] = *(const float4*)(Wout + (size_t)(n0 + arow[it]) * K + akv[it]);
    }
    int nk = K / TKk;
    for (int kt = 0; kt < nk; kt++) {
        int bsel = kt & 1;
#pragma unroll
        for (int it = 0; it < 2; it++) {
            int row = arow[it];
            int kv2 = (akv[it] >> 1);
            As2[bsel][kv2][row]     = make_float2(pa[it].x, pa[it].y);
            As2[bsel][kv2 + 1][row] = make_float2(pa[it].z, pa[it].w);
            Bs2[bsel][kv2][row]     = make_float2(pb[it].x, pb[it].y);
            Bs2[bsel][kv2 + 1][row] = make_float2(pb[it].z, pb[it].w);
        }
        __syncthreads();
        if (kt + 1 < nk) {
            int k0n = (kt + 1) * TKk;
#pragma unroll
            for (int it = 0; it < 2; it++) {
                int m = m0 + arow[it];
                int t = m & (TT - 1);
                const float* h0 = g_hout + ((size_t)ap0[it] * TT + t) * (2 * HH) + k0n + akv[it];
                const float* h1 = g_hout + ((size_t)ap1[it] * TT + t) * (2 * HH) + k0n + akv[it];
                float4 v0 = __ldg((const float4*)h0);
                float4 v1 = __ldg((const float4*)h1);
                pa[it] = make_float4(aw0[it] * v0.x + aw1[it] * v1.x, aw0[it] * v0.y + aw1[it] * v1.y,
                                     aw0[it] * v0.z + aw1[it] * v1.z, aw0[it] * v0.w + aw1[it] * v1.w);
                pb[it] = *(const float4*)(Wout + (size_t)(n0 + arow[it]) * K + k0n + akv[it]);
            }
        }
#pragma unroll
        for (int kk2 = 0; kk2 < TKk / 2; kk2++) {
            u64 a2[8], b2[8];
#pragma unroll
            for (int i = 0; i < 8; i++) a2[i] = *(const u64*)&As2[bsel][kk2][ty + 16 * i];
#pragma unroll
            for (int j = 0; j < 8; j++) b2[j] = *(const u64*)&Bs2[bsel][kk2][tx + 16 * j];
#pragma unroll
            for (int i = 0; i < 8; i++)
#pragma unroll
                for (int j = 0; j < 8; j++) acc2[i][j] = ffma2(a2[i], b2[j], acc2[i][j]);
        }
    }
#pragma unroll
    for (int j = 0; j < 8; j++) {
        int n = n0 + tx + 16 * j;
        float bv = bout[n];
#pragma unroll
        for (int i = 0; i < 8; i++) {
            int m = m0 + ty + 16 * i;
            out[(size_t)m * OUTD + n] = f2sum(acc2[i][j]) + bv;
        }
    }
}

// ---------------- persistent LSTM recurrence -----------------------------------
// Same math as R9; h smem transposed to row-major [row][kq] (stride 258 u64) so
// h loads are LDS.128 covering 2 k-quads (inner loop: 2 W + RPL h loads / 2 kq).
template<int RPL>
__device__ void run_lstm(int g, int d, int j0, int off, int cnt,
                         const float* __restrict__ Whh, u64* __restrict__ smem)
{
    u64* wsA = smem;
    u64* hs  = smem + 4 * WS_TILE;
    u64* redbuf = wsA;

    int tid = threadIdx.x;
    int half = tid >> 8;
    int htid = tid & 255;
    int lane = tid & 31;
    int w8 = htid >> 5;
    int r0 = lane & 3, hv = lane >> 2;
    int col = w8 * 4 + (hv >> 1);
    int gbase = (hv & 1) * 2;
    int j = j0 + col;
    int kbase = half * 256;

    const float* wsrc[8];
    int wdst_out[8];
    int fq = htid & 15;
#pragma unroll
    for (int it = 0; it < 8; it++) {
        int idx = htid + it * 256;
        int out = idx >> 4;
        int ww = out >> 4, rem = out & 15;
        int c = ww * 4 + (rem >> 2);
        int gate = ((rem >> 1) & 1) * 2 + (rem & 1);
        int grow = gate * HH + j0 + c;
        wsrc[it] = Whh + (size_t)grow * HH + kbase + fq * 4;
        wdst_out[it] = out;
    }

    int rows[RPL], chains[RPL];
#pragma unroll
    for (int ri = 0; ri < RPL; ri++) {
        rows[ri] = r0 + ri * 4;
        chains[ri] = (off + rows[ri]) * 2 + d;
    }
    float c_reg[RPL];
#pragma unroll
    for (int ri = 0; ri < RPL; ri++) c_reg[ri] = 0.f;

    int* bar = &g_gbar[g];

    float4 wreg[8];
#pragma unroll
    for (int it = 0; it < 8; it++) wreg[it] = __ldg((const float4*)wsrc[it]);

    for (int s = 0; s < TT; s++) {
        int rb = s & 1;
        int t = d ? (TT - 1 - s) : s;
        const float* hread = g_hbuf[rb];
        float* hwrite = g_hbuf[rb ^ 1];

        float xpv[RPL][2];
        if (half == 0) {
#pragma unroll
            for (int ri = 0; ri < RPL; ri++) {
                xpv[ri][0] = xpv[ri][1] = 0.f;
                if (rows[ri] < cnt) {
                    const float* xpt = g_xp + ((size_t)chains[ri] * TT + t) * G4H;
                    xpv[ri][0] = __ldg(xpt + (gbase + 0) * HH + j);
                    xpv[ri][1] = __ldg(xpt + (gbase + 1) * HH + j);
                }
            }
        }

        // h fill (row-major): RR rows x 128 f4g chunks, each half fills its 64
#pragma unroll
        for (int it = 0; it < RPL; it++) {
            int idx = htid + it * 256;
            int row = idx >> 6;
            int fl = idx & 63;
            int f4g = half * 64 + fl;
            float4 v = make_float4(0.f, 0.f, 0.f, 0.f);
            if (row < cnt)
                v = __ldcg((const float4*)(hread + (size_t)((off + row) * 2 + d) * HH + f4g * 4));
            union { float4 f4; ulonglong2 u2; } cv; cv.f4 = v;
            *(ulonglong2*)&hs[row * HS_RSTRIDE + f4g * 2] = cv.u2;
        }

        {
            u64* wbuf = wsA + (half * 2 + 0) * WS_TILE;
#pragma unroll
            for (int it = 0; it < 8; it++) {
                union { float4 f4; u64 u2[2]; } cv; cv.f4 = wreg[it];
                wbuf[(fq * 2 + 0) * WS_KSTRIDE + wdst_out[it]] = cv.u2[0];
                wbuf[(fq * 2 + 1) * WS_KSTRIDE + wdst_out[it]] = cv.u2[1];
            }
        }
        __syncthreads();

        u64 acc[RPL][2];
#pragma unroll
        for (int ri = 0; ri < RPL; ri++) { acc[ri][0] = 0ull; acc[ri][1] = 0ull; }

#pragma unroll
        for (int kt = 0; kt < 4; kt++) {
            int nkt = (kt + 1) & 3;
#pragma unroll
            for (int it = 0; it < 8; it++)
                wreg[it] = __ldg((const float4*)(wsrc[it] + nkt * 64));
            {
                const u64* wbuf = wsA + (half * 2 + (kt & 1)) * WS_TILE;
                const u64* wp = wbuf + w8 * 16 + hv * 2;
                int gpbase = half * 64 + kt * 16;
#pragma unroll 4
                for (int kqp = 0; kqp < 16; kqp++) {
                    ulonglong2 wv0 = *(const ulonglong2*)(wp + (2 * kqp)     * WS_KSTRIDE);
                    ulonglong2 wv1 = *(const ulonglong2*)(wp + (2 * kqp + 1) * WS_KSTRIDE);
#pragma unroll
                    for (int ri = 0; ri < RPL; ri++) {
                        ulonglong2 hh = *(const ulonglong2*)&hs[rows[ri] * HS_RSTRIDE + (gpbase + kqp) * 2];
                        acc[ri][0] = ffma2(hh.x, wv0.x, acc[ri][0]);
                        acc[ri][1] = ffma2(hh.x, wv0.y, acc[ri][1]);
                        acc[ri][0] = ffma2(hh.y, wv1.x, acc[ri][0]);
                        acc[ri][1] = ffma2(hh.y, wv1.y, acc[ri][1]);
                    }
                }
            }
            if (kt < 3) {
                u64* wbuf = wsA + (half * 2 + (nkt & 1)) * WS_TILE;
#pragma unroll
                for (int it = 0; it < 8; it++) {
                    union { float4 f4; u64 u2[2]; } cv; cv.f4 = wreg[it];
                    wbuf[(fq * 2 + 0) * WS_KSTRIDE + wdst_out[it]] = cv.u2[0];
                    wbuf[(fq * 2 + 1) * WS_KSTRIDE + wdst_out[it]] = cv.u2[1];
                }
            }
            __syncthreads();
        }

        if (half == 1) {
#pragma unroll
            for (int ri = 0; ri < RPL; ri++) {
                redbuf[((w8 * 32 + lane) * RPL + ri) * 2 + 0] = acc[ri][0];
                redbuf[((w8 * 32 + lane) * RPL + ri) * 2 + 1] = acc[ri][1];
            }
        }
        __syncthreads();

        if (half == 0) {
#pragma unroll
            for (int ri = 0; ri < RPL; ri++) {
                u64 b0 = redbuf[((w8 * 32 + lane) * RPL + ri) * 2 + 0];
                u64 b1 = redbuf[((w8 * 32 + lane) * RPL + ri) * 2 + 1];
                float v0 = xpv[ri][0] + f2sum(acc[ri][0]) + f2sum(b0);
                float v1 = xpv[ri][1] + f2sum(acc[ri][1]) + f2sum(b1);
                float p0 = __shfl_xor_sync(0xffffffffu, v0, 4);
                float p1 = __shfl_xor_sync(0xffffffffu, v1, 4);
                float gi = (hv & 1) ? p0 : v0;
                float gf = (hv & 1) ? p1 : v1;
                float gg = (hv & 1) ? v0 : p0;
                float go = (hv & 1) ? v1 : p1;
                float iv = sigmoid_fast(gi);
                float fv = sigmoid_fast(gf);
                float gv = __tanhf(gg);
                float ov = sigmoid_fast(go);
                float cvv = fv * c_reg[ri] + iv * gv;
                c_reg[ri] = cvv;
                float hvv = ov * __tanhf(cvv);
                if (!(hv & 1) && rows[ri] < cnt) {
                    __stcg(hwrite + (size_t)chains[ri] * HH + j, hvv);
                    __stcg(g_hout + ((size_t)(off + rows[ri]) * TT + t) * (2 * HH) + d * HH + j, hvv);
                }
            }
        }

        __syncthreads();
        if (tid == 0) {
            red_release_add(bar, 1);
            int target = (s + 1) * 16;
            while (ld_acq(bar) < target) __nanosleep(20);
        }
        __syncthreads();
    }
}

__global__ __launch_bounds__(512, 1) void lstm_persist_kernel(const float* __restrict__ Whh) {
    extern __shared__ __align__(16) u64 smem_dyn[];
    int bid = blockIdx.x;
    int g = bid >> 4;
    int ct = bid & 15;
    int e = g >> 1, d = g & 1;
    int cnt = g_cnt[e];
    int off = g_off[e];
    int j0 = ct * 32;
    if (cnt == 0) return;
    const float* W = Whh + (size_t)g * G4H * HH;
    int rpl = (cnt + 3) >> 2;
    switch (rpl) {
        case 1: run_lstm<1>(g, d, j0, off, cnt, W, smem_dyn); break;
        case 2: run_lstm<2>(g, d, j0, off, cnt, W, smem_dyn); break;
        case 3: run_lstm<3>(g, d, j0, off, cnt, W, smem_dyn); break;
        case 4: run_lstm<4>(g, d, j0, off, cnt, W, smem_dyn); break;
        case 5: run_lstm<5>(g, d, j0, off, cnt, W, smem_dyn); break;
        case 6: run_lstm<6>(g, d, j0, off, cnt, W, smem_dyn); break;
        case 7: run_lstm<7>(g, d, j0, off, cnt, W, smem_dyn); break;
        default: run_lstm<8>(g, d, j0, off, cnt, W, smem_dyn); break;
    }
}

__global__ void write_lb_kernel(float* out, int out_size) {
    out[out_size - 1] = g_lb;
}

// ---------------- host entry ---------------------------------------------------
extern "C" void kernel_launch(void* const* d_in, const int* in_sizes, int n_in,
                              void* d_out, int out_size) {
    const float* x    = (const float*)d_in[0];
    const float* rW1  = (const float*)d_in[1];
    const float* rb1  = (const float*)d_in[2];
    const float* rW2  = (const float*)d_in[3];
    const float* rb2  = (const float*)d_in[4];
    const float* Wih  = (const float*)d_in[5];
    const float* Whh  = (const float*)d_in[6];
    const float* bih  = (const float*)d_in[7];
    const float* bhh  = (const float*)d_in[8];
    const float* Wout = (const float*)d_in[9];
    const float* bout = (const float*)d_in[10];
    float* out = (float*)d_out;
    (void)in_sizes; (void)n_in;

    cudaFuncSetAttribute(lstm_persist_kernel,
                         cudaFuncAttributeMaxDynamicSharedMemorySize, SMEM_BYTES);
    cudaFuncSetAttribute(router12_kernel,
                         cudaFuncAttributeMaxDynamicSharedMemorySize, 2 * BB * II * 4);

    init_mean_kernel<<<96, 512>>>(x);                              // launch 1
    router12_kernel<<<1, 512, 2 * BB * II * 4>>>(rW1, rb1, rW2, rb2); // launch 2

    dim3 gxp(G4H / TNn, TT / TMm, NCHAIN);                         // (16, 4, 128)
    xp_gemm_kernel<<<gxp, 256>>>(x, Wih, bih, bhh);                // launch 3

    lstm_persist_kernel<<<LSTM_BLOCKS, 512, SMEM_BYTES>>>(Whh);    // launch 4 (profiled)

    dim3 gout(OUTD / TNn, (BB * TT) / TMm);                        // (4, 128)
    out_gemm_fused_kernel<<<gout, 256>>>(Wout, bout, out);         // launch 5

    write_lb_kernel<<<1, 1>>>(out, out_size);                      // launch 6
}

// round 11
// speedup vs baseline: 2.2409x; 1.3083x over previous
#include <cuda_runtime.h>
#include <cuda_bf16.h>
#include <cstdint>

typedef unsigned long long u64;
typedef unsigned int u32;

// Problem constants
#define BB 32
#define TT 512
#define II 512
#define HH 512
#define G4H 2048
#define EE 4
#define OUTD 512
#define NPAIR 64
#define NCHAIN 128
#define LSTM_BLOCKS 128   // 8 (e,d) groups x 16 col-tiles (32 cols each)

// recurrence smem layout
#define WB_STRIDE 258                          // u32 per out-row (256 kq + pad)
#define WB_U32    (128 * WB_STRIDE)            // 33024 u32  = 132,096 B
#define HS_RSTRIDE 258                         // u64 per row (256 kq + pad)
#define HS_U64    (32 * HS_RSTRIDE)            // 8256 u64   =  66,048 B
#define RED_F32   4096                         //             16,384 B
#define SMEM_BYTES (WB_U32 * 4 + HS_U64 * 8 + RED_F32 * 4)   // 214,528 B

// ---------------- device scratch ----------------------------------------------
__device__ __align__(16) float g_xp[(size_t)NCHAIN * TT * G4H];       // 512 MB
__device__ __align__(16) float g_hout[(size_t)NPAIR * TT * 2 * HH];   // 128 MB
__device__ __align__(16) float g_hbuf[2][NCHAIN * HH];
__device__ __align__(16) float g_router_in[BB * II];
__device__ int   g_pair_b[NPAIR];
__device__ int   g_pair_e[NPAIR];
__device__ int   g_off[EE];
__device__ int   g_cnt[EE];
__device__ int   g_bpair[BB * 2];
__device__ float g_bw[BB * 2];
__device__ float g_lb;
__device__ int   g_gbar[8];

// ---------------- helpers ------------------------------------------------------
__device__ __forceinline__ u64 ffma2(u64 a, u64 b, u64 c) {
    u64 d;
    asm("fma.rn.f32x2 %0, %1, %2, %3;" : "=l"(d) : "l"(a), "l"(b), "l"(c));
    return d;
}
__device__ __forceinline__ float f2sum(u64 v) {
    float lo, hi;
    asm("mov.b64 {%0,%1}, %2;" : "=f"(lo), "=f"(hi) : "l"(v));
    return lo + hi;
}
__device__ __forceinline__ u64 pack2(float lo, float hi) {
    u64 v;
    asm("mov.b64 %0, {%1,%2};" : "=l"(v) : "f"(lo), "f"(hi));
    return v;
}
// bf16x2 (lo=k, hi=k+1) -> f32x2 u64 (exact expansion)
__device__ __forceinline__ u64 bfpair(u32 v) {
    u32 lo = v << 16;
    u32 hi = v & 0xFFFF0000u;
    u64 r;
    asm("mov.b64 %0, {%1,%2};" : "=l"(r) : "r"(lo), "r"(hi));
    return r;
}
__device__ __forceinline__ float sigmoid_fast(float x) {
    return 0.5f * __tanhf(0.5f * x) + 0.5f;
}
__device__ __forceinline__ int ld_acq(const int* p) {
    int v;
    asm volatile("ld.acquire.gpu.b32 %0, [%1];" : "=r"(v) : "l"(p));
    return v;
}
__device__ __forceinline__ void red_release_add(int* p, int v) {
    asm volatile("red.release.gpu.global.add.s32 [%0], %1;" :: "l"(p), "r"(v) : "memory");
}

// ---------------- launch 1: fused init + mean ----------------------------------
__global__ __launch_bounds__(512) void init_mean_kernel(const float* __restrict__ x) {
    int bid = blockIdx.x;
    int tid = threadIdx.x;
    if (bid < BB) {
        const float* xb = x + (size_t)bid * TT * II + tid;
        float s = 0.f;
        for (int t = 0; t < TT; t++) s += xb[(size_t)t * II];
        g_router_in[bid * II + tid] = s * (1.0f / (float)TT);
    } else {
        int idx = (bid - BB) * 512 + tid;
        g_hbuf[0][idx] = 0.f;
        g_hbuf[0][idx + 32768] = 0.f;
        g_hbuf[1][idx] = 0.f;
        g_hbuf[1][idx + 32768] = 0.f;
        if (bid == BB && tid < 8) g_gbar[tid] = 0;
    }
}

// ---------------- launch 2: fused router (single block) ------------------------
__global__ __launch_bounds__(512, 1) void router12_kernel(
    const float* __restrict__ rW1, const float* __restrict__ rb1,
    const float* __restrict__ rW2, const float* __restrict__ rb2)
{
    extern __shared__ float rsm[];
    float* rin = rsm;
    float* r1h = rsm + BB * II;
    __shared__ float logits[BB][EE];
    __shared__ float probs[BB][EE];
    __shared__ float gate[BB][EE];
    int tid = threadIdx.x;

    for (int i = tid; i < BB * II; i += 512) rin[i] = g_router_in[i];
    __syncthreads();

    {
        int n = tid;
        u64 acc2[BB];
#pragma unroll
        for (int b = 0; b < BB; b++) acc2[b] = 0ull;
        const float* w = rW1 + (size_t)n * II;
        for (int k = 0; k < II; k += 4) {
            float4 wv = *(const float4*)(w + k);
            u64 w01 = pack2(wv.x, wv.y);
            u64 w23 = pack2(wv.z, wv.w);
#pragma unroll
            for (int b = 0; b < BB; b++) {
                float4 rv = *(const float4*)&rin[b * II + k];
                acc2[b] = ffma2(pack2(rv.x, rv.y), w01, acc2[b]);
                acc2[b] = ffma2(pack2(rv.z, rv.w), w23, acc2[b]);
            }
        }
        float bv = rb1[n];
#pragma unroll
        for (int b = 0; b < BB; b++) {
            float s = f2sum(acc2[b]) + bv;
            float sg = 1.f / (1.f + expf(-s));
            r1h[b * II + n] = s * sg;
        }
    }
    __syncthreads();

    if (tid < BB * EE) {
        int b = tid >> 2, e = tid & 3;
        float s = rb2[e];
        const float* w = rW2 + (size_t)e * II;
        const float* h = r1h + (size_t)b * II;
        for (int k = 0; k < II; k++) s += h[k] * w[k];
        logits[b][e] = s;
    }
    __syncthreads();

    if (tid < BB) {
        int b = tid;
        float m = logits[b][0];
        for (int e = 1; e < EE; e++) m = fmaxf(m, logits[b][e]);
        float pr[EE], sum = 0.f;
        for (int e = 0; e < EE; e++) { pr[e] = expf(logits[b][e] - m); sum += pr[e]; }
        for (int e = 0; e < EE; e++) { pr[e] /= sum; probs[b][e] = pr[e]; gate[b][e] = 0.f; }
        int i1 = 0;
        for (int e = 1; e < EE; e++) if (pr[e] > pr[i1]) i1 = e;
        int i2 = -1;
        for (int e = 0; e < EE; e++) {
            if (e == i1) continue;
            if (i2 < 0 || pr[e] > pr[i2]) i2 = e;
        }
        float ws = pr[i1] + pr[i2];
        gate[b][i1] = pr[i1] / ws;
        gate[b][i2] = pr[i2] / ws;
    }
    __syncthreads();
    if (tid == 0) {
        float lb = 0.f;
        for (int e = 0; e < EE; e++) {
            float u = 0.f;
            for (int b = 0; b < BB; b++) u += probs[b][e];
            u *= (1.f / (float)BB);
            float d = u - 1.0f / (float)EE;
            lb += d * d;
        }
        g_lb = 0.01f * (lb / (float)EE);
        int P = 0;
        int slotc[BB];
        for (int b = 0; b < BB; b++) slotc[b] = 0;
        for (int e = 0; e < EE; e++) {
            g_off[e] = P;
            for (int b = 0; b < BB; b++) {
                if (gate[b][e] > 0.f) {
                    g_pair_b[P] = b;
                    g_pair_e[P] = e;
                    g_bpair[b * 2 + slotc[b]] = P;
                    g_bw[b * 2 + slotc[b]] = gate[b][e];
                    slotc[b]++;
                    P++;
                }
            }
            g_cnt[e] = P - g_off[e];
        }
    }
}

// ---------- 128x128 SGEMM, f32x2, double-buffered software pipeline ------------
#define TMm 128
#define TNn 128
#define TKk 16

__device__ __forceinline__ void sgemm_block(
    const float* __restrict__ A, const float* __restrict__ Bw,
    float* __restrict__ C, int ldc, int K, int m0, int n0,
    const float* __restrict__ bias1, const float* __restrict__ bias2)
{
    __shared__ float2 As2[2][TKk / 2][TMm + 1];
    __shared__ float2 Bs2[2][TKk / 2][TNn + 1];
    int tid = threadIdx.x;
    int tx = tid & 15;
    int ty = tid >> 4;
    u64 acc2[8][8];
#pragma unroll
    for (int i = 0; i < 8; i++)
#pragma unroll
        for (int j = 0; j < 8; j++) acc2[i][j] = 0ull;

    float4 pa[2], pb[2];
#pragma unroll
    for (int it = 0; it < 2; it++) {
        int idx = tid + it * 256;
        int row = idx >> 2;
        int kv  = (idx & 3) * 4;
        pa[it] = *(const float4*)(A  + (size_t)(m0 + row) * K + kv);
        pb[it] = *(const float4*)(Bw + (size_t)(n0 + row) * K + kv);
    }
    int nk = K / TKk;
    for (int kt = 0; kt < nk; kt++) {
        int bsel = kt & 1;
#pragma unroll
        for (int it = 0; it < 2; it++) {
            int idx = tid + it * 256;
            int row = idx >> 2;
            int kv2 = (idx & 3) * 2;
            As2[bsel][kv2][row]     = make_float2(pa[it].x, pa[it].y);
            As2[bsel][kv2 + 1][row] = make_float2(pa[it].z, pa[it].w);
            Bs2[bsel][kv2][row]     = make_float2(pb[it].x, pb[it].y);
            Bs2[bsel][kv2 + 1][row] = make_float2(pb[it].z, pb[it].w);
        }
        __syncthreads();
        if (kt + 1 < nk) {
            int k0n = (kt + 1) * TKk;
#pragma unroll
            for (int it = 0; it < 2; it++) {
                int idx = tid + it * 256;
                int row = idx >> 2;
                int kv  = (idx & 3) * 4;
                pa[it] = *(const float4*)(A  + (size_t)(m0 + row) * K + k0n + kv);
                pb[it] = *(const float4*)(Bw + (size_t)(n0 + row) * K + k0n + kv);
            }
        }
#pragma unroll
        for (int kk2 = 0; kk2 < TKk / 2; kk2++) {
            u64 a2[8], b2[8];
#pragma unroll
            for (int i = 0; i < 8; i++) a2[i] = *(const u64*)&As2[bsel][kk2][ty + 16 * i];
#pragma unroll
            for (int j = 0; j < 8; j++) b2[j] = *(const u64*)&Bs2[bsel][kk2][tx + 16 * j];
#pragma unroll
            for (int i = 0; i < 8; i++)
#pragma unroll
                for (int j = 0; j < 8; j++) acc2[i][j] = ffma2(a2[i], b2[j], acc2[i][j]);
        }
    }
#pragma unroll
    for (int j = 0; j < 8; j++) {
        int n = n0 + tx + 16 * j;
        float bv = 0.f;
        if (bias1) bv += bias1[n];
        if (bias2) bv += bias2[n];
#pragma unroll
        for (int i = 0; i < 8; i++) {
            int m = m0 + ty + 16 * i;
            C[(size_t)m * ldc + n] = f2sum(acc2[i][j]) + bv;
        }
    }
}

__global__ __launch_bounds__(256, 1) void xp_gemm_kernel(
    const float* __restrict__ x, const float* __restrict__ Wih,
    const float* __restrict__ bih, const float* __restrict__ bhh)
{
    int z = blockIdx.z;
    int p = z >> 1, d = z & 1;
    int b = g_pair_b[p];
    int e = g_pair_e[p];
    int ed = e * 2 + d;
    const float* A  = x + (size_t)b * TT * II;
    const float* Bw = Wih + (size_t)ed * G4H * II;
    const float* b1 = bih + (size_t)ed * G4H;
    const float* b2 = bhh + (size_t)ed * G4H;
    float* C = g_xp + (size_t)z * TT * G4H;
    sgemm_block(A, Bw, C, G4H, II, blockIdx.y * TMm, blockIdx.x * TNn, b1, b2);
}

__global__ __launch_bounds__(256, 1) void out_gemm_fused_kernel(
    const float* __restrict__ Wout, const float* __restrict__ bout, float* __restrict__ out)
{
    const int K = 2 * HH;
    int m0 = blockIdx.y * TMm, n0 = blockIdx.x * TNn;
    __shared__ float2 As2[2][TKk / 2][TMm + 1];
    __shared__ float2 Bs2[2][TKk / 2][TNn + 1];
    int tid = threadIdx.x;
    int tx = tid & 15;
    int ty = tid >> 4;
    u64 acc2[8][8];
#pragma unroll
    for (int i = 0; i < 8; i++)
#pragma unroll
        for (int j = 0; j < 8; j++) acc2[i][j] = 0ull;

    int arow[2], akv[2];
    int ap0[2], ap1[2];
    float aw0[2], aw1[2];
#pragma unroll
    for (int it = 0; it < 2; it++) {
        int idx = tid + it * 256;
        arow[it] = idx >> 2;
        akv[it]  = (idx & 3) * 4;
        int m = m0 + arow[it];
        int b = m >> 9;
        ap0[it] = g_bpair[b * 2 + 0]; ap1[it] = g_bpair[b * 2 + 1];
        aw0[it] = g_bw[b * 2 + 0];    aw1[it] = g_bw[b * 2 + 1];
    }

    float4 pa[2], pb[2];
#pragma unroll
    for (int it = 0; it < 2; it++) {
        int m = m0 + arow[it];
        int t = m & (TT - 1);
        const float* h0 = g_hout + ((size_t)ap0[it] * TT + t) * (2 * HH) + akv[it];
        const float* h1 = g_hout + ((size_t)ap1[it] * TT + t) * (2 * HH) + akv[it];
        float4 v0 = __ldg((const float4*)h0);
        float4 v1 = __ldg((const float4*)h1);
        pa[it] = make_float4(aw0[it] * v0.x + aw1[it] * v1.x, aw0[it] * v0.y + aw1[it] * v1.y,
                             aw0[it] * v0.z + aw1[it] * v1.z, aw0[it] * v0.w + aw1[it] * v1.w);
        pb[it] = *(const float4*)(Wout + (size_t)(n0 + arow[it]) * K + akv[it]);
    }
    int nk = K / TKk;
    for (int kt = 0; kt < nk; kt++) {
        int bsel = kt & 1;
#pragma unroll
        for (int it = 0; it < 2; it++) {
            int row = arow[it];
            int kv2 = (akv[it] >> 1);
            As2[bsel][kv2][row]     = make_float2(pa[it].x, pa[it].y);
            As2[bsel][kv2 + 1][row] = make_float2(pa[it].z, pa[it].w);
            Bs2[bsel][kv2][row]     = make_float2(pb[it].x, pb[it].y);
            Bs2[bsel][kv2 + 1][row] = make_float2(pb[it].z, pb[it].w);
        }
        __syncthreads();
        if (kt + 1 < nk) {
            int k0n = (kt + 1) * TKk;
#pragma unroll
            for (int it = 0; it < 2; it++) {
                int m = m0 + arow[it];
                int t = m & (TT - 1);
                const float* h0 = g_hout + ((size_t)ap0[it] * TT + t) * (2 * HH) + k0n + akv[it];
                const float* h1 = g_hout + ((size_t)ap1[it] * TT + t) * (2 * HH) + k0n + akv[it];
                float4 v0 = __ldg((const float4*)h0);
                float4 v1 = __ldg((const float4*)h1);
                pa[it] = make_float4(aw0[it] * v0.x + aw1[it] * v1.x, aw0[it] * v0.y + aw1[it] * v1.y,
                                     aw0[it] * v0.z + aw1[it] * v1.z, aw0[it] * v0.w + aw1[it] * v1.w);
                pb[it] = *(const float4*)(Wout + (size_t)(n0 + arow[it]) * K + k0n + akv[it]);
            }
        }
#pragma unroll
        for (int kk2 = 0; kk2 < TKk / 2; kk2++) {
            u64 a2[8], b2[8];
#pragma unroll
            for (int i = 0; i < 8; i++) a2[i] = *(const u64*)&As2[bsel][kk2][ty + 16 * i];
#pragma unroll
            for (int j = 0; j < 8; j++) b2[j] = *(const u64*)&Bs2[bsel][kk2][tx + 16 * j];
#pragma unroll
            for (int i = 0; i < 8; i++)
#pragma unroll
                for (int j = 0; j < 8; j++) acc2[i][j] = ffma2(a2[i], b2[j], acc2[i][j]);
        }
    }
#pragma unroll
    for (int j = 0; j < 8; j++) {
        int n = n0 + tx + 16 * j;
        float bv = bout[n];
#pragma unroll
        for (int i = 0; i < 8; i++) {
            int m = m0 + ty + 16 * i;
            out[(size_t)m * OUTD + n] = f2sum(acc2[i][j]) + bv;
        }
    }
}

// ---------------- persistent LSTM recurrence: bf16 W RESIDENT in smem ----------
// 128 blocks = 8 (e,d) groups x 16 col-tiles (32 cols). 512 threads, k-split 2.
// W (128 outs x 512 k) converted to bf16 ONCE into smem (132KB) — no per-step
// W traffic. h fp32 in smem [row][kq] (66KB). Reduction buffer f32 (16KB).
// Compute identical math to R10 except W values rounded to bf16.
template<int RPL>
__device__ void run_lstm(int g, int d, int j0, int off, int cnt,
                         const float* __restrict__ Whh, char* __restrict__ smem)
{
    u32*   wb  = (u32*)smem;                          // [out][kq] bf16x2, stride 258
    u64*   hs  = (u64*)(smem + WB_U32 * 4);           // [row][kq] f32x2, stride 258
    float* red = (float*)(smem + WB_U32 * 4 + HS_U64 * 8);

    int tid = threadIdx.x;
    int half = tid >> 8;
    int htid = tid & 255;
    int lane = tid & 31;
    int w8 = htid >> 5;
    int r0 = lane & 3, hv = lane >> 2;
    int col = w8 * 4 + (hv >> 1);
    int gbase = (hv & 1) * 2;
    int j = j0 + col;

    // ---- one-time W preload: fp32 -> bf16x2 into smem ----
    for (int it = 0; it < 64; it++) {
        int idx = tid + it * 512;          // 0..32767
        int out = idx >> 8;                // 0..127
        int kqg = idx & 255;               // k pair index
        int ww = out >> 4, rem = out & 15;
        int c = ww * 4 + (rem >> 2);
        int gate = ((rem >> 1) & 1) * 2 + (rem & 1);
        int grow = gate * HH + j0 + c;
        float2 wv = *(const float2*)(Whh + (size_t)grow * HH + kqg * 2);
        __nv_bfloat162 bv = __float22bfloat162_rn(wv);
        wb[out * WB_STRIDE + kqg] = *(u32*)&bv;
    }

    int rows[RPL], chains[RPL];
#pragma unroll
    for (int ri = 0; ri < RPL; ri++) {
        rows[ri] = r0 + ri * 4;
        chains[ri] = (off + rows[ri]) * 2 + d;
    }
    float c_reg[RPL];
#pragma unroll
    for (int ri = 0; ri < RPL; ri++) c_reg[ri] = 0.f;

    int* bar = &g_gbar[g];
    const u32* wrow0 = wb + (size_t)(w8 * 16 + 2 * hv) * WB_STRIDE;
    const u32* wrow1 = wrow0 + WB_STRIDE;
    int kq0 = half * 128;

    __syncthreads();   // W preload visible

    for (int s = 0; s < TT; s++) {
        int rb = s & 1;
        int t = d ? (TT - 1 - s) : s;
        const float* hread = g_hbuf[rb];
        float* hwrite = g_hbuf[rb ^ 1];

        float xpv[RPL][2];
        if (half == 0) {
#pragma unroll
            for (int ri = 0; ri < RPL; ri++) {
                xpv[ri][0] = xpv[ri][1] = 0.f;
                if (rows[ri] < cnt) {
                    const float* xpt = g_xp + ((size_t)chains[ri] * TT + t) * G4H;
                    xpv[ri][0] = __ldg(xpt + (gbase + 0) * HH + j);
                    xpv[ri][1] = __ldg(xpt + (gbase + 1) * HH + j);
                }
            }
        }

        // h fill: each half fills its k-half (RR rows x 64 float4)
#pragma unroll
        for (int it = 0; it < RPL; it++) {
            int idx = htid + it * 256;
            int row = idx >> 6;
            int fl = idx & 63;
            int f4g = half * 64 + fl;
            float4 v = make_float4(0.f, 0.f, 0.f, 0.f);
            if (row < cnt)
                v = __ldcg((const float4*)(hread + (size_t)((off + row) * 2 + d) * HH + f4g * 4));
            union { float4 f4; ulonglong2 u2; } cv; cv.f4 = v;
            *(ulonglong2*)&hs[row * HS_RSTRIDE + f4g * 2] = cv.u2;
        }
        __syncthreads();

        u64 acc[RPL][2];
#pragma unroll
        for (int ri = 0; ri < RPL; ri++) { acc[ri][0] = 0ull; acc[ri][1] = 0ull; }

#pragma unroll 8
        for (int u = 0; u < 64; u++) {
            int kq = kq0 + 2 * u;
            u64 wp0 = *(const u64*)&wrow0[kq];      // out0: (kq, kq+1)
            u64 wp1 = *(const u64*)&wrow1[kq];      // out1
            u64 W0a = bfpair((u32)wp0);
            u64 W0b = bfpair((u32)(wp0 >> 32));
            u64 W1a = bfpair((u32)wp1);
            u64 W1b = bfpair((u32)(wp1 >> 32));
#pragma unroll
            for (int ri = 0; ri < RPL; ri++) {
                ulonglong2 hh = *(const ulonglong2*)&hs[rows[ri] * HS_RSTRIDE + kq];
                acc[ri][0] = ffma2(hh.x, W0a, acc[ri][0]);
                acc[ri][1] = ffma2(hh.x, W1a, acc[ri][1]);
                acc[ri][0] = ffma2(hh.y, W0b, acc[ri][0]);
                acc[ri][1] = ffma2(hh.y, W1b, acc[ri][1]);
            }
        }

        if (half == 1) {
#pragma unroll
            for (int ri = 0; ri < RPL; ri++) {
                red[((w8 * 32 + lane) * RPL + ri) * 2 + 0] = f2sum(acc[ri][0]);
                red[((w8 * 32 + lane) * RPL + ri) * 2 + 1] = f2sum(acc[ri][1]);
            }
        }
        __syncthreads();

        if (half == 0) {
#pragma unroll
            for (int ri = 0; ri < RPL; ri++) {
                float b0 = red[((w8 * 32 + lane) * RPL + ri) * 2 + 0];
                float b1 = red[((w8 * 32 + lane) * RPL + ri) * 2 + 1];
                float v0 = xpv[ri][0] + f2sum(acc[ri][0]) + b0;
                float v1 = xpv[ri][1] + f2sum(acc[ri][1]) + b1;
                float p0 = __shfl_xor_sync(0xffffffffu, v0, 4);
                float p1 = __shfl_xor_sync(0xffffffffu, v1, 4);
                float gi = (hv & 1) ? p0 : v0;
                float gf = (hv & 1) ? p1 : v1;
                float gg = (hv & 1) ? v0 : p0;
                float go = (hv & 1) ? v1 : p1;
                float iv = sigmoid_fast(gi);
                float fv = sigmoid_fast(gf);
                float gv = __tanhf(gg);
                float ov = sigmoid_fast(go);
                float cvv = fv * c_reg[ri] + iv * gv;
                c_reg[ri] = cvv;
                float hvv = ov * __tanhf(cvv);
                if (!(hv & 1) && rows[ri] < cnt) {
                    __stcg(hwrite + (size_t)chains[ri] * HH + j, hvv);
                    __stcg(g_hout + ((size_t)(off + rows[ri]) * TT + t) * (2 * HH) + d * HH + j, hvv);
                }
            }
        }

        __syncthreads();
        if (tid == 0) {
            red_release_add(bar, 1);
            int target = (s + 1) * 16;
            while (ld_acq(bar) < target) __nanosleep(20);
        }
        __syncthreads();
    }
}

__global__ __launch_bounds__(512, 1) void lstm_persist_kernel(const float* __restrict__ Whh) {
    extern __shared__ __align__(16) char smem_dyn[];
    int bid = blockIdx.x;
    int g = bid >> 4;
    int ct = bid & 15;
    int e = g >> 1, d = g & 1;
    int cnt = g_cnt[e];
    int off = g_off[e];
    int j0 = ct * 32;
    if (cnt == 0) return;
    const float* W = Whh + (size_t)g * G4H * HH;
    int rpl = (cnt + 3) >> 2;
    switch (rpl) {
        case 1: run_lstm<1>(g, d, j0, off, cnt, W, smem_dyn); break;
        case 2: run_lstm<2>(g, d, j0, off, cnt, W, smem_dyn); break;
        case 3: run_lstm<3>(g, d, j0, off, cnt, W, smem_dyn); break;
        case 4: run_lstm<4>(g, d, j0, off, cnt, W, smem_dyn); break;
        case 5: run_lstm<5>(g, d, j0, off, cnt, W, smem_dyn); break;
        case 6: run_lstm<6>(g, d, j0, off, cnt, W, smem_dyn); break;
        case 7: run_lstm<7>(g, d, j0, off, cnt, W, smem_dyn); break;
        default: run_lstm<8>(g, d, j0, off, cnt, W, smem_dyn); break;
    }
}

__global__ void write_lb_kernel(float* out, int out_size) {
    out[out_size - 1] = g_lb;
}

// ---------------- host entry ---------------------------------------------------
extern "C" void kernel_launch(void* const* d_in, const int* in_sizes, int n_in,
                              void* d_out, int out_size) {
    const float* x    = (const float*)d_in[0];
    const float* rW1  = (const float*)d_in[1];
    const float* rb1  = (const float*)d_in[2];
    const float* rW2  = (const float*)d_in[3];
    const float* rb2  = (const float*)d_in[4];
    const float* Wih  = (const float*)d_in[5];
    const float* Whh  = (const float*)d_in[6];
    const float* bih  = (const float*)d_in[7];
    const float* bhh  = (const float*)d_in[8];
    const float* Wout = (const float*)d_in[9];
    const float* bout = (const float*)d_in[10];
    float* out = (float*)d_out;
    (void)in_sizes; (void)n_in;

    cudaFuncSetAttribute(lstm_persist_kernel,
                         cudaFuncAttributeMaxDynamicSharedMemorySize, SMEM_BYTES);
    cudaFuncSetAttribute(router12_kernel,
                         cudaFuncAttributeMaxDynamicSharedMemorySize, 2 * BB * II * 4);

    init_mean_kernel<<<96, 512>>>(x);                                 // 1
    router12_kernel<<<1, 512, 2 * BB * II * 4>>>(rW1, rb1, rW2, rb2); // 2

    dim3 gxp(G4H / TNn, TT / TMm, NCHAIN);                            // (16, 4, 128)
    xp_gemm_kernel<<<gxp, 256>>>(x, Wih, bih, bhh);                   // 3

    lstm_persist_kernel<<<LSTM_BLOCKS, 512, SMEM_BYTES>>>(Whh);       // 4 (profiled)

    dim3 gout(OUTD / TNn, (BB * TT) / TMm);                           // (4, 128)
    out_gemm_fused_kernel<<<gout, 256>>>(Wout, bout, out);            // 5

    write_lb_kernel<<<1, 1>>>(out, out_size);                         // 6
}

// round 12
// speedup vs baseline: 3.6296x; 1.6197x over previous
#include <cuda_runtime.h>
#include <cuda_bf16.h>
#include <cstdint>

typedef unsigned long long u64;
typedef unsigned int u32;

// Problem constants
#define BB 32
#define TT 512
#define II 512
#define HH 512
#define G4H 2048
#define EE 4
#define OUTD 512
#define NPAIR 64
#define NCHAIN 128
#define LSTM_BLOCKS 128   // 8 (e,d) groups x 16 col-tiles (32 cols each)

// recurrence smem layout (bytes)
#define WF_U64   16384                         // 8 og x 64 ktile x 32 lane (u64)  = 131072 B
#define HSTR     516                           // f32 stride per h row
#define HS_F32   (32 * HSTR)                   // 16512 f32 = 66048 B
#define RSTR     17                            // red stride (f32), bank-clean
#define RED_F32  (8 * 32 * RSTR)               // 4352 f32 = 17408 B
#define SMEM_BYTES (WF_U64 * 8 + HS_F32 * 4 + RED_F32 * 4)   // 214,528 B

// ---------------- device scratch ----------------------------------------------
__device__ __align__(16) float g_xp[(size_t)NCHAIN * TT * G4H];       // 512 MB
__device__ __align__(16) float g_hout[(size_t)NPAIR * TT * 2 * HH];   // 128 MB
__device__ __align__(16) float g_hbuf[2][NCHAIN * HH];
__device__ __align__(16) float g_router_in[BB * II];
__device__ int   g_pair_b[NPAIR];
__device__ int   g_pair_e[NPAIR];
__device__ int   g_off[EE];
__device__ int   g_cnt[EE];
__device__ int   g_bpair[BB * 2];
__device__ float g_bw[BB * 2];
__device__ float g_lb;
__device__ int   g_gbar[8];

// ---------------- helpers ------------------------------------------------------
__device__ __forceinline__ u64 ffma2(u64 a, u64 b, u64 c) {
    u64 d;
    asm("fma.rn.f32x2 %0, %1, %2, %3;" : "=l"(d) : "l"(a), "l"(b), "l"(c));
    return d;
}
__device__ __forceinline__ float f2sum(u64 v) {
    float lo, hi;
    asm("mov.b64 {%0,%1}, %2;" : "=f"(lo), "=f"(hi) : "l"(v));
    return lo + hi;
}
__device__ __forceinline__ u64 pack2(float lo, float hi) {
    u64 v;
    asm("mov.b64 %0, {%1,%2};" : "=l"(v) : "f"(lo), "f"(hi));
    return v;
}
__device__ __forceinline__ float sigmoid_fast(float x) {
    return 0.5f * __tanhf(0.5f * x) + 0.5f;
}
__device__ __forceinline__ int ld_acq(const int* p) {
    int v;
    asm volatile("ld.acquire.gpu.b32 %0, [%1];" : "=r"(v) : "l"(p));
    return v;
}
__device__ __forceinline__ void red_release_add(int* p, int v) {
    asm volatile("red.release.gpu.global.add.s32 [%0], %1;" :: "l"(p), "r"(v) : "memory");
}
__device__ __forceinline__ u32 f2tf(float f) {
    u32 r;
    asm("cvt.rna.tf32.f32 %0, %1;" : "=r"(r) : "f"(f));
    return r;
}
__device__ __forceinline__ void mma_tf32(float& d0, float& d1, float& d2, float& d3,
                                         u32 a0, u32 a1, u32 a2, u32 a3,
                                         u32 b0, u32 b1) {
    asm("mma.sync.aligned.m16n8k8.row.col.f32.tf32.tf32.f32 "
        "{%0,%1,%2,%3}, {%4,%5,%6,%7}, {%8,%9}, {%0,%1,%2,%3};"
        : "+f"(d0), "+f"(d1), "+f"(d2), "+f"(d3)
        : "r"(a0), "r"(a1), "r"(a2), "r"(a3), "r"(b0), "r"(b1));
}

// ---------------- launch 1: fused init + mean ----------------------------------
__global__ __launch_bounds__(512) void init_mean_kernel(const float* __restrict__ x) {
    int bid = blockIdx.x;
    int tid = threadIdx.x;
    if (bid < BB) {
        const float* xb = x + (size_t)bid * TT * II + tid;
        float s = 0.f;
        for (int t = 0; t < TT; t++) s += xb[(size_t)t * II];
        g_router_in[bid * II + tid] = s * (1.0f / (float)TT);
    } else {
        int idx = (bid - BB) * 512 + tid;
        g_hbuf[0][idx] = 0.f;
        g_hbuf[0][idx + 32768] = 0.f;
        g_hbuf[1][idx] = 0.f;
        g_hbuf[1][idx + 32768] = 0.f;
        if (bid == BB && tid < 8) g_gbar[tid] = 0;
    }
}

// ---------------- launch 2: fused router (single block) ------------------------
__global__ __launch_bounds__(512, 1) void router12_kernel(
    const float* __restrict__ rW1, const float* __restrict__ rb1,
    const float* __restrict__ rW2, const float* __restrict__ rb2)
{
    extern __shared__ float rsm[];
    float* rin = rsm;
    float* r1h = rsm + BB * II;
    __shared__ float logits[BB][EE];
    __shared__ float probs[BB][EE];
    __shared__ float gate[BB][EE];
    int tid = threadIdx.x;

    for (int i = tid; i < BB * II; i += 512) rin[i] = g_router_in[i];
    __syncthreads();

    {
        int n = tid;
        u64 acc2[BB];
#pragma unroll
        for (int b = 0; b < BB; b++) acc2[b] = 0ull;
        const float* w = rW1 + (size_t)n * II;
        for (int k = 0; k < II; k += 4) {
            float4 wv = *(const float4*)(w + k);
            u64 w01 = pack2(wv.x, wv.y);
            u64 w23 = pack2(wv.z, wv.w);
#pragma unroll
            for (int b = 0; b < BB; b++) {
                float4 rv = *(const float4*)&rin[b * II + k];
                acc2[b] = ffma2(pack2(rv.x, rv.y), w01, acc2[b]);
                acc2[b] = ffma2(pack2(rv.z, rv.w), w23, acc2[b]);
            }
        }
        float bv = rb1[n];
#pragma unroll
        for (int b = 0; b < BB; b++) {
            float s = f2sum(acc2[b]) + bv;
            float sg = 1.f / (1.f + expf(-s));
            r1h[b * II + n] = s * sg;
        }
    }
    __syncthreads();

    if (tid < BB * EE) {
        int b = tid >> 2, e = tid & 3;
        float s = rb2[e];
        const float* w = rW2 + (size_t)e * II;
        const float* h = r1h + (size_t)b * II;
        for (int k = 0; k < II; k++) s += h[k] * w[k];
        logits[b][e] = s;
    }
    __syncthreads();

    if (tid < BB) {
        int b = tid;
        float m = logits[b][0];
        for (int e = 1; e < EE; e++) m = fmaxf(m, logits[b][e]);
        float pr[EE], sum = 0.f;
        for (int e = 0; e < EE; e++) { pr[e] = expf(logits[b][e] - m); sum += pr[e]; }
        for (int e = 0; e < EE; e++) { pr[e] /= sum; probs[b][e] = pr[e]; gate[b][e] = 0.f; }
        int i1 = 0;
        for (int e = 1; e < EE; e++) if (pr[e] > pr[i1]) i1 = e;
        int i2 = -1;
        for (int e = 0; e < EE; e++) {
            if (e == i1) continue;
            if (i2 < 0 || pr[e] > pr[i2]) i2 = e;
        }
        float ws = pr[i1] + pr[i2];
        gate[b][i1] = pr[i1] / ws;
        gate[b][i2] = pr[i2] / ws;
    }
    __syncthreads();
    if (tid == 0) {
        float lb = 0.f;
        for (int e = 0; e < EE; e++) {
            float u = 0.f;
            for (int b = 0; b < BB; b++) u += probs[b][e];
            u *= (1.f / (float)BB);
            float d = u - 1.0f / (float)EE;
            lb += d * d;
        }
        g_lb = 0.01f * (lb / (float)EE);
        int P = 0;
        int slotc[BB];
        for (int b = 0; b < BB; b++) slotc[b] = 0;
        for (int e = 0; e < EE; e++) {
            g_off[e] = P;
            for (int b = 0; b < BB; b++) {
                if (gate[b][e] > 0.f) {
                    g_pair_b[P] = b;
                    g_pair_e[P] = e;
                    g_bpair[b * 2 + slotc[b]] = P;
                    g_bw[b * 2 + slotc[b]] = gate[b][e];
                    slotc[b]++;
                    P++;
                }
            }
            g_cnt[e] = P - g_off[e];
        }
    }
}

// ---------- 128x128 SGEMM, f32x2, double-buffered software pipeline ------------
#define TMm 128
#define TNn 128
#define TKk 16

__device__ __forceinline__ void sgemm_block(
    const float* __restrict__ A, const float* __restrict__ Bw,
    float* __restrict__ C, int ldc, int K, int m0, int n0,
    const float* __restrict__ bias1, const float* __restrict__ bias2)
{
    __shared__ float2 As2[2][TKk / 2][TMm + 1];
    __shared__ float2 Bs2[2][TKk / 2][TNn + 1];
    int tid = threadIdx.x;
    int tx = tid & 15;
    int ty = tid >> 4;
    u64 acc2[8][8];
#pragma unroll
    for (int i = 0; i < 8; i++)
#pragma unroll
        for (int j = 0; j < 8; j++) acc2[i][j] = 0ull;

    float4 pa[2], pb[2];
#pragma unroll
    for (int it = 0; it < 2; it++) {
        int idx = tid + it * 256;
        int row = idx >> 2;
        int kv  = (idx & 3) * 4;
        pa[it] = *(const float4*)(A  + (size_t)(m0 + row) * K + kv);
        pb[it] = *(const float4*)(Bw + (size_t)(n0 + row) * K + kv);
    }
    int nk = K / TKk;
    for (int kt = 0; kt < nk; kt++) {
        int bsel = kt & 1;
#pragma unroll
        for (int it = 0; it < 2; it++) {
            int idx = tid + it * 256;
            int row = idx >> 2;
            int kv2 = (idx & 3) * 2;
            As2[bsel][kv2][row]     = make_float2(pa[it].x, pa[it].y);
            As2[bsel][kv2 + 1][row] = make_float2(pa[it].z, pa[it].w);
            Bs2[bsel][kv2][row]     = make_float2(pb[it].x, pb[it].y);
            Bs2[bsel][kv2 + 1][row] = make_float2(pb[it].z, pb[it].w);
        }
        __syncthreads();
        if (kt + 1 < nk) {
            int k0n = (kt + 1) * TKk;
#pragma unroll
            for (int it = 0; it < 2; it++) {
                int idx = tid + it * 256;
                int row = idx >> 2;
                int kv  = (idx & 3) * 4;
                pa[it] = *(const float4*)(A  + (size_t)(m0 + row) * K + k0n + kv);
                pb[it] = *(const float4*)(Bw + (size_t)(n0 + row) * K + k0n + kv);
            }
        }
#pragma unroll
        for (int kk2 = 0; kk2 < TKk / 2; kk2++) {
            u64 a2[8], b2[8];
#pragma unroll
            for (int i = 0; i < 8; i++) a2[i] = *(const u64*)&As2[bsel][kk2][ty + 16 * i];
#pragma unroll
            for (int j = 0; j < 8; j++) b2[j] = *(const u64*)&Bs2[bsel][kk2][tx + 16 * j];
#pragma unroll
            for (int i = 0; i < 8; i++)
#pragma unroll
                for (int j = 0; j < 8; j++) acc2[i][j] = ffma2(a2[i], b2[j], acc2[i][j]);
        }
    }
#pragma unroll
    for (int j = 0; j < 8; j++) {
        int n = n0 + tx + 16 * j;
        float bv = 0.f;
        if (bias1) bv += bias1[n];
        if (bias2) bv += bias2[n];
#pragma unroll
        for (int i = 0; i < 8; i++) {
            int m = m0 + ty + 16 * i;
            C[(size_t)m * ldc + n] = f2sum(acc2[i][j]) + bv;
        }
    }
}

__global__ __launch_bounds__(256, 1) void xp_gemm_kernel(
    const float* __restrict__ x, const float* __restrict__ Wih,
    const float* __restrict__ bih, const float* __restrict__ bhh)
{
    int z = blockIdx.z;
    int p = z >> 1, d = z & 1;
    int b = g_pair_b[p];
    int e = g_pair_e[p];
    int ed = e * 2 + d;
    const float* A  = x + (size_t)b * TT * II;
    const float* Bw = Wih + (size_t)ed * G4H * II;
    const float* b1 = bih + (size_t)ed * G4H;
    const float* b2 = bhh + (size_t)ed * G4H;
    float* C = g_xp + (size_t)z * TT * G4H;
    sgemm_block(A, Bw, C, G4H, II, blockIdx.y * TMm, blockIdx.x * TNn, b1, b2);
}

__global__ __launch_bounds__(256, 1) void out_gemm_fused_kernel(
    const float* __restrict__ Wout, const float* __restrict__ bout, float* __restrict__ out)
{
    const int K = 2 * HH;
    int m0 = blockIdx.y * TMm, n0 = blockIdx.x * TNn;
    __shared__ float2 As2[2][TKk / 2][TMm + 1];
    __shared__ float2 Bs2[2][TKk / 2][TNn + 1];
    int tid = threadIdx.x;
    int tx = tid & 15;
    int ty = tid >> 4;
    u64 acc2[8][8];
#pragma unroll
    for (int i = 0; i < 8; i++)
#pragma unroll
        for (int j = 0; j < 8; j++) acc2[i][j] = 0ull;

    int arow[2], akv[2];
    int ap0[2], ap1[2];
    float aw0[2], aw1[2];
#pragma unroll
    for (int it = 0; it < 2; it++) {
        int idx = tid + it * 256;
        arow[it] = idx >> 2;
        akv[it]  = (idx & 3) * 4;
        int m = m0 + arow[it];
        int b = m >> 9;
        ap0[it] = g_bpair[b * 2 + 0]; ap1[it] = g_bpair[b * 2 + 1];
        aw0[it] = g_bw[b * 2 + 0];    aw1[it] = g_bw[b * 2 + 1];
    }

    float4 pa[2], pb[2];
#pragma unroll
    for (int it = 0; it < 2; it++) {
        int m = m0 + arow[it];
        int t = m & (TT - 1);
        const float* h0 = g_hout + ((size_t)ap0[it] * TT + t) * (2 * HH) + akv[it];
        const float* h1 = g_hout + ((size_t)ap1[it] * TT + t) * (2 * HH) + akv[it];
        float4 v0 = __ldg((const float4*)h0);
        float4 v1 = __ldg((const float4*)h1);
        pa[it] = make_float4(aw0[it] * v0.x + aw1[it] * v1.x, aw0[it] * v0.y + aw1[it] * v1.y,
                             aw0[it] * v0.z + aw1[it] * v1.z, aw0[it] * v0.w + aw1[it] * v1.w);
        pb[it] = *(const float4*)(Wout + (size_t)(n0 + arow[it]) * K + akv[it]);
    }
    int nk = K / TKk;
    for (int kt = 0; kt < nk; kt++) {
        int bsel = kt & 1;
#pragma unroll
        for (int it = 0; it < 2; it++) {
            int row = arow[it];
            int kv2 = (akv[it] >> 1);
            As2[bsel][kv2][row]     = make_float2(pa[it].x, pa[it].y);
            As2[bsel][kv2 + 1][row] = make_float2(pa[it].z, pa[it].w);
            Bs2[bsel][kv2][row]     = make_float2(pb[it].x, pb[it].y);
            Bs2[bsel][kv2 + 1][row] = make_float2(pb[it].z, pb[it].w);
        }
        __syncthreads();
        if (kt + 1 < nk) {
            int k0n = (kt + 1) * TKk;
#pragma unroll
            for (int it = 0; it < 2; it++) {
                int m = m0 + arow[it];
                int t = m & (TT - 1);
                const float* h0 = g_hout + ((size_t)ap0[it] * TT + t) * (2 * HH) + k0n + akv[it];
                const float* h1 = g_hout + ((size_t)ap1[it] * TT + t) * (2 * HH) + k0n + akv[it];
                float4 v0 = __ldg((const float4*)h0);
                float4 v1 = __ldg((const float4*)h1);
                pa[it] = make_float4(aw0[it] * v0.x + aw1[it] * v1.x, aw0[it] * v0.y + aw1[it] * v1.y,
                                     aw0[it] * v0.z + aw1[it] * v1.z, aw0[it] * v0.w + aw1[it] * v1.w);
                pb[it] = *(const float4*)(Wout + (size_t)(n0 + arow[it]) * K + k0n + akv[it]);
            }
        }
#pragma unroll
        for (int kk2 = 0; kk2 < TKk / 2; kk2++) {
            u64 a2[8], b2[8];
#pragma unroll
            for (int i = 0; i < 8; i++) a2[i] = *(const u64*)&As2[bsel][kk2][ty + 16 * i];
#pragma unroll
            for (int j = 0; j < 8; j++) b2[j] = *(const u64*)&Bs2[bsel][kk2][tx + 16 * j];
#pragma unroll
            for (int i = 0; i < 8; i++)
#pragma unroll
                for (int j = 0; j < 8; j++) acc2[i][j] = ffma2(a2[i], b2[j], acc2[i][j]);
        }
    }
#pragma unroll
    for (int j = 0; j < 8; j++) {
        int n = n0 + tx + 16 * j;
        float bv = bout[n];
#pragma unroll
        for (int i = 0; i < 8; i++) {
            int m = m0 + ty + 16 * i;
            out[(size_t)m * OUTD + n] = f2sum(acc2[i][j]) + bv;
        }
    }
}

// ---------------- persistent LSTM recurrence: tf32 tensor-core mma -------------
// 128 blocks = 8 (e,d) groups x 16 col-tiles (32 cols). 512 threads = 16 warps:
// warp w: kh = w&1 (k-half of 256), og = w>>1 = gate(og&3) x colhalf(og>>2).
// Each warp: M=16 cols (one gate), N=32 rows, K=256 via mma.m16n8k8.tf32.
// W pre-permuted ONCE into A-fragment order (packed 4x bf16 per lane per ktile).
// h stored tf32 (cvt.rna) row-major in smem. Epilogue: k-half reduce + gate
// gather through smem (stride-17), 2 cells/thread fixed mapping, c-state in regs.
__global__ __launch_bounds__(512, 1) void lstm_persist_kernel(const float* __restrict__ Whh) {
    extern __shared__ __align__(16) char smem_dyn[];
    u64* wfrag = (u64*)smem_dyn;                            // [og][ktile][lane]
    u32* hs    = (u32*)(smem_dyn + WF_U64 * 8);             // [row][k] tf32 bits
    float* red = (float*)(smem_dyn + WF_U64 * 8 + HS_F32 * 4); // [og*32+lane][17]

    int bid = blockIdx.x;
    int g = bid >> 4;
    int ct = bid & 15;
    int e = g >> 1, d = g & 1;
    int cnt = g_cnt[e];
    int off = g_off[e];
    int j0 = ct * 32;
    if (cnt == 0) return;

    int tid = threadIdx.x;
    int w = tid >> 5, lane = tid & 31;
    int kh = w & 1, og = w >> 1;

    const float* W = Whh + (size_t)g * G4H * HH;

    // ---- one-time W permute: fp32 -> packed bf16 A-fragments ----
    for (int it = 0; it < 32; it++) {
        int id = tid + it * 512;               // 0..16383
        int ln = id & 31;
        int kt = (id >> 5) & 63;
        int ogp = id >> 11;
        int gatep = ogp & 3, chp = ogp >> 2;
        int m0 = ln >> 2;
        int k = kt * 8 + (ln & 3);
        int ra = gatep * HH + j0 + chp * 16 + m0;    // col = j0+chp*16+m0
        float w00 = W[(size_t)ra * HH + k];
        float w10 = W[(size_t)(ra + 8) * HH + k];
        float w01 = W[(size_t)ra * HH + k + 4];
        float w11 = W[(size_t)(ra + 8) * HH + k + 4];
        u32 lo = ((u32)__bfloat16_as_ushort(__float2bfloat16_rn(w00))) |
                 (((u32)__bfloat16_as_ushort(__float2bfloat16_rn(w10))) << 16);
        u32 hi = ((u32)__bfloat16_as_ushort(__float2bfloat16_rn(w01))) |
                 (((u32)__bfloat16_as_ushort(__float2bfloat16_rn(w11))) << 16);
        wfrag[id] = ((u64)hi << 32) | lo;
    }

    // ---- per-thread cell mapping (2 cells, fixed across steps) ----
    int colc[2], rowc[2], chainc[2], lslot[2], iidx[2], ogb[2];
    float c_reg[2];
#pragma unroll
    for (int u = 0; u < 2; u++) {
        int cid = tid * 2 + u;
        colc[u] = cid >> 5;            // 0..31
        rowc[u] = cid & 31;            // 0..31
        chainc[u] = (off + rowc[u]) * 2 + d;
        int m = colc[u] & 15;
        int nt = rowc[u] >> 3;
        lslot[u] = (m & 7) * 4 + ((rowc[u] & 7) >> 1);
        iidx[u] = nt * 4 + (m >> 3) * 2 + (rowc[u] & 1);
        ogb[u] = (colc[u] >> 4) << 2;  // og base (gate added later)
        c_reg[u] = 0.f;
    }
    int jcell[2] = { j0 + colc[0], j0 + colc[1] };

    int* bar = &g_gbar[g];
    const u64* wfw = wfrag + (size_t)og * 2048 + (size_t)kh * 32 * 32;  // my og, my k-half base

    __syncthreads();   // W permute visible

    for (int s = 0; s < TT; s++) {
        int rb = s & 1;
        int t = d ? (TT - 1 - s) : s;
        const float* hread = g_hbuf[rb];
        float* hwrite = g_hbuf[rb ^ 1];

        // xp prefetch: 4 gates x 2 cells
        float xq[2][4];
#pragma unroll
        for (int u = 0; u < 2; u++) {
            xq[u][0] = xq[u][1] = xq[u][2] = xq[u][3] = 0.f;
            if (rowc[u] < cnt) {
                const float* xpt = g_xp + ((size_t)chainc[u] * TT + t) * G4H;
#pragma unroll
                for (int gg = 0; gg < 4; gg++)
                    xq[u][gg] = __ldg(xpt + gg * HH + jcell[u]);
            }
        }

        // h fill: 32 rows x 128 float4 over 512 threads (tf32-rounded)
#pragma unroll
        for (int it = 0; it < 8; it++) {
            int idx = tid + it * 512;
            int row = idx >> 7;
            int f4 = idx & 127;
            float4 v = make_float4(0.f, 0.f, 0.f, 0.f);
            if (row < cnt)
                v = __ldcg((const float4*)(hread + (size_t)((off + row) * 2 + d) * HH + f4 * 4));
            uint4 tv;
            tv.x = f2tf(v.x); tv.y = f2tf(v.y); tv.z = f2tf(v.z); tv.w = f2tf(v.w);
            *(uint4*)&hs[row * HSTR + f4 * 4] = tv;
        }
        __syncthreads();

        float acc[16];
#pragma unroll
        for (int i = 0; i < 16; i++) acc[i] = 0.f;

        int kb = kh * 256;                 // my k-half base (floats)
        int brow = lane >> 2;              // B: n within tile
        int bk = lane & 3;                 // B: k within tile
#pragma unroll 8
        for (int ktl = 0; ktl < 32; ktl++) {
            u64 wv = wfw[ktl * 32 + lane];
            u32 lo = (u32)wv, hi = (u32)(wv >> 32);
            u32 a0 = lo << 16;
            u32 a1 = lo & 0xFFFF0000u;
            u32 a2 = hi << 16;
            u32 a3 = hi & 0xFFFF0000u;
            int k0 = kb + ktl * 8;
#pragma unroll
            for (int nt = 0; nt < 4; nt++) {
                u32 b0 = hs[(nt * 8 + brow) * HSTR + k0 + bk];
                u32 b1 = hs[(nt * 8 + brow) * HSTR + k0 + bk + 4];
                mma_tf32(acc[nt * 4 + 0], acc[nt * 4 + 1], acc[nt * 4 + 2], acc[nt * 4 + 3],
                         a0, a1, a2, a3, b0, b1);
            }
        }

        // k-half reduction into red, then gate-gathered by cells
        if (kh == 1) {
            float* rp = red + (og * 32 + lane) * RSTR;
#pragma unroll
            for (int i = 0; i < 16; i++) rp[i] = acc[i];
        }
        __syncthreads();
        if (kh == 0) {
            float* rp = red + (og * 32 + lane) * RSTR;
#pragma unroll
            for (int i = 0; i < 16; i++) acc[i] += rp[i];
#pragma unroll
            for (int i = 0; i < 16; i++) rp[i] = acc[i];
        }
        __syncthreads();

        // tail: each thread updates its 2 cells
#pragma unroll
        for (int u = 0; u < 2; u++) {
            if (rowc[u] < cnt) {
                float gi = xq[u][0] + red[((ogb[u] + 0) * 32 + lslot[u]) * RSTR + iidx[u]];
                float gf = xq[u][1] + red[((ogb[u] + 1) * 32 + lslot[u]) * RSTR + iidx[u]];
                float gg = xq[u][2] + red[((ogb[u] + 2) * 32 + lslot[u]) * RSTR + iidx[u]];
                float go = xq[u][3] + red[((ogb[u] + 3) * 32 + lslot[u]) * RSTR + iidx[u]];
                float iv = sigmoid_fast(gi);
                float fv = sigmoid_fast(gf);
                float gv = __tanhf(gg);
                float ov = sigmoid_fast(go);
                float cvv = fv * c_reg[u] + iv * gv;
                c_reg[u] = cvv;
                float hvv = ov * __tanhf(cvv);
                __stcg(hwrite + (size_t)chainc[u] * HH + jcell[u], hvv);
                __stcg(g_hout + ((size_t)(off + rowc[u]) * TT + t) * (2 * HH) + d * HH + jcell[u], hvv);
            }
        }

        __syncthreads();
        if (tid == 0) {
            red_release_add(bar, 1);
            int target = (s + 1) * 16;
            while (ld_acq(bar) < target) __nanosleep(20);
        }
        __syncthreads();
    }
}

__global__ void write_lb_kernel(float* out, int out_size) {
    out[out_size - 1] = g_lb;
}

// ---------------- host entry ---------------------------------------------------
extern "C" void kernel_launch(void* const* d_in, const int* in_sizes, int n_in,
                              void* d_out, int out_size) {
    const float* x    = (const float*)d_in[0];
    const float* rW1  = (const float*)d_in[1];
    const float* rb1  = (const float*)d_in[2];
    const float* rW2  = (const float*)d_in[3];
    const float* rb2  = (const float*)d_in[4];
    const float* Wih  = (const float*)d_in[5];
    const float* Whh  = (const float*)d_in[6];
    const float* bih  = (const float*)d_in[7];
    const float* bhh  = (const float*)d_in[8];
    const float* Wout = (const float*)d_in[9];
    const float* bout = (const float*)d_in[10];
    float* out = (float*)d_out;
    (void)in_sizes; (void)n_in;

    cudaFuncSetAttribute(lstm_persist_kernel,
                         cudaFuncAttributeMaxDynamicSharedMemorySize, SMEM_BYTES);
    cudaFuncSetAttribute(router12_kernel,
                         cudaFuncAttributeMaxDynamicSharedMemorySize, 2 * BB * II * 4);

    init_mean_kernel<<<96, 512>>>(x);                                 // 1
    router12_kernel<<<1, 512, 2 * BB * II * 4>>>(rW1, rb1, rW2, rb2); // 2

    dim3 gxp(G4H / TNn, TT / TMm, NCHAIN);                            // (16, 4, 128)
    xp_gemm_kernel<<<gxp, 256>>>(x, Wih, bih, bhh);                   // 3

    lstm_persist_kernel<<<LSTM_BLOCKS, 512, SMEM_BYTES>>>(Whh);       // 4 (profiled)

    dim3 gout(OUTD / TNn, (BB * TT) / TMm);                           // (4, 128)
    out_gemm_fused_kernel<<<gout, 256>>>(Wout, bout, out);            // 5

    write_lb_kernel<<<1, 1>>>(out, out_size);                         // 6
}

// round 13
// speedup vs baseline: 4.4246x; 1.2190x over previous
#include <cuda_runtime.h>
#include <cuda_bf16.h>
#include <cstdint>

typedef unsigned long long u64;
typedef unsigned int u32;

// Problem constants
#define BB 32
#define TT 512
#define II 512
#define HH 512
#define G4H 2048
#define EE 4
#define OUTD 512
#define NPAIR 64
#define NCHAIN 128
#define LSTM_BLOCKS 128

// recurrence smem layout (bytes)
#define WF_U64   16384
#define HSTR     516
#define HS_F32   (32 * HSTR)
#define RSTR     17
#define RED_F32  (8 * 32 * RSTR)
#define SMEM_BYTES (WF_U64 * 8 + HS_F32 * 4 + RED_F32 * 4)   // 214,528 B

// xp mma smem
#define XSTR 18
#define XP_SMEM_BYTES (2 * 2 * 128 * XSTR * 4)               // 73,728 B

// ---------------- device scratch ----------------------------------------------
__device__ __align__(16) float g_xp[(size_t)NCHAIN * TT * G4H];       // 512 MB
__device__ __align__(16) float g_hout[(size_t)NPAIR * TT * 2 * HH];   // 128 MB
__device__ __align__(16) float g_hbuf[2][NCHAIN * HH];
__device__ __align__(16) float g_router_in[BB * II];
__device__ int   g_pair_b[NPAIR];
__device__ int   g_pair_e[NPAIR];
__device__ int   g_off[EE];
__device__ int   g_cnt[EE];
__device__ int   g_bpair[BB * 2];
__device__ float g_bw[BB * 2];
__device__ float g_lb;
__device__ int   g_gbar[8];

// ---------------- helpers ------------------------------------------------------
__device__ __forceinline__ u64 ffma2(u64 a, u64 b, u64 c) {
    u64 d;
    asm("fma.rn.f32x2 %0, %1, %2, %3;" : "=l"(d) : "l"(a), "l"(b), "l"(c));
    return d;
}
__device__ __forceinline__ float f2sum(u64 v) {
    float lo, hi;
    asm("mov.b64 {%0,%1}, %2;" : "=f"(lo), "=f"(hi) : "l"(v));
    return lo + hi;
}
__device__ __forceinline__ u64 pack2(float lo, float hi) {
    u64 v;
    asm("mov.b64 %0, {%1,%2};" : "=l"(v) : "f"(lo), "f"(hi));
    return v;
}
__device__ __forceinline__ float sigmoid_fast(float x) {
    return 0.5f * __tanhf(0.5f * x) + 0.5f;
}
__device__ __forceinline__ int ld_acq(const int* p) {
    int v;
    asm volatile("ld.acquire.gpu.b32 %0, [%1];" : "=r"(v) : "l"(p));
    return v;
}
__device__ __forceinline__ void red_release_add(int* p, int v) {
    asm volatile("red.release.gpu.global.add.s32 [%0], %1;" :: "l"(p), "r"(v) : "memory");
}
__device__ __forceinline__ u32 f2tf(float f) {
    u32 r;
    asm("cvt.rna.tf32.f32 %0, %1;" : "=r"(r) : "f"(f));
    return r;
}
__device__ __forceinline__ void mma_tf32(float& d0, float& d1, float& d2, float& d3,
                                         u32 a0, u32 a1, u32 a2, u32 a3,
                                         u32 b0, u32 b1) {
    asm("mma.sync.aligned.m16n8k8.row.col.f32.tf32.tf32.f32 "
        "{%0,%1,%2,%3}, {%4,%5,%6,%7}, {%8,%9}, {%0,%1,%2,%3};"
        : "+f"(d0), "+f"(d1), "+f"(d2), "+f"(d3)
        : "r"(a0), "r"(a1), "r"(a2), "r"(a3), "r"(b0), "r"(b1));
}

// ---------------- launch 1: fused init + mean ----------------------------------
__global__ __launch_bounds__(512) void init_mean_kernel(const float* __restrict__ x) {
    int bid = blockIdx.x;
    int tid = threadIdx.x;
    if (bid < BB) {
        const float* xb = x + (size_t)bid * TT * II + tid;
        float s = 0.f;
        for (int t = 0; t < TT; t++) s += xb[(size_t)t * II];
        g_router_in[bid * II + tid] = s * (1.0f / (float)TT);
    } else {
        int idx = (bid - BB) * 512 + tid;
        g_hbuf[0][idx] = 0.f;
        g_hbuf[0][idx + 32768] = 0.f;
        g_hbuf[1][idx] = 0.f;
        g_hbuf[1][idx + 32768] = 0.f;
        if (bid == BB && tid < 8) g_gbar[tid] = 0;
    }
}

// ---------------- launch 2: fused router (single block) ------------------------
__global__ __launch_bounds__(512, 1) void router12_kernel(
    const float* __restrict__ rW1, const float* __restrict__ rb1,
    const float* __restrict__ rW2, const float* __restrict__ rb2)
{
    extern __shared__ float rsm[];
    float* rin = rsm;
    float* r1h = rsm + BB * II;
    __shared__ float logits[BB][EE];
    __shared__ float probs[BB][EE];
    __shared__ float gate[BB][EE];
    int tid = threadIdx.x;

    for (int i = tid; i < BB * II; i += 512) rin[i] = g_router_in[i];
    __syncthreads();

    {
        int n = tid;
        u64 acc2[BB];
#pragma unroll
        for (int b = 0; b < BB; b++) acc2[b] = 0ull;
        const float* w = rW1 + (size_t)n * II;
        for (int k = 0; k < II; k += 4) {
            float4 wv = *(const float4*)(w + k);
            u64 w01 = pack2(wv.x, wv.y);
            u64 w23 = pack2(wv.z, wv.w);
#pragma unroll
            for (int b = 0; b < BB; b++) {
                float4 rv = *(const float4*)&rin[b * II + k];
                acc2[b] = ffma2(pack2(rv.x, rv.y), w01, acc2[b]);
                acc2[b] = ffma2(pack2(rv.z, rv.w), w23, acc2[b]);
            }
        }
        float bv = rb1[n];
#pragma unroll
        for (int b = 0; b < BB; b++) {
            float s = f2sum(acc2[b]) + bv;
            float sg = 1.f / (1.f + expf(-s));
            r1h[b * II + n] = s * sg;
        }
    }
    __syncthreads();

    if (tid < BB * EE) {
        int b = tid >> 2, e = tid & 3;
        float s = rb2[e];
        const float* w = rW2 + (size_t)e * II;
        const float* h = r1h + (size_t)b * II;
        for (int k = 0; k < II; k++) s += h[k] * w[k];
        logits[b][e] = s;
    }
    __syncthreads();

    if (tid < BB) {
        int b = tid;
        float m = logits[b][0];
        for (int e = 1; e < EE; e++) m = fmaxf(m, logits[b][e]);
        float pr[EE], sum = 0.f;
        for (int e = 0; e < EE; e++) { pr[e] = expf(logits[b][e] - m); sum += pr[e]; }
        for (int e = 0; e < EE; e++) { pr[e] /= sum; probs[b][e] = pr[e]; gate[b][e] = 0.f; }
        int i1 = 0;
        for (int e = 1; e < EE; e++) if (pr[e] > pr[i1]) i1 = e;
        int i2 = -1;
        for (int e = 0; e < EE; e++) {
            if (e == i1) continue;
            if (i2 < 0 || pr[e] > pr[i2]) i2 = e;
        }
        float ws = pr[i1] + pr[i2];
        gate[b][i1] = pr[i1] / ws;
        gate[b][i2] = pr[i2] / ws;
    }
    __syncthreads();
    if (tid == 0) {
        float lb = 0.f;
        for (int e = 0; e < EE; e++) {
            float u = 0.f;
            for (int b = 0; b < BB; b++) u += probs[b][e];
            u *= (1.f / (float)BB);
            float d = u - 1.0f / (float)EE;
            lb += d * d;
        }
        g_lb = 0.01f * (lb / (float)EE);
        int P = 0;
        int slotc[BB];
        for (int b = 0; b < BB; b++) slotc[b] = 0;
        for (int e = 0; e < EE; e++) {
            g_off[e] = P;
            for (int b = 0; b < BB; b++) {
                if (gate[b][e] > 0.f) {
                    g_pair_b[P] = b;
                    g_pair_e[P] = e;
                    g_bpair[b * 2 + slotc[b]] = P;
                    g_bw[b * 2 + slotc[b]] = gate[b][e];
                    slotc[b]++;
                    P++;
                }
            }
            g_cnt[e] = P - g_off[e];
        }
    }
}

// ---------------- xp GEMM on tensor pipe (tf32 m16n8k8) ------------------------
// C[t, 2048] = x[b] @ Wih[ed]^T + (bih+bhh). 256 threads = 8 warps (2m x 4n),
// warp tile 64x32. Smem tiles 128x16 tf32 with perm(k)=8(k>>3)+2(k&3)+((k>>2)&1)
// so (k,k+4) fragment pairs are one aligned LDS.64. Double-buffered, 1 sync/tile.
__global__ __launch_bounds__(256, 1) void xp_gemm_mma_kernel(
    const float* __restrict__ x, const float* __restrict__ Wih,
    const float* __restrict__ bih, const float* __restrict__ bhh)
{
    extern __shared__ u32 xsm[];
    u32* As = xsm;                       // [2][128*XSTR]
    u32* Bs = xsm + 2 * 128 * XSTR;

    int z = blockIdx.z;
    int p = z >> 1, d = z & 1;
    int b = g_pair_b[p];
    int e = g_pair_e[p];
    int ed = e * 2 + d;
    const float* A  = x + (size_t)b * TT * II;
    const float* Bw = Wih + (size_t)ed * G4H * II;
    const float* b1 = bih + (size_t)ed * G4H;
    const float* b2 = bhh + (size_t)ed * G4H;
    float* C = g_xp + (size_t)z * TT * G4H;
    int m0 = blockIdx.y * 128, n0 = blockIdx.x * 128;

    int tid = threadIdx.x;
    int w = tid >> 5, lane = tid & 31;
    int wm = w >> 2, wn = w & 3;
    int lg = lane >> 2, lt = lane & 3;

    float acc[4][4][4];
#pragma unroll
    for (int mt = 0; mt < 4; mt++)
#pragma unroll
        for (int nt = 0; nt < 4; nt++)
#pragma unroll
            for (int q = 0; q < 4; q++) acc[mt][nt][q] = 0.f;

    int srow[2], skv[2], spb[2];
#pragma unroll
    for (int it = 0; it < 2; it++) {
        int idx = tid + it * 256;
        srow[it] = idx >> 2;
        skv[it] = (idx & 3) * 4;
        spb[it] = 8 * (skv[it] >> 3) + ((skv[it] >> 2) & 1);
    }

    float4 pa[2], pbv[2];
#pragma unroll
    for (int it = 0; it < 2; it++) {
        pa[it]  = *(const float4*)(A  + (size_t)(m0 + srow[it]) * II + skv[it]);
        pbv[it] = *(const float4*)(Bw + (size_t)(n0 + srow[it]) * II + skv[it]);
    }

    for (int kt = 0; kt < 32; kt++) {
        int bsel = kt & 1;
        u32* Ab = As + bsel * (128 * XSTR);
        u32* Bb = Bs + bsel * (128 * XSTR);
#pragma unroll
        for (int it = 0; it < 2; it++) {
            int abase = srow[it] * XSTR + spb[it];
            Ab[abase + 0] = f2tf(pa[it].x);
            Ab[abase + 2] = f2tf(pa[it].y);
            Ab[abase + 4] = f2tf(pa[it].z);
            Ab[abase + 6] = f2tf(pa[it].w);
            Bb[abase + 0] = f2tf(pbv[it].x);
            Bb[abase + 2] = f2tf(pbv[it].y);
            Bb[abase + 4] = f2tf(pbv[it].z);
            Bb[abase + 6] = f2tf(pbv[it].w);
        }
        __syncthreads();
        if (kt < 31) {
            int k0n = (kt + 1) * 16;
#pragma unroll
            for (int it = 0; it < 2; it++) {
                pa[it]  = *(const float4*)(A  + (size_t)(m0 + srow[it]) * II + k0n + skv[it]);
                pbv[it] = *(const float4*)(Bw + (size_t)(n0 + srow[it]) * II + k0n + skv[it]);
            }
        }
#pragma unroll
        for (int h = 0; h < 2; h++) {
            u32 a0[4], a1[4], a2[4], a3[4];
#pragma unroll
            for (int mt = 0; mt < 4; mt++) {
                int r = wm * 64 + mt * 16 + lg;
                u64 v  = *(const u64*)&Ab[r * XSTR + h * 8 + 2 * lt];
                u64 v2 = *(const u64*)&Ab[(r + 8) * XSTR + h * 8 + 2 * lt];
                a0[mt] = (u32)v;  a2[mt] = (u32)(v >> 32);
                a1[mt] = (u32)v2; a3[mt] = (u32)(v2 >> 32);
            }
            u32 bf0[4], bf1[4];
#pragma unroll
            for (int nt = 0; nt < 4; nt++) {
                int rn = wn * 32 + nt * 8 + lg;
                u64 v = *(const u64*)&Bb[rn * XSTR + h * 8 + 2 * lt];
                bf0[nt] = (u32)v; bf1[nt] = (u32)(v >> 32);
            }
#pragma unroll
            for (int mt = 0; mt < 4; mt++)
#pragma unroll
                for (int nt = 0; nt < 4; nt++)
                    mma_tf32(acc[mt][nt][0], acc[mt][nt][1], acc[mt][nt][2], acc[mt][nt][3],
                             a0[mt], a1[mt], a2[mt], a3[mt], bf0[nt], bf1[nt]);
        }
    }

    // epilogue
#pragma unroll
    for (int mt = 0; mt < 4; mt++) {
        int r0 = m0 + wm * 64 + mt * 16 + lg;
#pragma unroll
        for (int nt = 0; nt < 4; nt++) {
            int c = n0 + wn * 32 + nt * 8 + 2 * lt;
            float bv0 = b1[c] + b2[c];
            float bv1 = b1[c + 1] + b2[c + 1];
            *(float2*)&C[(size_t)r0 * G4H + c] =
                make_float2(acc[mt][nt][0] + bv0, acc[mt][nt][1] + bv1);
            *(float2*)&C[(size_t)(r0 + 8) * G4H + c] =
                make_float2(acc[mt][nt][2] + bv0, acc[mt][nt][3] + bv1);
        }
    }
}

// ---------- 128x128 SGEMM, f32x2 (kept for out-proj: exact fp32) ----------------
#define TMm 128
#define TNn 128
#define TKk 16

__global__ __launch_bounds__(256, 1) void out_gemm_fused_kernel(
    const float* __restrict__ Wout, const float* __restrict__ bout, float* __restrict__ out)
{
    const int K = 2 * HH;
    int m0 = blockIdx.y * TMm, n0 = blockIdx.x * TNn;
    __shared__ float2 As2[2][TKk / 2][TMm + 1];
    __shared__ float2 Bs2[2][TKk / 2][TNn + 1];
    int tid = threadIdx.x;
    int tx = tid & 15;
    int ty = tid >> 4;
    u64 acc2[8][8];
#pragma unroll
    for (int i = 0; i < 8; i++)
#pragma unroll
        for (int j = 0; j < 8; j++) acc2[i][j] = 0ull;

    int arow[2], akv[2];
    int ap0[2], ap1[2];
    float aw0[2], aw1[2];
#pragma unroll
    for (int it = 0; it < 2; it++) {
        int idx = tid + it * 256;
        arow[it] = idx >> 2;
        akv[it]  = (idx & 3) * 4;
        int m = m0 + arow[it];
        int b = m >> 9;
        ap0[it] = g_bpair[b * 2 + 0]; ap1[it] = g_bpair[b * 2 + 1];
        aw0[it] = g_bw[b * 2 + 0];    aw1[it] = g_bw[b * 2 + 1];
    }

    float4 pa[2], pb[2];
#pragma unroll
    for (int it = 0; it < 2; it++) {
        int m = m0 + arow[it];
        int t = m & (TT - 1);
        const float* h0 = g_hout + ((size_t)ap0[it] * TT + t) * (2 * HH) + akv[it];
        const float* h1 = g_hout + ((size_t)ap1[it] * TT + t) * (2 * HH) + akv[it];
        float4 v0 = __ldg((const float4*)h0);
        float4 v1 = __ldg((const float4*)h1);
        pa[it] = make_float4(aw0[it] * v0.x + aw1[it] * v1.x, aw0[it] * v0.y + aw1[it] * v1.y,
                             aw0[it] * v0.z + aw1[it] * v1.z, aw0[it] * v0.w + aw1[it] * v1.w);
        pb[it] = *(const float4*)(Wout + (size_t)(n0 + arow[it]) * K + akv[it]);
    }
    int nk = K / TKk;
    for (int kt = 0; kt < nk; kt++) {
        int bsel = kt & 1;
#pragma unroll
        for (int it = 0; it < 2; it++) {
            int row = arow[it];
            int kv2 = (akv[it] >> 1);
            As2[bsel][kv2][row]     = make_float2(pa[it].x, pa[it].y);
            As2[bsel][kv2 + 1][row] = make_float2(pa[it].z, pa[it].w);
            Bs2[bsel][kv2][row]     = make_float2(pb[it].x, pb[it].y);
            Bs2[bsel][kv2 + 1][row] = make_float2(pb[it].z, pb[it].w);
        }
        __syncthreads();
        if (kt + 1 < nk) {
            int k0n = (kt + 1) * TKk;
#pragma unroll
            for (int it = 0; it < 2; it++) {
                int m = m0 + arow[it];
                int t = m & (TT - 1);
                const float* h0 = g_hout + ((size_t)ap0[it] * TT + t) * (2 * HH) + k0n + akv[it];
                const float* h1 = g_hout + ((size_t)ap1[it] * TT + t) * (2 * HH) + k0n + akv[it];
                float4 v0 = __ldg((const float4*)h0);
                float4 v1 = __ldg((const float4*)h1);
                pa[it] = make_float4(aw0[it] * v0.x + aw1[it] * v1.x, aw0[it] * v0.y + aw1[it] * v1.y,
                                     aw0[it] * v0.z + aw1[it] * v1.z, aw0[it] * v0.w + aw1[it] * v1.w);
                pb[it] = *(const float4*)(Wout + (size_t)(n0 + arow[it]) * K + k0n + akv[it]);
            }
        }
#pragma unroll
        for (int kk2 = 0; kk2 < TKk / 2; kk2++) {
            u64 a2[8], b2[8];
#pragma unroll
            for (int i = 0; i < 8; i++) a2[i] = *(const u64*)&As2[bsel][kk2][ty + 16 * i];
#pragma unroll
            for (int j = 0; j < 8; j++) b2[j] = *(const u64*)&Bs2[bsel][kk2][tx + 16 * j];
#pragma unroll
            for (int i = 0; i < 8; i++)
#pragma unroll
                for (int j = 0; j < 8; j++) acc2[i][j] = ffma2(a2[i], b2[j], acc2[i][j]);
        }
    }
#pragma unroll
    for (int j = 0; j < 8; j++) {
        int n = n0 + tx + 16 * j;
        float bv = bout[n];
#pragma unroll
        for (int i = 0; i < 8; i++) {
            int m = m0 + ty + 16 * i;
            out[(size_t)m * OUTD + n] = f2sum(acc2[i][j]) + bv;
        }
    }
}

// ---------------- persistent LSTM recurrence: tf32 tensor-core mma -------------
__global__ __launch_bounds__(512, 1) void lstm_persist_kernel(const float* __restrict__ Whh) {
    extern __shared__ __align__(16) char smem_dyn[];
    u64* wfrag = (u64*)smem_dyn;
    u32* hs    = (u32*)(smem_dyn + WF_U64 * 8);
    float* red = (float*)(smem_dyn + WF_U64 * 8 + HS_F32 * 4);

    int bid = blockIdx.x;
    int g = bid >> 4;
    int ct = bid & 15;
    int e = g >> 1, d = g & 1;
    int cnt = g_cnt[e];
    int off = g_off[e];
    int j0 = ct * 32;
    if (cnt == 0) return;

    int tid = threadIdx.x;
    int w = tid >> 5, lane = tid & 31;
    int kh = w & 1, og = w >> 1;

    const float* W = Whh + (size_t)g * G4H * HH;

    for (int it = 0; it < 32; it++) {
        int id = tid + it * 512;
        int ln = id & 31;
        int kt = (id >> 5) & 63;
        int ogp = id >> 11;
        int gatep = ogp & 3, chp = ogp >> 2;
        int m0 = ln >> 2;
        int k = kt * 8 + (ln & 3);
        int ra = gatep * HH + j0 + chp * 16 + m0;
        float w00 = W[(size_t)ra * HH + k];
        float w10 = W[(size_t)(ra + 8) * HH + k];
        float w01 = W[(size_t)ra * HH + k + 4];
        float w11 = W[(size_t)(ra + 8) * HH + k + 4];
        u32 lo = ((u32)__bfloat16_as_ushort(__float2bfloat16_rn(w00))) |
                 (((u32)__bfloat16_as_ushort(__float2bfloat16_rn(w10))) << 16);
        u32 hi = ((u32)__bfloat16_as_ushort(__float2bfloat16_rn(w01))) |
                 (((u32)__bfloat16_as_ushort(__float2bfloat16_rn(w11))) << 16);
        wfrag[id] = ((u64)hi << 32) | lo;
    }

    int colc[2], rowc[2], chainc[2], lslot[2], iidx[2], ogb[2];
    float c_reg[2];
#pragma unroll
    for (int u = 0; u < 2; u++) {
        int cid = tid * 2 + u;
        colc[u] = cid >> 5;
        rowc[u] = cid & 31;
        chainc[u] = (off + rowc[u]) * 2 + d;
        int m = colc[u] & 15;
        int nt = rowc[u] >> 3;
        lslot[u] = (m & 7) * 4 + ((rowc[u] & 7) >> 1);
        iidx[u] = nt * 4 + (m >> 3) * 2 + (rowc[u] & 1);
        ogb[u] = (colc[u] >> 4) << 2;
        c_reg[u] = 0.f;
    }
    int jcell[2] = { j0 + colc[0], j0 + colc[1] };

    int* bar = &g_gbar[g];
    const u64* wfw = wfrag + (size_t)og * 2048 + (size_t)kh * 32 * 32;

    __syncthreads();

    for (int s = 0; s < TT; s++) {
        int rb = s & 1;
        int t = d ? (TT - 1 - s) : s;
        const float* hread = g_hbuf[rb];
        float* hwrite = g_hbuf[rb ^ 1];

        float xq[2][4];
#pragma unroll
        for (int u = 0; u < 2; u++) {
            xq[u][0] = xq[u][1] = xq[u][2] = xq[u][3] = 0.f;
            if (rowc[u] < cnt) {
                const float* xpt = g_xp + ((size_t)chainc[u] * TT + t) * G4H;
#pragma unroll
                for (int gg = 0; gg < 4; gg++)
                    xq[u][gg] = __ldg(xpt + gg * HH + jcell[u]);
            }
        }

#pragma unroll
        for (int it = 0; it < 8; it++) {
            int idx = tid + it * 512;
            int row = idx >> 7;
            int f4 = idx & 127;
            float4 v = make_float4(0.f, 0.f, 0.f, 0.f);
            if (row < cnt)
                v = __ldcg((const float4*)(hread + (size_t)((off + row) * 2 + d) * HH + f4 * 4));
            uint4 tv;
            tv.x = f2tf(v.x); tv.y = f2tf(v.y); tv.z = f2tf(v.z); tv.w = f2tf(v.w);
            *(uint4*)&hs[row * HSTR + f4 * 4] = tv;
        }
        __syncthreads();

        float acc[16];
#pragma unroll
        for (int i = 0; i < 16; i++) acc[i] = 0.f;

        int kb = kh * 256;
        int brow = lane >> 2;
        int bk = lane & 3;
#pragma unroll 8
        for (int ktl = 0; ktl < 32; ktl++) {
            u64 wv = wfw[ktl * 32 + lane];
            u32 lo = (u32)wv, hi = (u32)(wv >> 32);
            u32 a0 = lo << 16;
            u32 a1 = lo & 0xFFFF0000u;
            u32 a2 = hi << 16;
            u32 a3 = hi & 0xFFFF0000u;
            int k0 = kb + ktl * 8;
#pragma unroll
            for (int nt = 0; nt < 4; nt++) {
                u32 b0 = hs[(nt * 8 + brow) * HSTR + k0 + bk];
                u32 b1 = hs[(nt * 8 + brow) * HSTR + k0 + bk + 4];
                mma_tf32(acc[nt * 4 + 0], acc[nt * 4 + 1], acc[nt * 4 + 2], acc[nt * 4 + 3],
                         a0, a1, a2, a3, b0, b1);
            }
        }

        if (kh == 1) {
            float* rp = red + (og * 32 + lane) * RSTR;
#pragma unroll
            for (int i = 0; i < 16; i++) rp[i] = acc[i];
        }
        __syncthreads();
        if (kh == 0) {
            float* rp = red + (og * 32 + lane) * RSTR;
#pragma unroll
            for (int i = 0; i < 16; i++) acc[i] += rp[i];
#pragma unroll
            for (int i = 0; i < 16; i++) rp[i] = acc[i];
        }
        __syncthreads();

#pragma unroll
        for (int u = 0; u < 2; u++) {
            if (rowc[u] < cnt) {
                float gi = xq[u][0] + red[((ogb[u] + 0) * 32 + lslot[u]) * RSTR + iidx[u]];
                float gf = xq[u][1] + red[((ogb[u] + 1) * 32 + lslot[u]) * RSTR + iidx[u]];
                float gg = xq[u][2] + red[((ogb[u] + 2) * 32 + lslot[u]) * RSTR + iidx[u]];
                float go = xq[u][3] + red[((ogb[u] + 3) * 32 + lslot[u]) * RSTR + iidx[u]];
                float iv = sigmoid_fast(gi);
                float fv = sigmoid_fast(gf);
                float gv = __tanhf(gg);
                float ov = sigmoid_fast(go);
                float cvv = fv * c_reg[u] + iv * gv;
                c_reg[u] = cvv;
                float hvv = ov * __tanhf(cvv);
                __stcg(hwrite + (size_t)chainc[u] * HH + jcell[u], hvv);
                __stcg(g_hout + ((size_t)(off + rowc[u]) * TT + t) * (2 * HH) + d * HH + jcell[u], hvv);
            }
        }

        __syncthreads();
        if (tid == 0) {
            red_release_add(bar, 1);
            int target = (s + 1) * 16;
            while (ld_acq(bar) < target) __nanosleep(20);
        }
        __syncthreads();
    }
}

__global__ void write_lb_kernel(float* out, int out_size) {
    out[out_size - 1] = g_lb;
}

// ---------------- host entry ---------------------------------------------------
extern "C" void kernel_launch(void* const* d_in, const int* in_sizes, int n_in,
                              void* d_out, int out_size) {
    const float* x    = (const float*)d_in[0];
    const float* rW1  = (const float*)d_in[1];
    const float* rb1  = (const float*)d_in[2];
    const float* rW2  = (const float*)d_in[3];
    const float* rb2  = (const float*)d_in[4];
    const float* Wih  = (const float*)d_in[5];
    const float* Whh  = (const float*)d_in[6];
    const float* bih  = (const float*)d_in[7];
    const float* bhh  = (const float*)d_in[8];
    const float* Wout = (const float*)d_in[9];
    const float* bout = (const float*)d_in[10];
    float* out = (float*)d_out;
    (void)in_sizes; (void)n_in;

    cudaFuncSetAttribute(lstm_persist_kernel,
                         cudaFuncAttributeMaxDynamicSharedMemorySize, SMEM_BYTES);
    cudaFuncSetAttribute(router12_kernel,
                         cudaFuncAttributeMaxDynamicSharedMemorySize, 2 * BB * II * 4);
    cudaFuncSetAttribute(xp_gemm_mma_kernel,
                         cudaFuncAttributeMaxDynamicSharedMemorySize, XP_SMEM_BYTES);

    init_mean_kernel<<<96, 512>>>(x);                                 // 1
    router12_kernel<<<1, 512, 2 * BB * II * 4>>>(rW1, rb1, rW2, rb2); // 2

    dim3 gxp(G4H / 128, TT / 128, NCHAIN);                            // (16, 4, 128)
    xp_gemm_mma_kernel<<<gxp, 256, XP_SMEM_BYTES>>>(x, Wih, bih, bhh);// 3

    lstm_persist_kernel<<<LSTM_BLOCKS, 512, SMEM_BYTES>>>(Whh);       // 4 (profiled)

    dim3 gout(OUTD / TNn, (BB * TT) / TMm);                           // (4, 128)
    out_gemm_fused_kernel<<<gout, 256>>>(Wout, bout, out);            // 5

    write_lb_kernel<<<1, 1>>>(out, out_size);                         // 6
}